// round 1
// baseline (speedup 1.0000x reference)
#include <cuda_runtime.h>
#include <math.h>

#define D   768
#define LL  103
#define RR  512
#define BBATCH 2
#define SSEQ 512
#define M_TOT (LL*RR)              /* 52736 */
#define INV_SQRT_D 0.03608439182435161f

/* ---------------- static device scratch (no allocation allowed) ------------- */
__device__ float  g_Wc[D*D];                 /* (Wk @ Wq^T) * inv_sqrt_d        */
__device__ float  g_fk2[BBATCH*SSEQ*D];      /* output @ g_Wc + bkq'            */
__device__ float4 g_colpack[BBATCH*SSEQ];    /* {sbias'+mask, vlaw, vaccu, vterm} */
__device__ float  g_u[5][D];                 /* u_law,u_accu,u_term,wkbq',bkq'  */
__device__ float  g_c[4];                    /* c0', cv_law, cv_accu, cv_term   */
__device__ float4 g_pre[BBATCH*M_TOT];       /* {law_pre, accu_pre, term_pre,0} */
__device__ float  g_hax[BBATCH*LL];
__device__ float  g_htx[BBATCH*LL];

/* ---------------- f32x2 packed helpers (Blackwell FFMA2) -------------------- */
__device__ __forceinline__ unsigned long long pk2(float x, float y) {
    unsigned long long r;
    asm("mov.b64 %0, {%1, %2};" : "=l"(r) : "f"(x), "f"(y));
    return r;
}
__device__ __forceinline__ unsigned long long fma2(unsigned long long a,
                                                   unsigned long long b,
                                                   unsigned long long c) {
    unsigned long long d;
    asm("fma.rn.f32x2 %0, %1, %2, %3;" : "=l"(d) : "l"(a), "l"(b), "l"(c));
    return d;
}
__device__ __forceinline__ float2 up2(unsigned long long v) {
    float2 r;
    asm("mov.b64 {%0, %1}, %2;" : "=f"(r.x), "=f"(r.y) : "l"(v));
    return r;
}

/* ---------------- tiny precompute kernels ----------------------------------- */
/* g_u[w][e]: w=0..2: Wv[e,:]·w_{law,accu,term}_d ; w=3: inv*Wk[e,:]·bq ; w=4: inv*Σ_d bk[d]*Wq[e,d] */
__global__ void k_vecs(const float* __restrict__ Wv, const float* __restrict__ Wk,
                       const float* __restrict__ Wq,
                       const float* __restrict__ wl, const float* __restrict__ wa,
                       const float* __restrict__ wt,
                       const float* __restrict__ bq, const float* __restrict__ bk) {
    int e = blockIdx.x, w = blockIdx.y, tid = threadIdx.x;
    const float *row, *vec; float scale = 1.0f;
    if      (w == 0) { row = Wv + e*D; vec = wl; }
    else if (w == 1) { row = Wv + e*D; vec = wa; }
    else if (w == 2) { row = Wv + e*D; vec = wt; }
    else if (w == 3) { row = Wk + e*D; vec = bq; scale = INV_SQRT_D; }
    else             { row = Wq + e*D; vec = bk; scale = INV_SQRT_D; }
    float p = 0.f;
    for (int d = tid; d < D; d += 256) p += row[d] * vec[d];
    __shared__ float sm[256];
    sm[tid] = p; __syncthreads();
    for (int s = 128; s > 0; s >>= 1) { if (tid < s) sm[tid] += sm[tid + s]; __syncthreads(); }
    if (tid == 0) g_u[w][e] = sm[0] * scale;
}

__global__ void k_scal(const float* __restrict__ bk, const float* __restrict__ bq,
                       const float* __restrict__ bv,
                       const float* __restrict__ wl, const float* __restrict__ wa,
                       const float* __restrict__ wt) {
    int tid = threadIdx.x;
    float p0 = 0, p1 = 0, p2 = 0, p3 = 0;
    for (int d = tid; d < D; d += 256) {
        float b = bv[d];
        p0 += bk[d] * bq[d]; p1 += b * wl[d]; p2 += b * wa[d]; p3 += b * wt[d];
    }
    __shared__ float sm[4][256];
    sm[0][tid] = p0; sm[1][tid] = p1; sm[2][tid] = p2; sm[3][tid] = p3;
    __syncthreads();
    for (int s = 128; s > 0; s >>= 1) {
        if (tid < s) for (int c = 0; c < 4; c++) sm[c][tid] += sm[c][tid + s];
        __syncthreads();
    }
    if (tid == 0) {
        g_c[0] = sm[0][0] * INV_SQRT_D;
        g_c[1] = sm[1][0]; g_c[2] = sm[2][0]; g_c[3] = sm[3][0];
    }
}

/* g_Wc = inv * Wk @ Wq^T : NT GEMM 768x768x768, 64x64 tiles */
__global__ __launch_bounds__(256) void k_wc(const float* __restrict__ A,
                                            const float* __restrict__ Bm) {
    __shared__ float As[16][68], Bs[16][68];
    int tid = threadIdx.x, tx = tid % 16, ty = tid / 16;
    int i0 = blockIdx.y * 64, j0 = blockIdx.x * 64;
    int lk = tid % 16, lr = tid / 16;
    float acc[4][4] = {};
    for (int k0 = 0; k0 < D; k0 += 16) {
        #pragma unroll
        for (int i = 0; i < 4; i++) {
            As[lk][lr*4+i] = A [(i0 + lr*4 + i)*D + k0 + lk];
            Bs[lk][lr*4+i] = Bm[(j0 + lr*4 + i)*D + k0 + lk];
        }
        __syncthreads();
        #pragma unroll
        for (int k = 0; k < 16; k++) {
            float4 av = *(const float4*)&As[k][ty*4];
            float4 bv = *(const float4*)&Bs[k][tx*4];
            float a[4] = {av.x, av.y, av.z, av.w};
            float b[4] = {bv.x, bv.y, bv.z, bv.w};
            #pragma unroll
            for (int i = 0; i < 4; i++)
                #pragma unroll
                for (int j = 0; j < 4; j++) acc[i][j] += a[i] * b[j];
        }
        __syncthreads();
    }
    #pragma unroll
    for (int i = 0; i < 4; i++)
        #pragma unroll
        for (int j = 0; j < 4; j++)
            g_Wc[(i0 + ty*4 + i)*D + j0 + tx*4 + j] = acc[i][j] * INV_SQRT_D;
}

/* g_fk2 = output @ g_Wc + bkq' : NN GEMM 1024x768x768 */
__global__ __launch_bounds__(256) void k_fk2(const float* __restrict__ A) {
    __shared__ float As[16][68], Bs[16][68];
    int tid = threadIdx.x, tx = tid % 16, ty = tid / 16;
    int i0 = blockIdx.y * 64, j0 = blockIdx.x * 64;
    int lk = tid % 16, lr = tid / 16;
    int ln = tid % 64, lkb = tid / 64;
    float acc[4][4] = {};
    for (int k0 = 0; k0 < D; k0 += 16) {
        #pragma unroll
        for (int i = 0; i < 4; i++)
            As[lk][lr*4+i] = A[(i0 + lr*4 + i)*D + k0 + lk];
        #pragma unroll
        for (int i = 0; i < 4; i++)
            Bs[lkb*4+i][ln] = g_Wc[(k0 + lkb*4 + i)*D + j0 + ln];
        __syncthreads();
        #pragma unroll
        for (int k = 0; k < 16; k++) {
            float4 av = *(const float4*)&As[k][ty*4];
            float4 bv = *(const float4*)&Bs[k][tx*4];
            float a[4] = {av.x, av.y, av.z, av.w};
            float b[4] = {bv.x, bv.y, bv.z, bv.w};
            #pragma unroll
            for (int i = 0; i < 4; i++)
                #pragma unroll
                for (int j = 0; j < 4; j++) acc[i][j] += a[i] * b[j];
        }
        __syncthreads();
    }
    #pragma unroll
    for (int i = 0; i < 4; i++)
        #pragma unroll
        for (int j = 0; j < 4; j++)
            g_fk2[(i0 + ty*4 + i)*D + j0 + tx*4 + j] = acc[i][j] + g_u[4][j0 + tx*4 + j];
}

/* per (b,s): sbias'(+mask), and the three v projections */
__global__ void k_colpack(const float* __restrict__ outp, const int* __restrict__ mask) {
    int row = blockIdx.x, tid = threadIdx.x;
    const float* x = outp + (size_t)row * D;
    float p0 = 0, p1 = 0, p2 = 0, p3 = 0;
    for (int d = tid; d < D; d += 256) {
        float xv = x[d];
        p0 += xv * g_u[3][d]; p1 += xv * g_u[0][d];
        p2 += xv * g_u[1][d]; p3 += xv * g_u[2][d];
    }
    __shared__ float sm[4][256];
    sm[0][tid] = p0; sm[1][tid] = p1; sm[2][tid] = p2; sm[3][tid] = p3;
    __syncthreads();
    for (int s = 128; s > 0; s >>= 1) {
        if (tid < s) for (int c = 0; c < 4; c++) sm[c][tid] += sm[c][tid + s];
        __syncthreads();
    }
    if (tid == 0) {
        float sb = sm[0][0] + g_c[0] + (1.0f - (float)mask[row]) * (-10000.0f);
        g_colpack[row] = make_float4(sb, sm[1][0] + g_c[1], sm[2][0] + g_c[2], sm[3][0] + g_c[3]);
    }
}

/* ------------- big fused kernel: scores GEMM + softmax + 3 weighted sums ---- */
/* grid (824, 2); CTA: 64 laws-rows x all 512 s of batch b, K=768, chunks of 128 cols */
__global__ __launch_bounds__(256) void k_big(const float* __restrict__ laws) {
    union SmU {
        struct { float As[16][68]; float Bs[16][132]; } t;
        float red[64*16*4];
    };
    __shared__ SmU sm;
    __shared__ float fin[64][4];

    int b = blockIdx.y;
    int m0 = blockIdx.x * 64;
    int tid = threadIdx.x, tx = tid % 16, ty = tid / 16;
    int lk = tid % 16, lr = tid / 16;

    float rs[4][4];
    #pragma unroll
    for (int i = 0; i < 4; i++)
        #pragma unroll
        for (int c = 0; c < 4; c++) rs[i][c] = 0.f;

    for (int chunk = 0; chunk < 4; chunk++) {
        unsigned long long acc[4][4];
        #pragma unroll
        for (int i = 0; i < 4; i++)
            #pragma unroll
            for (int j = 0; j < 4; j++) acc[i][j] = 0ull;

        int col0 = b * SSEQ + chunk * 128;
        float ra[4], rb[8];
        #pragma unroll
        for (int i = 0; i < 4; i++) ra[i] = laws [(size_t)(m0 + lr*4 + i)*D + lk];
        #pragma unroll
        for (int i = 0; i < 8; i++) rb[i] = g_fk2[(size_t)(col0 + lr*8 + i)*D + lk];

        for (int kt = 0; kt < 48; kt++) {
            #pragma unroll
            for (int i = 0; i < 4; i++) sm.t.As[lk][lr*4+i] = ra[i];
            #pragma unroll
            for (int i = 0; i < 8; i++) sm.t.Bs[lk][lr*8+i] = rb[i];
            __syncthreads();
            if (kt < 47) {
                int k0 = (kt + 1) * 16;
                #pragma unroll
                for (int i = 0; i < 4; i++) ra[i] = laws [(size_t)(m0 + lr*4 + i)*D + k0 + lk];
                #pragma unroll
                for (int i = 0; i < 8; i++) rb[i] = g_fk2[(size_t)(col0 + lr*8 + i)*D + k0 + lk];
            }
            #pragma unroll
            for (int k = 0; k < 16; k++) {
                float4 av = *(const float4*)&sm.t.As[k][ty*4];
                float4 b0 = *(const float4*)&sm.t.Bs[k][tx*8];
                float4 b1 = *(const float4*)&sm.t.Bs[k][tx*8 + 4];
                unsigned long long bp[4] = { pk2(b0.x, b0.y), pk2(b0.z, b0.w),
                                             pk2(b1.x, b1.y), pk2(b1.z, b1.w) };
                float a[4] = {av.x, av.y, av.z, av.w};
                #pragma unroll
                for (int i = 0; i < 4; i++) {
                    unsigned long long ad = pk2(a[i], a[i]);
                    #pragma unroll
                    for (int j = 0; j < 4; j++) acc[i][j] = fma2(ad, bp[j], acc[i][j]);
                }
            }
            __syncthreads();
        }

        /* chunk epilogue: exp + online weighted sums (no probs materialized) */
        #pragma unroll
        for (int j = 0; j < 4; j++) {
            #pragma unroll
            for (int p = 0; p < 2; p++) {
                int col = chunk * 128 + tx * 8 + 2*j + p;
                float4 cp = g_colpack[b * SSEQ + col];
                #pragma unroll
                for (int i = 0; i < 4; i++) {
                    float2 cv = up2(acc[i][j]);
                    float c = p ? cv.y : cv.x;
                    float e = __expf(c + cp.x);
                    rs[i][0] += e;
                    rs[i][1] += e * cp.y;
                    rs[i][2] += e * cp.z;
                    rs[i][3] += e * cp.w;
                }
            }
        }
    }

    __syncthreads();
    #pragma unroll
    for (int i = 0; i < 4; i++)
        #pragma unroll
        for (int c = 0; c < 4; c++)
            sm.red[(((ty*4 + i) * 16) + tx) * 4 + c] = rs[i][c];
    __syncthreads();
    {
        int m = tid / 4, c = tid % 4;
        float s = 0.f;
        #pragma unroll
        for (int k = 0; k < 16; k++) s += sm.red[((m*16) + k)*4 + c];
        fin[m][c] = s;
    }
    __syncthreads();
    if (tid < 64) {
        float den = fin[tid][0];
        g_pre[(size_t)b * M_TOT + m0 + tid] =
            make_float4(fin[tid][1] / den, fin[tid][2] / den, fin[tid][3] / den, 0.f);
    }
}

/* ------------- heads ------------------------------------------------------- */
__global__ void k_heads(const float* __restrict__ b_law_d, const float* __restrict__ w_law1,
                        const float* __restrict__ b_law1,
                        const float* __restrict__ b_accu_d, const float* __restrict__ w_accu1,
                        const float* __restrict__ b_accu1,
                        const float* __restrict__ b_term_d, const float* __restrict__ w_term1,
                        const float* __restrict__ b_term1,
                        float* __restrict__ out) {
    int l = blockIdx.x, b = blockIdx.y, tid = threadIdx.x;
    float bl = b_law_d[0], ba = b_accu_d[0], bt = b_term_d[0];
    float s0 = 0, s1 = 0, s2 = 0;
    for (int r = tid; r < RR; r += 256) {
        float4 p = g_pre[(size_t)b * M_TOT + l * RR + r];
        s0 += tanhf(p.x + bl) * w_law1[r];
        s1 += tanhf(p.y + ba) * w_accu1[r];
        s2 += tanhf(p.z + bt) * w_term1[r];
    }
    __shared__ float sm[3][256];
    sm[0][tid] = s0; sm[1][tid] = s1; sm[2][tid] = s2;
    __syncthreads();
    for (int s = 128; s > 0; s >>= 1) {
        if (tid < s) for (int c = 0; c < 3; c++) sm[c][tid] += sm[c][tid + s];
        __syncthreads();
    }
    if (tid == 0) {
        out[b * LL + l] = sm[0][0] + b_law1[0];
        g_hax[b * LL + l] = tanhf(sm[1][0] + b_accu1[0]);
        g_htx[b * LL + l] = tanhf(sm[2][0] + b_term1[0]);
    }
}

__global__ void k_final(const float* __restrict__ Wa2, const float* __restrict__ ba2,
                        const float* __restrict__ Wt2, const float* __restrict__ bt2,
                        float* __restrict__ out) {
    int b = blockIdx.x, tid = threadIdx.x;
    if (tid < 119) {
        float s = ba2[tid];
        for (int l = 0; l < LL; l++) s += Wa2[tid * LL + l] * g_hax[b * LL + l];
        out[BBATCH*LL + b * 119 + tid] = s;
    } else if (tid < 130) {
        int j = tid - 119;
        float s = bt2[j];
        for (int l = 0; l < LL; l++) s += Wt2[j * LL + l] * g_htx[b * LL + l];
        out[BBATCH*LL + BBATCH*119 + b * 11 + j] = s;
    }
}

/* ---------------- launch --------------------------------------------------- */
extern "C" void kernel_launch(void* const* d_in, const int* in_sizes, int n_in,
                              void* d_out, int out_size) {
    const float* outp   = (const float*)d_in[0];
    const int*   amask  = (const int*)  d_in[1];
    const float* laws   = (const float*)d_in[2];
    const float* Wq     = (const float*)d_in[3];
    const float* bq     = (const float*)d_in[4];
    const float* Wk     = (const float*)d_in[5];
    const float* bk     = (const float*)d_in[6];
    const float* Wv     = (const float*)d_in[7];
    const float* bv     = (const float*)d_in[8];
    const float* w_law_d  = (const float*)d_in[9];
    const float* b_law_d  = (const float*)d_in[10];
    const float* w_law1   = (const float*)d_in[11];
    const float* b_law1   = (const float*)d_in[12];
    const float* w_accu_d = (const float*)d_in[13];
    const float* b_accu_d = (const float*)d_in[14];
    const float* w_accu1  = (const float*)d_in[15];
    const float* b_accu1  = (const float*)d_in[16];
    const float* W_accu2  = (const float*)d_in[17];
    const float* b_accu2  = (const float*)d_in[18];
    const float* w_term_d = (const float*)d_in[19];
    const float* b_term_d = (const float*)d_in[20];
    const float* w_term1  = (const float*)d_in[21];
    const float* b_term1  = (const float*)d_in[22];
    const float* W_term2  = (const float*)d_in[23];
    const float* b_term2  = (const float*)d_in[24];
    float* out = (float*)d_out;

    k_vecs<<<dim3(D, 5), 256>>>(Wv, Wk, Wq, w_law_d, w_accu_d, w_term_d, bq, bk);
    k_scal<<<1, 256>>>(bk, bq, bv, w_law_d, w_accu_d, w_term_d);
    k_wc<<<dim3(D/64, D/64), 256>>>(Wk, Wq);
    k_fk2<<<dim3(D/64, (BBATCH*SSEQ)/64), 256>>>(outp);
    k_colpack<<<BBATCH*SSEQ, 256>>>(outp, amask);
    k_big<<<dim3(M_TOT/64, BBATCH), 256>>>(laws);
    k_heads<<<dim3(LL, BBATCH), 256>>>(b_law_d, w_law1, b_law1,
                                       b_accu_d, w_accu1, b_accu1,
                                       b_term_d, w_term1, b_term1, out);
    k_final<<<BBATCH, 130>>>(W_accu2, b_accu2, W_term2, b_term2, out);
}

// round 6
// speedup vs baseline: 2.9590x; 2.9590x over previous
#include <cuda_runtime.h>
#include <math.h>
#include <stdint.h>

#define D   768
#define LL  103
#define RR  512
#define BBATCH 2
#define SSEQ 512
#define M_TOT (LL*RR)              /* 52736 */
#define INV_SQRT_D 0.03608439182435161f

/* ---------------- static device scratch (no allocation allowed) ------------- */
__device__ __align__(128) float  g_Wc[D*D];              /* (Wk @ Wq^T) * inv_sqrt_d  */
__device__ __align__(128) float  g_fk2[BBATCH*SSEQ*D];   /* output @ g_Wc + bkq'      */
__device__ __align__(16)  float4 g_colpack[BBATCH*SSEQ]; /* {sbias', vlaw, vaccu, vterm} */
__device__ float  g_u[5][D];
__device__ float  g_c[4];
__device__ __align__(16) float4 g_pre[BBATCH*M_TOT];     /* {law,accu,term,0} pre-act */
__device__ float  g_hax[BBATCH*LL];
__device__ float  g_htx[BBATCH*LL];

/* ---------------- PTX helpers ---------------------------------------------- */
__device__ __forceinline__ uint32_t smem_u32(const void* p) {
    uint32_t a;
    asm("{ .reg .u64 t; cvta.to.shared.u64 t, %1; cvt.u32.u64 %0, t; }" : "=r"(a) : "l"(p));
    return a;
}
__device__ __forceinline__ void cpa16(uint32_t saddr, const void* g) {
    asm volatile("cp.async.cg.shared.global [%0], [%1], 16;" :: "r"(saddr), "l"(g) : "memory");
}
__device__ __forceinline__ void mma_tf32_16x8x8(float* d, const uint32_t* a, const uint32_t* b) {
    asm volatile(
        "mma.sync.aligned.m16n8k8.row.col.f32.tf32.tf32.f32 "
        "{%0,%1,%2,%3}, {%4,%5,%6,%7}, {%8,%9}, {%0,%1,%2,%3};"
        : "+f"(d[0]), "+f"(d[1]), "+f"(d[2]), "+f"(d[3])
        : "r"(a[0]), "r"(a[1]), "r"(a[2]), "r"(a[3]), "r"(b[0]), "r"(b[1]));
}

/* ---------------- tiny precompute kernels ----------------------------------- */
__global__ void k_vecs(const float* __restrict__ Wv, const float* __restrict__ Wk,
                       const float* __restrict__ Wq,
                       const float* __restrict__ wl, const float* __restrict__ wa,
                       const float* __restrict__ wt,
                       const float* __restrict__ bq, const float* __restrict__ bk) {
    int e = blockIdx.x, w = blockIdx.y, tid = threadIdx.x;
    const float *row, *vec; float scale = 1.0f;
    if      (w == 0) { row = Wv + e*D; vec = wl; }
    else if (w == 1) { row = Wv + e*D; vec = wa; }
    else if (w == 2) { row = Wv + e*D; vec = wt; }
    else if (w == 3) { row = Wk + e*D; vec = bq; scale = INV_SQRT_D; }
    else             { row = Wq + e*D; vec = bk; scale = INV_SQRT_D; }
    float p = 0.f;
    for (int d = tid; d < D; d += 256) p += row[d] * vec[d];
    __shared__ float sm[256];
    sm[tid] = p; __syncthreads();
    for (int s = 128; s > 0; s >>= 1) { if (tid < s) sm[tid] += sm[tid + s]; __syncthreads(); }
    if (tid == 0) g_u[w][e] = sm[0] * scale;
}

__global__ void k_scal(const float* __restrict__ bk, const float* __restrict__ bq,
                       const float* __restrict__ bv,
                       const float* __restrict__ wl, const float* __restrict__ wa,
                       const float* __restrict__ wt) {
    int tid = threadIdx.x;
    float p0 = 0, p1 = 0, p2 = 0, p3 = 0;
    for (int d = tid; d < D; d += 256) {
        float b = bv[d];
        p0 += bk[d] * bq[d]; p1 += b * wl[d]; p2 += b * wa[d]; p3 += b * wt[d];
    }
    __shared__ float sm[4][256];
    sm[0][tid] = p0; sm[1][tid] = p1; sm[2][tid] = p2; sm[3][tid] = p3;
    __syncthreads();
    for (int s = 128; s > 0; s >>= 1) {
        if (tid < s) for (int c = 0; c < 4; c++) sm[c][tid] += sm[c][tid + s];
        __syncthreads();
    }
    if (tid == 0) {
        g_c[0] = sm[0][0] * INV_SQRT_D;
        g_c[1] = sm[1][0]; g_c[2] = sm[2][0]; g_c[3] = sm[3][0];
    }
}

/* g_Wc = inv * Wk @ Wq^T : NT GEMM 768x768x768 */
__global__ __launch_bounds__(256) void k_wc(const float* __restrict__ A,
                                            const float* __restrict__ Bm) {
    __shared__ float As[16][68], Bs[16][68];
    int tid = threadIdx.x, tx = tid % 16, ty = tid / 16;
    int i0 = blockIdx.y * 64, j0 = blockIdx.x * 64;
    int lk = tid % 16, lr = tid / 16;
    float acc[4][4] = {};
    for (int k0 = 0; k0 < D; k0 += 16) {
        #pragma unroll
        for (int i = 0; i < 4; i++) {
            As[lk][lr*4+i] = A [(i0 + lr*4 + i)*D + k0 + lk];
            Bs[lk][lr*4+i] = Bm[(j0 + lr*4 + i)*D + k0 + lk];
        }
        __syncthreads();
        #pragma unroll
        for (int k = 0; k < 16; k++) {
            float4 av = *(const float4*)&As[k][ty*4];
            float4 bv = *(const float4*)&Bs[k][tx*4];
            float a[4] = {av.x, av.y, av.z, av.w};
            float b[4] = {bv.x, bv.y, bv.z, bv.w};
            #pragma unroll
            for (int i = 0; i < 4; i++)
                #pragma unroll
                for (int j = 0; j < 4; j++) acc[i][j] += a[i] * b[j];
        }
        __syncthreads();
    }
    #pragma unroll
    for (int i = 0; i < 4; i++)
        #pragma unroll
        for (int j = 0; j < 4; j++)
            g_Wc[(i0 + ty*4 + i)*D + j0 + tx*4 + j] = acc[i][j] * INV_SQRT_D;
}

/* g_fk2 = output @ g_Wc + bkq' : NN GEMM 1024x768x768 */
__global__ __launch_bounds__(256) void k_fk2(const float* __restrict__ A) {
    __shared__ float As[16][68], Bs[16][68];
    int tid = threadIdx.x, tx = tid % 16, ty = tid / 16;
    int i0 = blockIdx.y * 64, j0 = blockIdx.x * 64;
    int lk = tid % 16, lr = tid / 16;
    int ln = tid % 64, lkb = tid / 64;
    float acc[4][4] = {};
    for (int k0 = 0; k0 < D; k0 += 16) {
        #pragma unroll
        for (int i = 0; i < 4; i++)
            As[lk][lr*4+i] = A[(i0 + lr*4 + i)*D + k0 + lk];
        #pragma unroll
        for (int i = 0; i < 4; i++)
            Bs[lkb*4+i][ln] = g_Wc[(k0 + lkb*4 + i)*D + j0 + ln];
        __syncthreads();
        #pragma unroll
        for (int k = 0; k < 16; k++) {
            float4 av = *(const float4*)&As[k][ty*4];
            float4 bv = *(const float4*)&Bs[k][tx*4];
            float a[4] = {av.x, av.y, av.z, av.w};
            float b[4] = {bv.x, bv.y, bv.z, bv.w};
            #pragma unroll
            for (int i = 0; i < 4; i++)
                #pragma unroll
                for (int j = 0; j < 4; j++) acc[i][j] += a[i] * b[j];
        }
        __syncthreads();
    }
    #pragma unroll
    for (int i = 0; i < 4; i++)
        #pragma unroll
        for (int j = 0; j < 4; j++)
            g_fk2[(i0 + ty*4 + i)*D + j0 + tx*4 + j] = acc[i][j] + g_u[4][j0 + tx*4 + j];
}

/* per (b,s): sbias' (+mask), and the three v projections */
__global__ void k_colpack(const float* __restrict__ outp, const int* __restrict__ mask) {
    int row = blockIdx.x, tid = threadIdx.x;
    const float* x = outp + (size_t)row * D;
    float p0 = 0, p1 = 0, p2 = 0, p3 = 0;
    for (int d = tid; d < D; d += 256) {
        float xv = x[d];
        p0 += xv * g_u[3][d]; p1 += xv * g_u[0][d];
        p2 += xv * g_u[1][d]; p3 += xv * g_u[2][d];
    }
    __shared__ float sm[4][256];
    sm[0][tid] = p0; sm[1][tid] = p1; sm[2][tid] = p2; sm[3][tid] = p3;
    __syncthreads();
    for (int s = 128; s > 0; s >>= 1) {
        if (tid < s) for (int c = 0; c < 4; c++) sm[c][tid] += sm[c][tid + s];
        __syncthreads();
    }
    if (tid == 0) {
        float sb = sm[0][0] + g_c[0] + (1.0f - (float)mask[row]) * (-10000.0f);
        g_colpack[row] = make_float4(sb, sm[1][0] + g_c[1], sm[2][0] + g_c[2], sm[3][0] + g_c[3]);
    }
}

/* ------------- big fused kernel: tf32 mma.sync GEMM + softmax epilogue ------ */
/* CTA: 512 thr (16 warps, 4x4). Tile M=128, N=256 per chunk, 2 chunks.        */
/* SMEM: stage stride 55296B (A 18432 + B 36864) x2; colpack @110592; red @118784 */
#define KT        32
#define NKC       (D/KT)          /* 24 */
#define A_ROWSTR  36              /* padded floats per smem row (conflict-free frags) */
#define STG_BYTES 55296
#define SMEM_BIG  126976

__global__ __launch_bounds__(512) void k_big_mma(const float* __restrict__ laws) {
    extern __shared__ float smf[];
    uint32_t sb = smem_u32(smf);
    int tid = threadIdx.x, lane = tid & 31, wid = tid >> 5;
    int wm = wid >> 2, wn = wid & 3;          /* 4x4 warp grid */
    int g = lane >> 2, c = lane & 3;
    int b = blockIdx.y, m0 = blockIdx.x * 128;
    const float* fk2b = g_fk2 + (size_t)b * SSEQ * D;

    float4* scp  = (float4*)(smf + 27648);    /* byte 110592 */
    float4* red4 = (float4*)(smf + 29696);    /* byte 118784, [4][128] */

    { const float4* gcp = g_colpack + b * SSEQ;
      for (int i = tid; i < SSEQ; i += 512) scp[i] = gcp[i]; }

    float rs[2][2][4];
    #pragma unroll
    for (int mt = 0; mt < 2; mt++)
        #pragma unroll
        for (int h = 0; h < 2; h++)
            #pragma unroll
            for (int e = 0; e < 4; e++) rs[mt][h][e] = 0.f;

#define LOADST(st, kc, n0) do {                                                \
        uint32_t Ab = sb + (st) * STG_BYTES;                                   \
        uint32_t Bb = Ab + 18432;                                              \
        const float* asrc = laws + (size_t)m0 * D + (kc) * KT;                 \
        const float* bsrc = fk2b + (size_t)(n0) * D + (kc) * KT;               \
        _Pragma("unroll")                                                      \
        for (int i = tid; i < 1024; i += 512) {                                \
            int row = i >> 3, seg = i & 7;                                     \
            cpa16(Ab + row * 144 + seg * 16, asrc + (size_t)row * D + seg * 4);\
        }                                                                      \
        _Pragma("unroll")                                                      \
        for (int i = tid; i < 2048; i += 512) {                                \
            int row = i >> 3, seg = i & 7;                                     \
            cpa16(Bb + row * 144 + seg * 16, bsrc + (size_t)row * D + seg * 4);\
        }                                                                      \
        asm volatile("cp.async.commit_group;" ::: "memory");                   \
    } while (0)

    for (int chunk = 0; chunk < 2; chunk++) {
        int n0 = chunk * 256;
        float acc[2][8][4];
        #pragma unroll
        for (int mt = 0; mt < 2; mt++)
            #pragma unroll
            for (int nt = 0; nt < 8; nt++)
                #pragma unroll
                for (int e = 0; e < 4; e++) acc[mt][nt][e] = 0.f;

        LOADST(0, 0, n0);
        for (int kc = 0; kc < NKC; kc++) {
            int st = kc & 1;
            if (kc + 1 < NKC) {
                LOADST(st ^ 1, kc + 1, n0);
                asm volatile("cp.async.wait_group 1;" ::: "memory");
            } else {
                asm volatile("cp.async.wait_group 0;" ::: "memory");
            }
            __syncthreads();
            const float* As = smf + st * (STG_BYTES / 4);
            const float* Bs = As + 4608;
            #pragma unroll
            for (int kk = 0; kk < 4; kk++) {
                int kb = kk * 8;
                uint32_t af[2][4];
                #pragma unroll
                for (int mt = 0; mt < 2; mt++) {
                    int m = wm * 32 + mt * 16 + g;
                    af[mt][0] = __float_as_uint(As[m * A_ROWSTR + kb + c]);
                    af[mt][1] = __float_as_uint(As[(m + 8) * A_ROWSTR + kb + c]);
                    af[mt][2] = __float_as_uint(As[m * A_ROWSTR + kb + c + 4]);
                    af[mt][3] = __float_as_uint(As[(m + 8) * A_ROWSTR + kb + c + 4]);
                }
                uint32_t bf[8][2];
                #pragma unroll
                for (int nt = 0; nt < 8; nt++) {
                    int n = wn * 64 + nt * 8 + g;
                    bf[nt][0] = __float_as_uint(Bs[n * A_ROWSTR + kb + c]);
                    bf[nt][1] = __float_as_uint(Bs[n * A_ROWSTR + kb + c + 4]);
                }
                #pragma unroll
                for (int mt = 0; mt < 2; mt++)
                    #pragma unroll
                    for (int nt = 0; nt < 8; nt++)
                        mma_tf32_16x8x8(acc[mt][nt], af[mt], bf[nt]);
            }
            __syncthreads();
        }

        /* fused epilogue: exp + online weighted sums */
        #pragma unroll
        for (int mt = 0; mt < 2; mt++) {
            #pragma unroll
            for (int nt = 0; nt < 8; nt++) {
                int s = chunk * 256 + wn * 64 + nt * 8 + 2 * c;
                float4 cp0 = scp[s], cp1 = scp[s + 1];
                float e0 = __expf(acc[mt][nt][0] + cp0.x);
                rs[mt][0][0] += e0; rs[mt][0][1] += e0 * cp0.y;
                rs[mt][0][2] += e0 * cp0.z; rs[mt][0][3] += e0 * cp0.w;
                float e1 = __expf(acc[mt][nt][1] + cp1.x);
                rs[mt][0][0] += e1; rs[mt][0][1] += e1 * cp1.y;
                rs[mt][0][2] += e1 * cp1.z; rs[mt][0][3] += e1 * cp1.w;
                float e2 = __expf(acc[mt][nt][2] + cp0.x);
                rs[mt][1][0] += e2; rs[mt][1][1] += e2 * cp0.y;
                rs[mt][1][2] += e2 * cp0.z; rs[mt][1][3] += e2 * cp0.w;
                float e3 = __expf(acc[mt][nt][3] + cp1.x);
                rs[mt][1][0] += e3; rs[mt][1][1] += e3 * cp1.y;
                rs[mt][1][2] += e3 * cp1.z; rs[mt][1][3] += e3 * cp1.w;
            }
        }
    }
#undef LOADST

    /* reduce across the 4 lanes of each quad (cols), then across wn warps */
    #pragma unroll
    for (int mt = 0; mt < 2; mt++)
        #pragma unroll
        for (int h = 0; h < 2; h++)
            #pragma unroll
            for (int e = 0; e < 4; e++) {
                float v = rs[mt][h][e];
                v += __shfl_xor_sync(0xFFFFFFFFu, v, 1);
                v += __shfl_xor_sync(0xFFFFFFFFu, v, 2);
                rs[mt][h][e] = v;
            }
    if (c == 0) {
        #pragma unroll
        for (int mt = 0; mt < 2; mt++)
            #pragma unroll
            for (int h = 0; h < 2; h++) {
                int row = wm * 32 + mt * 16 + h * 8 + g;
                red4[wn * 128 + row] = make_float4(rs[mt][h][0], rs[mt][h][1],
                                                   rs[mt][h][2], rs[mt][h][3]);
            }
    }
    __syncthreads();
    if (tid < 128) {
        float4 a0 = red4[tid], a1 = red4[128 + tid],
               a2 = red4[256 + tid], a3 = red4[384 + tid];
        float den = a0.x + a1.x + a2.x + a3.x;
        float inv = 1.0f / den;
        g_pre[(size_t)b * M_TOT + m0 + tid] =
            make_float4((a0.y + a1.y + a2.y + a3.y) * inv,
                        (a0.z + a1.z + a2.z + a3.z) * inv,
                        (a0.w + a1.w + a2.w + a3.w) * inv, 0.f);
    }
}

/* ------------- heads ------------------------------------------------------- */
__global__ void k_heads(const float* __restrict__ b_law_d, const float* __restrict__ w_law1,
                        const float* __restrict__ b_law1,
                        const float* __restrict__ b_accu_d, const float* __restrict__ w_accu1,
                        const float* __restrict__ b_accu1,
                        const float* __restrict__ b_term_d, const float* __restrict__ w_term1,
                        const float* __restrict__ b_term1,
                        float* __restrict__ out) {
    int l = blockIdx.x, b = blockIdx.y, tid = threadIdx.x;
    float bl = b_law_d[0], ba = b_accu_d[0], bt = b_term_d[0];
    float s0 = 0, s1 = 0, s2 = 0;
    for (int r = tid; r < RR; r += 256) {
        float4 p = g_pre[(size_t)b * M_TOT + l * RR + r];
        s0 += tanhf(p.x + bl) * w_law1[r];
        s1 += tanhf(p.y + ba) * w_accu1[r];
        s2 += tanhf(p.z + bt) * w_term1[r];
    }
    __shared__ float sm[3][256];
    sm[0][tid] = s0; sm[1][tid] = s1; sm[2][tid] = s2;
    __syncthreads();
    for (int s = 128; s > 0; s >>= 1) {
        if (tid < s) for (int c = 0; c < 3; c++) sm[c][tid] += sm[c][tid + s];
        __syncthreads();
    }
    if (tid == 0) {
        out[b * LL + l] = sm[0][0] + b_law1[0];
        g_hax[b * LL + l] = tanhf(sm[1][0] + b_accu1[0]);
        g_htx[b * LL + l] = tanhf(sm[2][0] + b_term1[0]);
    }
}

__global__ void k_final(const float* __restrict__ Wa2, const float* __restrict__ ba2,
                        const float* __restrict__ Wt2, const float* __restrict__ bt2,
                        float* __restrict__ out) {
    int b = blockIdx.x, tid = threadIdx.x;
    if (tid < 119) {
        float s = ba2[tid];
        for (int l = 0; l < LL; l++) s += Wa2[tid * LL + l] * g_hax[b * LL + l];
        out[BBATCH*LL + b * 119 + tid] = s;
    } else if (tid < 130) {
        int j = tid - 119;
        float s = bt2[j];
        for (int l = 0; l < LL; l++) s += Wt2[j * LL + l] * g_htx[b * LL + l];
        out[BBATCH*LL + BBATCH*119 + b * 11 + j] = s;
    }
}

/* ---------------- launch --------------------------------------------------- */
extern "C" void kernel_launch(void* const* d_in, const int* in_sizes, int n_in,
                              void* d_out, int out_size) {
    const float* outp   = (const float*)d_in[0];
    const int*   amask  = (const int*)  d_in[1];
    const float* laws   = (const float*)d_in[2];
    const float* Wq     = (const float*)d_in[3];
    const float* bq     = (const float*)d_in[4];
    const float* Wk     = (const float*)d_in[5];
    const float* bk     = (const float*)d_in[6];
    const float* Wv     = (const float*)d_in[7];
    const float* bv     = (const float*)d_in[8];
    const float* w_law_d  = (const float*)d_in[9];
    const float* b_law_d  = (const float*)d_in[10];
    const float* w_law1   = (const float*)d_in[11];
    const float* b_law1   = (const float*)d_in[12];
    const float* w_accu_d = (const float*)d_in[13];
    const float* b_accu_d = (const float*)d_in[14];
    const float* w_accu1  = (const float*)d_in[15];
    const float* b_accu1  = (const float*)d_in[16];
    const float* W_accu2  = (const float*)d_in[17];
    const float* b_accu2  = (const float*)d_in[18];
    const float* w_term_d = (const float*)d_in[19];
    const float* b_term_d = (const float*)d_in[20];
    const float* w_term1  = (const float*)d_in[21];
    const float* b_term1  = (const float*)d_in[22];
    const float* W_term2  = (const float*)d_in[23];
    const float* b_term2  = (const float*)d_in[24];
    float* out = (float*)d_out;

    cudaFuncSetAttribute(k_big_mma, cudaFuncAttributeMaxDynamicSharedMemorySize, SMEM_BIG);

    k_vecs<<<dim3(D, 5), 256>>>(Wv, Wk, Wq, w_law_d, w_accu_d, w_term_d, bq, bk);
    k_scal<<<1, 256>>>(bk, bq, bv, w_law_d, w_accu_d, w_term_d);
    k_wc<<<dim3(D/64, D/64), 256>>>(Wk, Wq);
    k_fk2<<<dim3(D/64, (BBATCH*SSEQ)/64), 256>>>(outp);
    k_colpack<<<BBATCH*SSEQ, 256>>>(outp, amask);
    k_big_mma<<<dim3(M_TOT/128, BBATCH), 512, SMEM_BIG>>>(laws);
    k_heads<<<dim3(LL, BBATCH), 256>>>(b_law_d, w_law1, b_law1,
                                       b_accu_d, w_accu1, b_accu1,
                                       b_term_d, w_term1, b_term1, out);
    k_final<<<BBATCH, 130>>>(W_accu2, b_accu2, W_term2, b_term2, out);
}

// round 7
// speedup vs baseline: 6.4456x; 2.1783x over previous
#include <cuda_runtime.h>
#include <cuda_fp16.h>
#include <math.h>
#include <stdint.h>

#define D   768
#define LL  103
#define RR  512
#define BBATCH 2
#define SSEQ 512
#define M_TOT (LL*RR)              /* 52736 */
#define INV_SQRT_D 0.03608439182435161f

/* ---------------- static device scratch (no allocation allowed) ------------- */
__device__ __align__(128) float  g_Wc[D*D];                /* (Wk @ Wq^T) * inv_sqrt_d  */
__device__ __align__(128) __half g_fk2h[BBATCH*SSEQ*D];    /* half(output @ g_Wc + bkq')*/
__device__ __align__(128) __half g_lawsh[M_TOT*D];         /* half(laws)                */
__device__ __align__(16)  float4 g_colpack[BBATCH*SSEQ];   /* {sbias', vlaw, vaccu, vterm} */
__device__ float  g_u[5][D];
__device__ float  g_c[4];
__device__ __align__(16) float4 g_pre[BBATCH*M_TOT];       /* {law,accu,term,0} pre-act */
__device__ float  g_hax[BBATCH*LL];
__device__ float  g_htx[BBATCH*LL];

/* ---------------- PTX helpers ---------------------------------------------- */
__device__ __forceinline__ uint32_t smem_u32(const void* p) {
    uint32_t a;
    asm("{ .reg .u64 t; cvta.to.shared.u64 t, %1; cvt.u32.u64 %0, t; }" : "=r"(a) : "l"(p));
    return a;
}
__device__ __forceinline__ void cpa16(uint32_t saddr, const void* g) {
    asm volatile("cp.async.cg.shared.global [%0], [%1], 16;" :: "r"(saddr), "l"(g) : "memory");
}
__device__ __forceinline__ void mma_f16_16x8x16(float* d, const uint32_t* a, const uint32_t* b) {
    asm volatile(
        "mma.sync.aligned.m16n8k16.row.col.f32.f16.f16.f32 "
        "{%0,%1,%2,%3}, {%4,%5,%6,%7}, {%8,%9}, {%0,%1,%2,%3};"
        : "+f"(d[0]), "+f"(d[1]), "+f"(d[2]), "+f"(d[3])
        : "r"(a[0]), "r"(a[1]), "r"(a[2]), "r"(a[3]), "r"(b[0]), "r"(b[1]));
}

/* ---------------- laws fp32 -> fp16 ---------------------------------------- */
__global__ void k_cvt(const float* __restrict__ laws) {
    const float4* src = (const float4*)laws;
    uint2* dst = (uint2*)g_lawsh;
    int n4 = M_TOT * D / 4;
    for (int i = blockIdx.x * blockDim.x + threadIdx.x; i < n4;
         i += gridDim.x * blockDim.x) {
        float4 v = src[i];
        __half2 h0 = __floats2half2_rn(v.x, v.y);
        __half2 h1 = __floats2half2_rn(v.z, v.w);
        dst[i] = make_uint2(*(uint32_t*)&h0, *(uint32_t*)&h1);
    }
}

/* ---------------- tiny precompute kernels (warp-per-dot) -------------------- */
__global__ void k_vecs(const float* __restrict__ Wv, const float* __restrict__ Wk,
                       const float* __restrict__ Wq,
                       const float* __restrict__ wl, const float* __restrict__ wa,
                       const float* __restrict__ wt,
                       const float* __restrict__ bq, const float* __restrict__ bk) {
    int gid = blockIdx.x * 8 + (threadIdx.x >> 5);
    int lane = threadIdx.x & 31;
    int w = gid / D, e = gid % D;
    const float *row, *vec; float scale = 1.0f;
    if      (w == 0) { row = Wv + e*D; vec = wl; }
    else if (w == 1) { row = Wv + e*D; vec = wa; }
    else if (w == 2) { row = Wv + e*D; vec = wt; }
    else if (w == 3) { row = Wk + e*D; vec = bq; scale = INV_SQRT_D; }
    else             { row = Wq + e*D; vec = bk; scale = INV_SQRT_D; }
    float p = 0.f;
    for (int d = lane; d < D; d += 32) p += row[d] * vec[d];
    #pragma unroll
    for (int s = 16; s > 0; s >>= 1) p += __shfl_xor_sync(0xFFFFFFFFu, p, s);
    if (lane == 0) g_u[w][e] = p * scale;
}

__global__ void k_scal(const float* __restrict__ bk, const float* __restrict__ bq,
                       const float* __restrict__ bv,
                       const float* __restrict__ wl, const float* __restrict__ wa,
                       const float* __restrict__ wt) {
    int tid = threadIdx.x;
    float p0 = 0, p1 = 0, p2 = 0, p3 = 0;
    for (int d = tid; d < D; d += 256) {
        float b = bv[d];
        p0 += bk[d] * bq[d]; p1 += b * wl[d]; p2 += b * wa[d]; p3 += b * wt[d];
    }
    __shared__ float sm[4][256];
    sm[0][tid] = p0; sm[1][tid] = p1; sm[2][tid] = p2; sm[3][tid] = p3;
    __syncthreads();
    for (int s = 128; s > 0; s >>= 1) {
        if (tid < s) for (int c = 0; c < 4; c++) sm[c][tid] += sm[c][tid + s];
        __syncthreads();
    }
    if (tid == 0) {
        g_c[0] = sm[0][0] * INV_SQRT_D;
        g_c[1] = sm[1][0]; g_c[2] = sm[2][0]; g_c[3] = sm[3][0];
    }
}

/* g_Wc = inv * Wk @ Wq^T : NT GEMM 768x768x768, tiles 64(M)x32(N) */
__global__ __launch_bounds__(256) void k_wc(const float* __restrict__ A,
                                            const float* __restrict__ Bm) {
    __shared__ float As[16][68], Bs[16][36];
    int tid = threadIdx.x, tx = tid % 16, ty = tid / 16;
    int i0 = blockIdx.y * 64, j0 = blockIdx.x * 32;
    int lk = tid % 16, lr = tid / 16;
    float acc[4][2] = {};
    for (int k0 = 0; k0 < D; k0 += 16) {
        #pragma unroll
        for (int i = 0; i < 4; i++)
            As[lk][lr*4+i] = A[(i0 + lr*4 + i)*D + k0 + lk];
        #pragma unroll
        for (int i = 0; i < 2; i++)
            Bs[lk][lr*2+i] = Bm[(j0 + lr*2 + i)*D + k0 + lk];
        __syncthreads();
        #pragma unroll
        for (int k = 0; k < 16; k++) {
            float4 av = *(const float4*)&As[k][ty*4];
            float b0 = Bs[k][tx*2], b1 = Bs[k][tx*2+1];
            float a[4] = {av.x, av.y, av.z, av.w};
            #pragma unroll
            for (int i = 0; i < 4; i++) { acc[i][0] += a[i]*b0; acc[i][1] += a[i]*b1; }
        }
        __syncthreads();
    }
    #pragma unroll
    for (int i = 0; i < 4; i++)
        #pragma unroll
        for (int j = 0; j < 2; j++)
            g_Wc[(i0 + ty*4 + i)*D + j0 + tx*2 + j] = acc[i][j] * INV_SQRT_D;
}

/* g_fk2h = half(output @ g_Wc + bkq') : NN GEMM 1024x768x768, tiles 64x32 */
__global__ __launch_bounds__(256) void k_fk2(const float* __restrict__ A) {
    __shared__ float As[16][68], Bs[16][36];
    int tid = threadIdx.x, tx = tid % 16, ty = tid / 16;
    int i0 = blockIdx.y * 64, j0 = blockIdx.x * 32;
    int lk = tid % 16, lr = tid / 16;
    int ln = tid % 32, lkb = tid / 32;
    float acc[4][2] = {};
    for (int k0 = 0; k0 < D; k0 += 16) {
        #pragma unroll
        for (int i = 0; i < 4; i++)
            As[lk][lr*4+i] = A[(i0 + lr*4 + i)*D + k0 + lk];
        #pragma unroll
        for (int i = 0; i < 2; i++)
            Bs[lkb*2+i][ln] = g_Wc[(k0 + lkb*2 + i)*D + j0 + ln];
        __syncthreads();
        #pragma unroll
        for (int k = 0; k < 16; k++) {
            float4 av = *(const float4*)&As[k][ty*4];
            float b0 = Bs[k][tx*2], b1 = Bs[k][tx*2+1];
            float a[4] = {av.x, av.y, av.z, av.w};
            #pragma unroll
            for (int i = 0; i < 4; i++) { acc[i][0] += a[i]*b0; acc[i][1] += a[i]*b1; }
        }
        __syncthreads();
    }
    #pragma unroll
    for (int i = 0; i < 4; i++)
        #pragma unroll
        for (int j = 0; j < 2; j++)
            g_fk2h[(i0 + ty*4 + i)*D + j0 + tx*2 + j] =
                __float2half_rn(acc[i][j] + g_u[4][j0 + tx*2 + j]);
}

/* per (b,s): sbias' (+mask), and the three v projections  (warp per row) */
__global__ void k_colpack(const float* __restrict__ outp, const int* __restrict__ mask) {
    int row = blockIdx.x * 8 + (threadIdx.x >> 5);
    int lane = threadIdx.x & 31;
    const float* x = outp + (size_t)row * D;
    float p0 = 0, p1 = 0, p2 = 0, p3 = 0;
    for (int d = lane; d < D; d += 32) {
        float xv = x[d];
        p0 += xv * g_u[3][d]; p1 += xv * g_u[0][d];
        p2 += xv * g_u[1][d]; p3 += xv * g_u[2][d];
    }
    #pragma unroll
    for (int s = 16; s > 0; s >>= 1) {
        p0 += __shfl_xor_sync(0xFFFFFFFFu, p0, s);
        p1 += __shfl_xor_sync(0xFFFFFFFFu, p1, s);
        p2 += __shfl_xor_sync(0xFFFFFFFFu, p2, s);
        p3 += __shfl_xor_sync(0xFFFFFFFFu, p3, s);
    }
    if (lane == 0) {
        float sb = p0 + g_c[0] + (1.0f - (float)mask[row]) * (-10000.0f);
        g_colpack[row] = make_float4(sb, p1 + g_c[1], p2 + g_c[2], p3 + g_c[3]);
    }
}

/* ------------- big fused kernel: fp16 mma.sync GEMM + softmax epilogue ------ */
/* CTA: 512 thr (16 warps, 4x4). Tile M=128, N=256 per chunk, 2 chunks.        */
/* 4-stage cp.async pipeline. Stage = A 128x80B + B 256x80B = 30720 B.         */
#define KT        32               /* halves per K chunk */
#define NKC       (D/KT)           /* 24 */
#define RSW       20               /* smem row stride in 32-bit words (80 B)   */
#define STG_B     30720
#define SMEM_BIG  139264

__global__ __launch_bounds__(512) void k_big_h(int dummy) {
    extern __shared__ float smf[];
    uint32_t sb = smem_u32(smf);
    const uint32_t* smw = (const uint32_t*)smf;
    int tid = threadIdx.x, lane = tid & 31, wid = tid >> 5;
    int wm = wid >> 2, wn = wid & 3;
    int g = lane >> 2, c = lane & 3;
    int b = blockIdx.y, m0 = blockIdx.x * 128;
    const __half* fk2b = g_fk2h + (size_t)b * SSEQ * D;

    float4* scp  = (float4*)(smf + 30720);   /* byte 122880, 8 KB */
    float4* red4 = (float4*)(smf + 32768);   /* byte 131072, 8 KB */

    { const float4* gcp = g_colpack + b * SSEQ;
      for (int i = tid; i < SSEQ; i += 512) scp[i] = gcp[i]; }

    float rs[2][2][4];
    #pragma unroll
    for (int mt = 0; mt < 2; mt++)
        #pragma unroll
        for (int h = 0; h < 2; h++)
            #pragma unroll
            for (int e = 0; e < 4; e++) rs[mt][h][e] = 0.f;

#define LOADH(st, kc, n0) do {                                                 \
        uint32_t Ab = sb + (st) * STG_B;                                       \
        uint32_t Bb = Ab + 10240;                                              \
        const __half* asrc = g_lawsh + (size_t)m0 * D + (kc) * KT;             \
        const __half* bsrc = fk2b + (size_t)(n0) * D + (kc) * KT;              \
        { int row = tid >> 2, seg = tid & 3;                                   \
          cpa16(Ab + row * 80 + seg * 16, asrc + (size_t)row * D + seg * 8); } \
        { int row = tid >> 2, seg = tid & 3;                                   \
          cpa16(Bb + row * 80 + seg * 16, bsrc + (size_t)row * D + seg * 8); } \
        { int i2 = tid + 512; int row = i2 >> 2, seg = i2 & 3;                 \
          cpa16(Bb + row * 80 + seg * 16, bsrc + (size_t)row * D + seg * 8); } \
        asm volatile("cp.async.commit_group;" ::: "memory");                   \
    } while (0)

    for (int chunk = 0; chunk < 2; chunk++) {
        int n0 = chunk * 256;
        float acc[2][8][4];
        #pragma unroll
        for (int mt = 0; mt < 2; mt++)
            #pragma unroll
            for (int nt = 0; nt < 8; nt++)
                #pragma unroll
                for (int e = 0; e < 4; e++) acc[mt][nt][e] = 0.f;

        LOADH(0, 0, n0); LOADH(1, 1, n0); LOADH(2, 2, n0);

        for (int kc = 0; kc < NKC; kc++) {
            asm volatile("cp.async.wait_group 2;" ::: "memory");
            __syncthreads();
            if (kc + 3 < NKC) LOADH((kc + 3) & 3, kc + 3, n0);
            else asm volatile("cp.async.commit_group;" ::: "memory");

            const uint32_t* Aw = smw + (kc & 3) * (STG_B / 4);
            const uint32_t* Bw = Aw + 2560;
            #pragma unroll
            for (int s2 = 0; s2 < 2; s2++) {
                int kw = s2 * 8;
                uint32_t af[2][4], bf[8][2];
                #pragma unroll
                for (int mt = 0; mt < 2; mt++) {
                    int m = wm * 32 + mt * 16 + g;
                    af[mt][0] = Aw[m * RSW + kw + c];
                    af[mt][1] = Aw[(m + 8) * RSW + kw + c];
                    af[mt][2] = Aw[m * RSW + kw + c + 4];
                    af[mt][3] = Aw[(m + 8) * RSW + kw + c + 4];
                }
                #pragma unroll
                for (int nt = 0; nt < 8; nt++) {
                    int n = wn * 64 + nt * 8 + g;
                    bf[nt][0] = Bw[n * RSW + kw + c];
                    bf[nt][1] = Bw[n * RSW + kw + c + 4];
                }
                #pragma unroll
                for (int mt = 0; mt < 2; mt++)
                    #pragma unroll
                    for (int nt = 0; nt < 8; nt++)
                        mma_f16_16x8x16(acc[mt][nt], af[mt], bf[nt]);
            }
        }

        /* fused epilogue: exp + online weighted sums */
        #pragma unroll
        for (int mt = 0; mt < 2; mt++) {
            #pragma unroll
            for (int nt = 0; nt < 8; nt++) {
                int s = chunk * 256 + wn * 64 + nt * 8 + 2 * c;
                float4 cp0 = scp[s], cp1 = scp[s + 1];
                float e0 = __expf(acc[mt][nt][0] + cp0.x);
                rs[mt][0][0] += e0; rs[mt][0][1] += e0 * cp0.y;
                rs[mt][0][2] += e0 * cp0.z; rs[mt][0][3] += e0 * cp0.w;
                float e1 = __expf(acc[mt][nt][1] + cp1.x);
                rs[mt][0][0] += e1; rs[mt][0][1] += e1 * cp1.y;
                rs[mt][0][2] += e1 * cp1.z; rs[mt][0][3] += e1 * cp1.w;
                float e2 = __expf(acc[mt][nt][2] + cp0.x);
                rs[mt][1][0] += e2; rs[mt][1][1] += e2 * cp0.y;
                rs[mt][1][2] += e2 * cp0.z; rs[mt][1][3] += e2 * cp0.w;
                float e3 = __expf(acc[mt][nt][3] + cp1.x);
                rs[mt][1][0] += e3; rs[mt][1][1] += e3 * cp1.y;
                rs[mt][1][2] += e3 * cp1.z; rs[mt][1][3] += e3 * cp1.w;
            }
        }
    }
#undef LOADH

    /* reduce across the 4 lanes of each quad (cols), then across wn warps */
    #pragma unroll
    for (int mt = 0; mt < 2; mt++)
        #pragma unroll
        for (int h = 0; h < 2; h++)
            #pragma unroll
            for (int e = 0; e < 4; e++) {
                float v = rs[mt][h][e];
                v += __shfl_xor_sync(0xFFFFFFFFu, v, 1);
                v += __shfl_xor_sync(0xFFFFFFFFu, v, 2);
                rs[mt][h][e] = v;
            }
    __syncthreads();
    if (c == 0) {
        #pragma unroll
        for (int mt = 0; mt < 2; mt++)
            #pragma unroll
            for (int h = 0; h < 2; h++) {
                int row = wm * 32 + mt * 16 + h * 8 + g;
                red4[wn * 128 + row] = make_float4(rs[mt][h][0], rs[mt][h][1],
                                                   rs[mt][h][2], rs[mt][h][3]);
            }
    }
    __syncthreads();
    if (tid < 128) {
        float4 a0 = red4[tid], a1 = red4[128 + tid],
               a2 = red4[256 + tid], a3 = red4[384 + tid];
        float den = a0.x + a1.x + a2.x + a3.x;
        float inv = 1.0f / den;
        g_pre[(size_t)b * M_TOT + m0 + tid] =
            make_float4((a0.y + a1.y + a2.y + a3.y) * inv,
                        (a0.z + a1.z + a2.z + a3.z) * inv,
                        (a0.w + a1.w + a2.w + a3.w) * inv, 0.f);
    }
}

/* ------------- heads ------------------------------------------------------- */
__global__ void k_heads(const float* __restrict__ b_law_d, const float* __restrict__ w_law1,
                        const float* __restrict__ b_law1,
                        const float* __restrict__ b_accu_d, const float* __restrict__ w_accu1,
                        const float* __restrict__ b_accu1,
                        const float* __restrict__ b_term_d, const float* __restrict__ w_term1,
                        const float* __restrict__ b_term1,
                        float* __restrict__ out) {
    int l = blockIdx.x, b = blockIdx.y, tid = threadIdx.x;
    float bl = b_law_d[0], ba = b_accu_d[0], bt = b_term_d[0];
    float s0 = 0, s1 = 0, s2 = 0;
    for (int r = tid; r < RR; r += 256) {
        float4 p = g_pre[(size_t)b * M_TOT + l * RR + r];
        s0 += tanhf(p.x + bl) * w_law1[r];
        s1 += tanhf(p.y + ba) * w_accu1[r];
        s2 += tanhf(p.z + bt) * w_term1[r];
    }
    __shared__ float sm[3][256];
    sm[0][tid] = s0; sm[1][tid] = s1; sm[2][tid] = s2;
    __syncthreads();
    for (int s = 128; s > 0; s >>= 1) {
        if (tid < s) for (int c = 0; c < 3; c++) sm[c][tid] += sm[c][tid + s];
        __syncthreads();
    }
    if (tid == 0) {
        out[b * LL + l] = sm[0][0] + b_law1[0];
        g_hax[b * LL + l] = tanhf(sm[1][0] + b_accu1[0]);
        g_htx[b * LL + l] = tanhf(sm[2][0] + b_term1[0]);
    }
}

__global__ void k_final(const float* __restrict__ Wa2, const float* __restrict__ ba2,
                        const float* __restrict__ Wt2, const float* __restrict__ bt2,
                        float* __restrict__ out) {
    int b = blockIdx.x, tid = threadIdx.x;
    if (tid < 119) {
        float s = ba2[tid];
        for (int l = 0; l < LL; l++) s += Wa2[tid * LL + l] * g_hax[b * LL + l];
        out[BBATCH*LL + b * 119 + tid] = s;
    } else if (tid < 130) {
        int j = tid - 119;
        float s = bt2[j];
        for (int l = 0; l < LL; l++) s += Wt2[j * LL + l] * g_htx[b * LL + l];
        out[BBATCH*LL + BBATCH*119 + b * 11 + j] = s;
    }
}

/* ---------------- launch --------------------------------------------------- */
extern "C" void kernel_launch(void* const* d_in, const int* in_sizes, int n_in,
                              void* d_out, int out_size) {
    const float* outp   = (const float*)d_in[0];
    const int*   amask  = (const int*)  d_in[1];
    const float* laws   = (const float*)d_in[2];
    const float* Wq     = (const float*)d_in[3];
    const float* bq     = (const float*)d_in[4];
    const float* Wk     = (const float*)d_in[5];
    const float* bk     = (const float*)d_in[6];
    const float* Wv     = (const float*)d_in[7];
    const float* bv     = (const float*)d_in[8];
    const float* w_law_d  = (const float*)d_in[9];
    const float* b_law_d  = (const float*)d_in[10];
    const float* w_law1   = (const float*)d_in[11];
    const float* b_law1   = (const float*)d_in[12];
    const float* w_accu_d = (const float*)d_in[13];
    const float* b_accu_d = (const float*)d_in[14];
    const float* w_accu1  = (const float*)d_in[15];
    const float* b_accu1  = (const float*)d_in[16];
    const float* W_accu2  = (const float*)d_in[17];
    const float* b_accu2  = (const float*)d_in[18];
    const float* w_term_d = (const float*)d_in[19];
    const float* b_term_d = (const float*)d_in[20];
    const float* w_term1  = (const float*)d_in[21];
    const float* b_term1  = (const float*)d_in[22];
    const float* W_term2  = (const float*)d_in[23];
    const float* b_term2  = (const float*)d_in[24];
    float* out = (float*)d_out;

    cudaFuncSetAttribute(k_big_h, cudaFuncAttributeMaxDynamicSharedMemorySize, SMEM_BIG);

    k_cvt<<<2048, 256>>>(laws);
    k_vecs<<<480, 256>>>(Wv, Wk, Wq, w_law_d, w_accu_d, w_term_d, bq, bk);
    k_scal<<<1, 256>>>(bk, bq, bv, w_law_d, w_accu_d, w_term_d);
    k_wc<<<dim3(D/32, D/64), 256>>>(Wk, Wq);
    k_fk2<<<dim3(D/32, (BBATCH*SSEQ)/64), 256>>>(outp);
    k_colpack<<<BBATCH*SSEQ/8, 256>>>(outp, amask);
    k_big_h<<<dim3(M_TOT/128, BBATCH), 512, SMEM_BIG>>>(0);
    k_heads<<<dim3(LL, BBATCH), 256>>>(b_law_d, w_law1, b_law1,
                                       b_accu_d, w_accu1, b_accu1,
                                       b_term_d, w_term1, b_term1, out);
    k_final<<<BBATCH, 130>>>(W_accu2, b_accu2, W_term2, b_term2, out);
}

// round 9
// speedup vs baseline: 7.0100x; 1.0876x over previous
#include <cuda_runtime.h>
#include <cuda_fp16.h>
#include <math.h>
#include <stdint.h>

#define D   768
#define LL  103
#define RR  512
#define BBATCH 2
#define SSEQ 512
#define M_TOT (LL*RR)              /* 52736 */
#define INV_SQRT_D 0.03608439182435161f

/* ---------------- static device scratch (no allocation allowed) ------------- */
__device__ __align__(128) float  g_Wct[D*D];               /* (Wq @ Wk^T)*inv = Wc^T    */
__device__ __align__(128) __half g_fk2h[BBATCH*SSEQ*D];    /* half(output @ Wc + bkq')  */
__device__ __align__(128) __half g_lawsh[M_TOT*D];         /* half(laws)                */
__device__ __align__(16)  float4 g_colpack[BBATCH*SSEQ];   /* {sbias', vlaw, vaccu, vterm} */
__device__ float  g_u[5][D];
__device__ float  g_c[4];
__device__ __align__(16) float4 g_pre[BBATCH*M_TOT];       /* {law,accu,term,0} pre-act */
__device__ float  g_hax[BBATCH*LL];
__device__ float  g_htx[BBATCH*LL];

/* ---------------- PTX helpers ---------------------------------------------- */
__device__ __forceinline__ uint32_t smem_u32(const void* p) {
    uint32_t a;
    asm("{ .reg .u64 t; cvta.to.shared.u64 t, %1; cvt.u32.u64 %0, t; }" : "=r"(a) : "l"(p));
    return a;
}
__device__ __forceinline__ void cpa16(uint32_t saddr, const void* g) {
    asm volatile("cp.async.cg.shared.global [%0], [%1], 16;" :: "r"(saddr), "l"(g) : "memory");
}
__device__ __forceinline__ void mma_f16_16x8x16(float* d, const uint32_t* a, const uint32_t* b) {
    asm volatile(
        "mma.sync.aligned.m16n8k16.row.col.f32.f16.f16.f32 "
        "{%0,%1,%2,%3}, {%4,%5,%6,%7}, {%8,%9}, {%0,%1,%2,%3};"
        : "+f"(d[0]), "+f"(d[1]), "+f"(d[2]), "+f"(d[3])
        : "r"(a[0]), "r"(a[1]), "r"(a[2]), "r"(a[3]), "r"(b[0]), "r"(b[1]));
}
__device__ __forceinline__ void mma_tf32_16x8x8(float* d, const uint32_t* a, const uint32_t* b) {
    asm volatile(
        "mma.sync.aligned.m16n8k8.row.col.f32.tf32.tf32.f32 "
        "{%0,%1,%2,%3}, {%4,%5,%6,%7}, {%8,%9}, {%0,%1,%2,%3};"
        : "+f"(d[0]), "+f"(d[1]), "+f"(d[2]), "+f"(d[3])
        : "r"(a[0]), "r"(a[1]), "r"(a[2]), "r"(a[3]), "r"(b[0]), "r"(b[1]));
}
/* split fp32 into tf32-exact hi + residual lo (3xTF32 compensation) */
__device__ __forceinline__ void tf32_split(uint32_t u, uint32_t& hi, uint32_t& lo) {
    hi = u & 0xFFFFE000u;
    lo = __float_as_uint(__uint_as_float(u) - __uint_as_float(hi));
}

/* ---------------- laws fp32 -> fp16 ---------------------------------------- */
__global__ void k_cvt(const float* __restrict__ laws) {
    const float4* src = (const float4*)laws;
    uint2* dst = (uint2*)g_lawsh;
    int n4 = M_TOT * D / 4;
    for (int i = blockIdx.x * blockDim.x + threadIdx.x; i < n4;
         i += gridDim.x * blockDim.x) {
        float4 v = src[i];
        __half2 h0 = __floats2half2_rn(v.x, v.y);
        __half2 h1 = __floats2half2_rn(v.z, v.w);
        dst[i] = make_uint2(*(uint32_t*)&h0, *(uint32_t*)&h1);
    }
}

/* ---------------- tiny precompute kernels (warp-per-dot) -------------------- */
__global__ void k_vecs(const float* __restrict__ Wv, const float* __restrict__ Wk,
                       const float* __restrict__ Wq,
                       const float* __restrict__ wl, const float* __restrict__ wa,
                       const float* __restrict__ wt,
                       const float* __restrict__ bq, const float* __restrict__ bk) {
    int gid = blockIdx.x * 8 + (threadIdx.x >> 5);
    int lane = threadIdx.x & 31;
    int w = gid / D, e = gid % D;
    const float *row, *vec; float scale = 1.0f;
    if      (w == 0) { row = Wv + e*D; vec = wl; }
    else if (w == 1) { row = Wv + e*D; vec = wa; }
    else if (w == 2) { row = Wv + e*D; vec = wt; }
    else if (w == 3) { row = Wk + e*D; vec = bq; scale = INV_SQRT_D; }
    else             { row = Wq + e*D; vec = bk; scale = INV_SQRT_D; }
    float p = 0.f;
    for (int d = lane; d < D; d += 32) p += row[d] * vec[d];
    #pragma unroll
    for (int s = 16; s > 0; s >>= 1) p += __shfl_xor_sync(0xFFFFFFFFu, p, s);
    if (lane == 0) g_u[w][e] = p * scale;
}

__global__ void k_scal(const float* __restrict__ bk, const float* __restrict__ bq,
                       const float* __restrict__ bv,
                       const float* __restrict__ wl, const float* __restrict__ wa,
                       const float* __restrict__ wt) {
    int tid = threadIdx.x;
    float p0 = 0, p1 = 0, p2 = 0, p3 = 0;
    for (int d = tid; d < D; d += 256) {
        float b = bv[d];
        p0 += bk[d] * bq[d]; p1 += b * wl[d]; p2 += b * wa[d]; p3 += b * wt[d];
    }
    __shared__ float sm[4][256];
    sm[0][tid] = p0; sm[1][tid] = p1; sm[2][tid] = p2; sm[3][tid] = p3;
    __syncthreads();
    for (int s = 128; s > 0; s >>= 1) {
        if (tid < s) for (int c = 0; c < 4; c++) sm[c][tid] += sm[c][tid + s];
        __syncthreads();
    }
    if (tid == 0) {
        g_c[0] = sm[0][0] * INV_SQRT_D;
        g_c[1] = sm[1][0]; g_c[2] = sm[2][0]; g_c[3] = sm[3][0];
    }
}

/* ---- 3xTF32 mma GEMM (NT): g_Wct = inv * Wq @ Wk^T  (768x768x768) ---------- */
__global__ __launch_bounds__(256) void k_wc_t(const float* __restrict__ A,
                                              const float* __restrict__ B) {
    __shared__ float As[2][1280], Bs[2][1280];   /* 64 rows x 20 floats */
    int tid = threadIdx.x, lane = tid & 31, wid = tid >> 5;
    int wm = wid >> 2, wn = wid & 3, g = lane >> 2, c = lane & 3;
    int i0 = blockIdx.y * 64, j0 = blockIdx.x * 64;
    uint32_t sa = smem_u32(As), sbm = smem_u32(Bs);
    int row = tid >> 2, seg = tid & 3;
    float acc[2][2][4] = {};

#define LDWC(st, kc) do {                                                      \
        cpa16(sa  + (st)*5120 + row*80 + seg*16,                               \
              A + (size_t)(i0 + row)*D + (kc)*16 + seg*4);                     \
        cpa16(sbm + (st)*5120 + row*80 + seg*16,                               \
              B + (size_t)(j0 + row)*D + (kc)*16 + seg*4);                     \
        asm volatile("cp.async.commit_group;" ::: "memory");                   \
    } while (0)

    LDWC(0, 0);
    for (int kc = 0; kc < 48; kc++) {
        if (kc + 1 < 48) {
            LDWC((kc + 1) & 1, kc + 1);
            asm volatile("cp.async.wait_group 1;" ::: "memory");
        } else {
            asm volatile("cp.async.wait_group 0;" ::: "memory");
        }
        __syncthreads();
        const float* Aw = As[kc & 1];
        const float* Bw = Bs[kc & 1];
        #pragma unroll
        for (int s2 = 0; s2 < 2; s2++) {
            int kw = s2 * 8;
            uint32_t ah[2][4], al[2][4], bh[2][2], bl[2][2];
            #pragma unroll
            for (int mt = 0; mt < 2; mt++) {
                int m = wm * 32 + mt * 16 + g;
                tf32_split(__float_as_uint(Aw[m * 20 + kw + c]),        ah[mt][0], al[mt][0]);
                tf32_split(__float_as_uint(Aw[(m + 8) * 20 + kw + c]),  ah[mt][1], al[mt][1]);
                tf32_split(__float_as_uint(Aw[m * 20 + kw + c + 4]),    ah[mt][2], al[mt][2]);
                tf32_split(__float_as_uint(Aw[(m + 8) * 20 + kw + c+4]),ah[mt][3], al[mt][3]);
            }
            #pragma unroll
            for (int nt = 0; nt < 2; nt++) {
                int n = wn * 16 + nt * 8 + g;
                tf32_split(__float_as_uint(Bw[n * 20 + kw + c]),     bh[nt][0], bl[nt][0]);
                tf32_split(__float_as_uint(Bw[n * 20 + kw + c + 4]), bh[nt][1], bl[nt][1]);
            }
            #pragma unroll
            for (int mt = 0; mt < 2; mt++)
                #pragma unroll
                for (int nt = 0; nt < 2; nt++) {
                    mma_tf32_16x8x8(acc[mt][nt], ah[mt], bl[nt]);
                    mma_tf32_16x8x8(acc[mt][nt], al[mt], bh[nt]);
                    mma_tf32_16x8x8(acc[mt][nt], ah[mt], bh[nt]);
                }
        }
        __syncthreads();
    }
#undef LDWC
    #pragma unroll
    for (int mt = 0; mt < 2; mt++)
        #pragma unroll
        for (int nt = 0; nt < 2; nt++) {
            int r0 = i0 + wm * 32 + mt * 16 + g;
            int col = j0 + wn * 16 + nt * 8 + 2 * c;
            g_Wct[(size_t)r0 * D + col]       = acc[mt][nt][0] * INV_SQRT_D;
            g_Wct[(size_t)r0 * D + col + 1]   = acc[mt][nt][1] * INV_SQRT_D;
            g_Wct[(size_t)(r0+8) * D + col]   = acc[mt][nt][2] * INV_SQRT_D;
            g_Wct[(size_t)(r0+8) * D + col+1] = acc[mt][nt][3] * INV_SQRT_D;
        }
}

/* ---- 3xTF32 mma GEMM (NT): g_fk2h = half(output @ Wct^T + bkq') ------------ */
__global__ __launch_bounds__(256) void k_fk2_t(const float* __restrict__ A) {
    __shared__ float As[2][1280], Bs[2][1280];
    int tid = threadIdx.x, lane = tid & 31, wid = tid >> 5;
    int wm = wid >> 2, wn = wid & 3, g = lane >> 2, c = lane & 3;
    int i0 = blockIdx.y * 64, j0 = blockIdx.x * 64;
    uint32_t sa = smem_u32(As), sbm = smem_u32(Bs);
    int row = tid >> 2, seg = tid & 3;
    float acc[2][2][4] = {};

#define LDFK(st, kc) do {                                                      \
        cpa16(sa  + (st)*5120 + row*80 + seg*16,                               \
              A + (size_t)(i0 + row)*D + (kc)*16 + seg*4);                     \
        cpa16(sbm + (st)*5120 + row*80 + seg*16,                               \
              g_Wct + (size_t)(j0 + row)*D + (kc)*16 + seg*4);                 \
        asm volatile("cp.async.commit_group;" ::: "memory");                   \
    } while (0)

    LDFK(0, 0);
    for (int kc = 0; kc < 48; kc++) {
        if (kc + 1 < 48) {
            LDFK((kc + 1) & 1, kc + 1);
            asm volatile("cp.async.wait_group 1;" ::: "memory");
        } else {
            asm volatile("cp.async.wait_group 0;" ::: "memory");
        }
        __syncthreads();
        const float* Aw = As[kc & 1];
        const float* Bw = Bs[kc & 1];
        #pragma unroll
        for (int s2 = 0; s2 < 2; s2++) {
            int kw = s2 * 8;
            uint32_t ah[2][4], al[2][4], bh[2][2], bl[2][2];
            #pragma unroll
            for (int mt = 0; mt < 2; mt++) {
                int m = wm * 32 + mt * 16 + g;
                tf32_split(__float_as_uint(Aw[m * 20 + kw + c]),        ah[mt][0], al[mt][0]);
                tf32_split(__float_as_uint(Aw[(m + 8) * 20 + kw + c]),  ah[mt][1], al[mt][1]);
                tf32_split(__float_as_uint(Aw[m * 20 + kw + c + 4]),    ah[mt][2], al[mt][2]);
                tf32_split(__float_as_uint(Aw[(m + 8) * 20 + kw + c+4]),ah[mt][3], al[mt][3]);
            }
            #pragma unroll
            for (int nt = 0; nt < 2; nt++) {
                int n = wn * 16 + nt * 8 + g;
                tf32_split(__float_as_uint(Bw[n * 20 + kw + c]),     bh[nt][0], bl[nt][0]);
                tf32_split(__float_as_uint(Bw[n * 20 + kw + c + 4]), bh[nt][1], bl[nt][1]);
            }
            #pragma unroll
            for (int mt = 0; mt < 2; mt++)
                #pragma unroll
                for (int nt = 0; nt < 2; nt++) {
                    mma_tf32_16x8x8(acc[mt][nt], ah[mt], bl[nt]);
                    mma_tf32_16x8x8(acc[mt][nt], al[mt], bh[nt]);
                    mma_tf32_16x8x8(acc[mt][nt], ah[mt], bh[nt]);
                }
        }
        __syncthreads();
    }
#undef LDFK
    #pragma unroll
    for (int mt = 0; mt < 2; mt++)
        #pragma unroll
        for (int nt = 0; nt < 2; nt++) {
            int r0 = i0 + wm * 32 + mt * 16 + g;
            int col = j0 + wn * 16 + nt * 8 + 2 * c;
            float b0 = g_u[4][col], b1 = g_u[4][col + 1];
            g_fk2h[(size_t)r0 * D + col]       = __float2half_rn(acc[mt][nt][0] + b0);
            g_fk2h[(size_t)r0 * D + col + 1]   = __float2half_rn(acc[mt][nt][1] + b1);
            g_fk2h[(size_t)(r0+8) * D + col]   = __float2half_rn(acc[mt][nt][2] + b0);
            g_fk2h[(size_t)(r0+8) * D + col+1] = __float2half_rn(acc[mt][nt][3] + b1);
        }
}

/* per (b,s): sbias' (+mask), and the three v projections  (warp per row) */
__global__ void k_colpack(const float* __restrict__ outp, const int* __restrict__ mask) {
    int row = blockIdx.x * 8 + (threadIdx.x >> 5);
    int lane = threadIdx.x & 31;
    const float* x = outp + (size_t)row * D;
    float p0 = 0, p1 = 0, p2 = 0, p3 = 0;
    for (int d = lane; d < D; d += 32) {
        float xv = x[d];
        p0 += xv * g_u[3][d]; p1 += xv * g_u[0][d];
        p2 += xv * g_u[1][d]; p3 += xv * g_u[2][d];
    }
    #pragma unroll
    for (int s = 16; s > 0; s >>= 1) {
        p0 += __shfl_xor_sync(0xFFFFFFFFu, p0, s);
        p1 += __shfl_xor_sync(0xFFFFFFFFu, p1, s);
        p2 += __shfl_xor_sync(0xFFFFFFFFu, p2, s);
        p3 += __shfl_xor_sync(0xFFFFFFFFu, p3, s);
    }
    if (lane == 0) {
        float sb = p0 + g_c[0] + (1.0f - (float)mask[row]) * (-10000.0f);
        g_colpack[row] = make_float4(sb, p1 + g_c[1], p2 + g_c[2], p3 + g_c[3]);
    }
}

/* ------------- big fused kernel: fp16 mma.sync GEMM + softmax epilogue ------ */
#define KT        32               /* halves per K chunk */
#define NKC       (D/KT)           /* 24 */
#define RSW       20               /* smem row stride in 32-bit words (80 B)   */
#define STG_B     30720
#define SMEM_BIG  139264

__global__ __launch_bounds__(512) void k_big_h(int dummy) {
    extern __shared__ float smf[];
    uint32_t sb = smem_u32(smf);
    const uint32_t* smw = (const uint32_t*)smf;
    int tid = threadIdx.x, lane = tid & 31, wid = tid >> 5;
    int wm = wid >> 2, wn = wid & 3;
    int g = lane >> 2, c = lane & 3;
    int b = blockIdx.y, m0 = blockIdx.x * 128;
    const __half* fk2b = g_fk2h + (size_t)b * SSEQ * D;

    float4* scp  = (float4*)(smf + 30720);
    float4* red4 = (float4*)(smf + 32768);

    { const float4* gcp = g_colpack + b * SSEQ;
      for (int i = tid; i < SSEQ; i += 512) scp[i] = gcp[i]; }

    float rs[2][2][4];
    #pragma unroll
    for (int mt = 0; mt < 2; mt++)
        #pragma unroll
        for (int h = 0; h < 2; h++)
            #pragma unroll
            for (int e = 0; e < 4; e++) rs[mt][h][e] = 0.f;

#define LOADH(st, kc, n0) do {                                                 \
        uint32_t Ab = sb + (st) * STG_B;                                       \
        uint32_t Bb = Ab + 10240;                                              \
        const __half* asrc = g_lawsh + (size_t)m0 * D + (kc) * KT;             \
        const __half* bsrc = fk2b + (size_t)(n0) * D + (kc) * KT;              \
        { int row = tid >> 2, seg = tid & 3;                                   \
          cpa16(Ab + row * 80 + seg * 16, asrc + (size_t)row * D + seg * 8); } \
        { int row = tid >> 2, seg = tid & 3;                                   \
          cpa16(Bb + row * 80 + seg * 16, bsrc + (size_t)row * D + seg * 8); } \
        { int i2 = tid + 512; int row = i2 >> 2, seg = i2 & 3;                 \
          cpa16(Bb + row * 80 + seg * 16, bsrc + (size_t)row * D + seg * 8); } \
        asm volatile("cp.async.commit_group;" ::: "memory");                   \
    } while (0)

    for (int chunk = 0; chunk < 2; chunk++) {
        int n0 = chunk * 256;
        float acc[2][8][4];
        #pragma unroll
        for (int mt = 0; mt < 2; mt++)
            #pragma unroll
            for (int nt = 0; nt < 8; nt++)
                #pragma unroll
                for (int e = 0; e < 4; e++) acc[mt][nt][e] = 0.f;

        LOADH(0, 0, n0); LOADH(1, 1, n0); LOADH(2, 2, n0);

        for (int kc = 0; kc < NKC; kc++) {
            asm volatile("cp.async.wait_group 2;" ::: "memory");
            __syncthreads();
            if (kc + 3 < NKC) LOADH((kc + 3) & 3, kc + 3, n0);
            else asm volatile("cp.async.commit_group;" ::: "memory");

            const uint32_t* Aw = smw + (kc & 3) * (STG_B / 4);
            const uint32_t* Bw = Aw + 2560;
            #pragma unroll
            for (int s2 = 0; s2 < 2; s2++) {
                int kw = s2 * 8;
                uint32_t af[2][4], bf[8][2];
                #pragma unroll
                for (int mt = 0; mt < 2; mt++) {
                    int m = wm * 32 + mt * 16 + g;
                    af[mt][0] = Aw[m * RSW + kw + c];
                    af[mt][1] = Aw[(m + 8) * RSW + kw + c];
                    af[mt][2] = Aw[m * RSW + kw + c + 4];
                    af[mt][3] = Aw[(m + 8) * RSW + kw + c + 4];
                }
                #pragma unroll
                for (int nt = 0; nt < 8; nt++) {
                    int n = wn * 64 + nt * 8 + g;
                    bf[nt][0] = Bw[n * RSW + kw + c];
                    bf[nt][1] = Bw[n * RSW + kw + c + 4];
                }
                #pragma unroll
                for (int mt = 0; mt < 2; mt++)
                    #pragma unroll
                    for (int nt = 0; nt < 8; nt++)
                        mma_f16_16x8x16(acc[mt][nt], af[mt], bf[nt]);
            }
        }

        #pragma unroll
        for (int mt = 0; mt < 2; mt++) {
            #pragma unroll
            for (int nt = 0; nt < 8; nt++) {
                int s = chunk * 256 + wn * 64 + nt * 8 + 2 * c;
                float4 cp0 = scp[s], cp1 = scp[s + 1];
                float e0 = __expf(acc[mt][nt][0] + cp0.x);
                rs[mt][0][0] += e0; rs[mt][0][1] += e0 * cp0.y;
                rs[mt][0][2] += e0 * cp0.z; rs[mt][0][3] += e0 * cp0.w;
                float e1 = __expf(acc[mt][nt][1] + cp1.x);
                rs[mt][0][0] += e1; rs[mt][0][1] += e1 * cp1.y;
                rs[mt][0][2] += e1 * cp1.z; rs[mt][0][3] += e1 * cp1.w;
                float e2 = __expf(acc[mt][nt][2] + cp0.x);
                rs[mt][1][0] += e2; rs[mt][1][1] += e2 * cp0.y;
                rs[mt][1][2] += e2 * cp0.z; rs[mt][1][3] += e2 * cp0.w;
                float e3 = __expf(acc[mt][nt][3] + cp1.x);
                rs[mt][1][0] += e3; rs[mt][1][1] += e3 * cp1.y;
                rs[mt][1][2] += e3 * cp1.z; rs[mt][1][3] += e3 * cp1.w;
            }
        }
    }
#undef LOADH

    #pragma unroll
    for (int mt = 0; mt < 2; mt++)
        #pragma unroll
        for (int h = 0; h < 2; h++)
            #pragma unroll
            for (int e = 0; e < 4; e++) {
                float v = rs[mt][h][e];
                v += __shfl_xor_sync(0xFFFFFFFFu, v, 1);
                v += __shfl_xor_sync(0xFFFFFFFFu, v, 2);
                rs[mt][h][e] = v;
            }
    __syncthreads();
    if (c == 0) {
        #pragma unroll
        for (int mt = 0; mt < 2; mt++)
            #pragma unroll
            for (int h = 0; h < 2; h++) {
                int row = wm * 32 + mt * 16 + h * 8 + g;
                red4[wn * 128 + row] = make_float4(rs[mt][h][0], rs[mt][h][1],
                                                   rs[mt][h][2], rs[mt][h][3]);
            }
    }
    __syncthreads();
    if (tid < 128) {
        float4 a0 = red4[tid], a1 = red4[128 + tid],
               a2 = red4[256 + tid], a3 = red4[384 + tid];
        float den = a0.x + a1.x + a2.x + a3.x;
        float inv = 1.0f / den;
        g_pre[(size_t)b * M_TOT + m0 + tid] =
            make_float4((a0.y + a1.y + a2.y + a3.y) * inv,
                        (a0.z + a1.z + a2.z + a3.z) * inv,
                        (a0.w + a1.w + a2.w + a3.w) * inv, 0.f);
    }
}

/* ------------- heads ------------------------------------------------------- */
__global__ void k_heads(const float* __restrict__ b_law_d, const float* __restrict__ w_law1,
                        const float* __restrict__ b_law1,
                        const float* __restrict__ b_accu_d, const float* __restrict__ w_accu1,
                        const float* __restrict__ b_accu1,
                        const float* __restrict__ b_term_d, const float* __restrict__ w_term1,
                        const float* __restrict__ b_term1,
                        float* __restrict__ out) {
    int l = blockIdx.x, b = blockIdx.y, tid = threadIdx.x;
    float bl = b_law_d[0], ba = b_accu_d[0], bt = b_term_d[0];
    float s0 = 0, s1 = 0, s2 = 0;
    for (int r = tid; r < RR; r += 256) {
        float4 p = g_pre[(size_t)b * M_TOT + l * RR + r];
        s0 += tanhf(p.x + bl) * w_law1[r];
        s1 += tanhf(p.y + ba) * w_accu1[r];
        s2 += tanhf(p.z + bt) * w_term1[r];
    }
    __shared__ float sm[3][256];
    sm[0][tid] = s0; sm[1][tid] = s1; sm[2][tid] = s2;
    __syncthreads();
    for (int s = 128; s > 0; s >>= 1) {
        if (tid < s) for (int c = 0; c < 3; c++) sm[c][tid] += sm[c][tid + s];
        __syncthreads();
    }
    if (tid == 0) {
        out[b * LL + l] = sm[0][0] + b_law1[0];
        g_hax[b * LL + l] = tanhf(sm[1][0] + b_accu1[0]);
        g_htx[b * LL + l] = tanhf(sm[2][0] + b_term1[0]);
    }
}

__global__ void k_final(const float* __restrict__ Wa2, const float* __restrict__ ba2,
                        const float* __restrict__ Wt2, const float* __restrict__ bt2,
                        float* __restrict__ out) {
    int b = blockIdx.x, tid = threadIdx.x;
    if (tid < 119) {
        float s = ba2[tid];
        for (int l = 0; l < LL; l++) s += Wa2[tid * LL + l] * g_hax[b * LL + l];
        out[BBATCH*LL + b * 119 + tid] = s;
    } else if (tid < 130) {
        int j = tid - 119;
        float s = bt2[j];
        for (int l = 0; l < LL; l++) s += Wt2[j * LL + l] * g_htx[b * LL + l];
        out[BBATCH*LL + BBATCH*119 + b * 11 + j] = s;
    }
}

/* ---------------- launch --------------------------------------------------- */
extern "C" void kernel_launch(void* const* d_in, const int* in_sizes, int n_in,
                              void* d_out, int out_size) {
    const float* outp   = (const float*)d_in[0];
    const int*   amask  = (const int*)  d_in[1];
    const float* laws   = (const float*)d_in[2];
    const float* Wq     = (const float*)d_in[3];
    const float* bq     = (const float*)d_in[4];
    const float* Wk     = (const float*)d_in[5];
    const float* bk     = (const float*)d_in[6];
    const float* Wv     = (const float*)d_in[7];
    const float* bv     = (const float*)d_in[8];
    const float* w_law_d  = (const float*)d_in[9];
    const float* b_law_d  = (const float*)d_in[10];
    const float* w_law1   = (const float*)d_in[11];
    const float* b_law1   = (const float*)d_in[12];
    const float* w_accu_d = (const float*)d_in[13];
    const float* b_accu_d = (const float*)d_in[14];
    const float* w_accu1  = (const float*)d_in[15];
    const float* b_accu1  = (const float*)d_in[16];
    const float* W_accu2  = (const float*)d_in[17];
    const float* b_accu2  = (const float*)d_in[18];
    const float* w_term_d = (const float*)d_in[19];
    const float* b_term_d = (const float*)d_in[20];
    const float* w_term1  = (const float*)d_in[21];
    const float* b_term1  = (const float*)d_in[22];
    const float* W_term2  = (const float*)d_in[23];
    const float* b_term2  = (const float*)d_in[24];
    float* out = (float*)d_out;

    cudaFuncSetAttribute(k_big_h, cudaFuncAttributeMaxDynamicSharedMemorySize, SMEM_BIG);

    k_cvt<<<2048, 256>>>(laws);
    k_vecs<<<480, 256>>>(Wv, Wk, Wq, w_law_d, w_accu_d, w_term_d, bq, bk);
    k_scal<<<1, 256>>>(bk, bq, bv, w_law_d, w_accu_d, w_term_d);
    k_wc_t<<<dim3(D/64, D/64), 256>>>(Wq, Wk);
    k_fk2_t<<<dim3(D/64, (BBATCH*SSEQ)/64), 256>>>(outp);
    k_colpack<<<BBATCH*SSEQ/8, 256>>>(outp, amask);
    k_big_h<<<dim3(M_TOT/128, BBATCH), 512, SMEM_BIG>>>(0);
    k_heads<<<dim3(LL, BBATCH), 256>>>(b_law_d, w_law1, b_law1,
                                       b_accu_d, w_accu1, b_accu1,
                                       b_term_d, w_term1, b_term1, out);
    k_final<<<BBATCH, 130>>>(W_accu2, b_accu2, W_term2, b_term2, out);
}

// round 10
// speedup vs baseline: 7.0497x; 1.0057x over previous
#include <cuda_runtime.h>
#include <cuda_fp16.h>
#include <math.h>
#include <stdint.h>

#define D   768
#define LL  103
#define RR  512
#define BBATCH 2
#define SSEQ 512
#define M_TOT (LL*RR)              /* 52736 */
#define INV_SQRT_D 0.03608439182435161f

/* ---------------- static device scratch (no allocation allowed) ------------- */
__device__ __align__(128) float  g_Wct[D*D];               /* (Wq @ Wk^T)*inv = Wc^T    */
__device__ __align__(128) __half g_fk2h[BBATCH*SSEQ*D];    /* half(output @ Wc + bkq')  */
__device__ __align__(128) __half g_lawsh[M_TOT*D];         /* half(laws)                */
__device__ __align__(16)  float4 g_colpack[BBATCH*SSEQ];   /* {sbias', vlaw, vaccu, vterm} */
__device__ float  g_u[5][D];
__device__ float  g_c[4];
__device__ __align__(16) float4 g_pre[BBATCH*M_TOT];       /* {law,accu,term,0} pre-act */
__device__ float  g_hax[BBATCH*LL];
__device__ float  g_htx[BBATCH*LL];

/* ---------------- PTX helpers ---------------------------------------------- */
__device__ __forceinline__ uint32_t smem_u32(const void* p) {
    uint32_t a;
    asm("{ .reg .u64 t; cvta.to.shared.u64 t, %1; cvt.u32.u64 %0, t; }" : "=r"(a) : "l"(p));
    return a;
}
__device__ __forceinline__ void cpa16(uint32_t saddr, const void* g) {
    asm volatile("cp.async.cg.shared.global [%0], [%1], 16;" :: "r"(saddr), "l"(g) : "memory");
}
__device__ __forceinline__ void mma_f16_16x8x16(float* d, const uint32_t* a, const uint32_t* b) {
    asm volatile(
        "mma.sync.aligned.m16n8k16.row.col.f32.f16.f16.f32 "
        "{%0,%1,%2,%3}, {%4,%5,%6,%7}, {%8,%9}, {%0,%1,%2,%3};"
        : "+f"(d[0]), "+f"(d[1]), "+f"(d[2]), "+f"(d[3])
        : "r"(a[0]), "r"(a[1]), "r"(a[2]), "r"(a[3]), "r"(b[0]), "r"(b[1]));
}
__device__ __forceinline__ void mma_tf32_16x8x8(float* d, const uint32_t* a, const uint32_t* b) {
    asm volatile(
        "mma.sync.aligned.m16n8k8.row.col.f32.tf32.tf32.f32 "
        "{%0,%1,%2,%3}, {%4,%5,%6,%7}, {%8,%9}, {%0,%1,%2,%3};"
        : "+f"(d[0]), "+f"(d[1]), "+f"(d[2]), "+f"(d[3])
        : "r"(a[0]), "r"(a[1]), "r"(a[2]), "r"(a[3]), "r"(b[0]), "r"(b[1]));
}
/* split fp32 into tf32-exact hi + residual lo (3xTF32 compensation) */
__device__ __forceinline__ void tf32_split(uint32_t u, uint32_t& hi, uint32_t& lo) {
    hi = u & 0xFFFFE000u;
    lo = __float_as_uint(__uint_as_float(u) - __uint_as_float(hi));
}

/* ---------------- laws fp32 -> fp16 ---------------------------------------- */
__global__ void k_cvt(const float* __restrict__ laws) {
    const float4* src = (const float4*)laws;
    uint2* dst = (uint2*)g_lawsh;
    int n4 = M_TOT * D / 4;
    for (int i = blockIdx.x * blockDim.x + threadIdx.x; i < n4;
         i += gridDim.x * blockDim.x) {
        float4 v = src[i];
        __half2 h0 = __floats2half2_rn(v.x, v.y);
        __half2 h1 = __floats2half2_rn(v.z, v.w);
        dst[i] = make_uint2(*(uint32_t*)&h0, *(uint32_t*)&h1);
    }
}

/* ---------------- tiny precompute kernels (warp-per-dot) -------------------- */
__global__ void k_vecs(const float* __restrict__ Wv, const float* __restrict__ Wk,
                       const float* __restrict__ Wq,
                       const float* __restrict__ wl, const float* __restrict__ wa,
                       const float* __restrict__ wt,
                       const float* __restrict__ bq, const float* __restrict__ bk) {
    int gid = blockIdx.x * 8 + (threadIdx.x >> 5);
    int lane = threadIdx.x & 31;
    int w = gid / D, e = gid % D;
    const float *row, *vec; float scale = 1.0f;
    if      (w == 0) { row = Wv + e*D; vec = wl; }
    else if (w == 1) { row = Wv + e*D; vec = wa; }
    else if (w == 2) { row = Wv + e*D; vec = wt; }
    else if (w == 3) { row = Wk + e*D; vec = bq; scale = INV_SQRT_D; }
    else             { row = Wq + e*D; vec = bk; scale = INV_SQRT_D; }
    float p = 0.f;
    for (int d = lane; d < D; d += 32) p += row[d] * vec[d];
    #pragma unroll
    for (int s = 16; s > 0; s >>= 1) p += __shfl_xor_sync(0xFFFFFFFFu, p, s);
    if (lane == 0) g_u[w][e] = p * scale;
}

__global__ void k_scal(const float* __restrict__ bk, const float* __restrict__ bq,
                       const float* __restrict__ bv,
                       const float* __restrict__ wl, const float* __restrict__ wa,
                       const float* __restrict__ wt) {
    int tid = threadIdx.x;
    float p0 = 0, p1 = 0, p2 = 0, p3 = 0;
    for (int d = tid; d < D; d += 256) {
        float b = bv[d];
        p0 += bk[d] * bq[d]; p1 += b * wl[d]; p2 += b * wa[d]; p3 += b * wt[d];
    }
    __shared__ float sm[4][256];
    sm[0][tid] = p0; sm[1][tid] = p1; sm[2][tid] = p2; sm[3][tid] = p3;
    __syncthreads();
    for (int s = 128; s > 0; s >>= 1) {
        if (tid < s) for (int c = 0; c < 4; c++) sm[c][tid] += sm[c][tid + s];
        __syncthreads();
    }
    if (tid == 0) {
        g_c[0] = sm[0][0] * INV_SQRT_D;
        g_c[1] = sm[1][0]; g_c[2] = sm[2][0]; g_c[3] = sm[3][0];
    }
}

/* ---- 3xTF32 mma GEMM (NT), 4-stage: g_Wct = inv * Wq @ Wk^T  (768^3) ------- */
__global__ __launch_bounds__(256) void k_wc_t(const float* __restrict__ A,
                                              const float* __restrict__ B) {
    __shared__ float As[4][1280], Bs[4][1280];   /* 64 rows x 20 floats x 4 stages */
    int tid = threadIdx.x, lane = tid & 31, wid = tid >> 5;
    int wm = wid >> 2, wn = wid & 3, g = lane >> 2, c = lane & 3;
    int i0 = blockIdx.y * 64, j0 = blockIdx.x * 64;
    uint32_t sa = smem_u32(As), sbm = smem_u32(Bs);
    int row = tid >> 2, seg = tid & 3;
    float acc[2][2][4] = {};

#define LDWC(st, kc) do {                                                      \
        cpa16(sa  + (st)*5120 + row*80 + seg*16,                               \
              A + (size_t)(i0 + row)*D + (kc)*16 + seg*4);                     \
        cpa16(sbm + (st)*5120 + row*80 + seg*16,                               \
              B + (size_t)(j0 + row)*D + (kc)*16 + seg*4);                     \
        asm volatile("cp.async.commit_group;" ::: "memory");                   \
    } while (0)

    LDWC(0, 0); LDWC(1, 1); LDWC(2, 2);
    for (int kc = 0; kc < 48; kc++) {
        asm volatile("cp.async.wait_group 2;" ::: "memory");
        __syncthreads();
        if (kc + 3 < 48) LDWC((kc + 3) & 3, kc + 3);
        else asm volatile("cp.async.commit_group;" ::: "memory");
        const float* Aw = As[kc & 3];
        const float* Bw = Bs[kc & 3];
        #pragma unroll
        for (int s2 = 0; s2 < 2; s2++) {
            int kw = s2 * 8;
            uint32_t ah[2][4], al[2][4], bh[2][2], bl[2][2];
            #pragma unroll
            for (int mt = 0; mt < 2; mt++) {
                int m = wm * 32 + mt * 16 + g;
                tf32_split(__float_as_uint(Aw[m * 20 + kw + c]),        ah[mt][0], al[mt][0]);
                tf32_split(__float_as_uint(Aw[(m + 8) * 20 + kw + c]),  ah[mt][1], al[mt][1]);
                tf32_split(__float_as_uint(Aw[m * 20 + kw + c + 4]),    ah[mt][2], al[mt][2]);
                tf32_split(__float_as_uint(Aw[(m + 8) * 20 + kw + c+4]),ah[mt][3], al[mt][3]);
            }
            #pragma unroll
            for (int nt = 0; nt < 2; nt++) {
                int n = wn * 16 + nt * 8 + g;
                tf32_split(__float_as_uint(Bw[n * 20 + kw + c]),     bh[nt][0], bl[nt][0]);
                tf32_split(__float_as_uint(Bw[n * 20 + kw + c + 4]), bh[nt][1], bl[nt][1]);
            }
            #pragma unroll
            for (int mt = 0; mt < 2; mt++)
                #pragma unroll
                for (int nt = 0; nt < 2; nt++) {
                    mma_tf32_16x8x8(acc[mt][nt], ah[mt], bl[nt]);
                    mma_tf32_16x8x8(acc[mt][nt], al[mt], bh[nt]);
                    mma_tf32_16x8x8(acc[mt][nt], ah[mt], bh[nt]);
                }
        }
        __syncthreads();
    }
#undef LDWC
    #pragma unroll
    for (int mt = 0; mt < 2; mt++)
        #pragma unroll
        for (int nt = 0; nt < 2; nt++) {
            int r0 = i0 + wm * 32 + mt * 16 + g;
            int col = j0 + wn * 16 + nt * 8 + 2 * c;
            g_Wct[(size_t)r0 * D + col]       = acc[mt][nt][0] * INV_SQRT_D;
            g_Wct[(size_t)r0 * D + col + 1]   = acc[mt][nt][1] * INV_SQRT_D;
            g_Wct[(size_t)(r0+8) * D + col]   = acc[mt][nt][2] * INV_SQRT_D;
            g_Wct[(size_t)(r0+8) * D + col+1] = acc[mt][nt][3] * INV_SQRT_D;
        }
}

/* ---- 3xTF32 mma GEMM (NT), 4-stage: g_fk2h = half(output @ Wct^T + bkq') --- */
__global__ __launch_bounds__(256) void k_fk2_t(const float* __restrict__ A) {
    __shared__ float As[4][1280], Bs[4][1280];
    int tid = threadIdx.x, lane = tid & 31, wid = tid >> 5;
    int wm = wid >> 2, wn = wid & 3, g = lane >> 2, c = lane & 3;
    int i0 = blockIdx.y * 64, j0 = blockIdx.x * 64;
    uint32_t sa = smem_u32(As), sbm = smem_u32(Bs);
    int row = tid >> 2, seg = tid & 3;
    float acc[2][2][4] = {};

#define LDFK(st, kc) do {                                                      \
        cpa16(sa  + (st)*5120 + row*80 + seg*16,                               \
              A + (size_t)(i0 + row)*D + (kc)*16 + seg*4);                     \
        cpa16(sbm + (st)*5120 + row*80 + seg*16,                               \
              g_Wct + (size_t)(j0 + row)*D + (kc)*16 + seg*4);                 \
        asm volatile("cp.async.commit_group;" ::: "memory");                   \
    } while (0)

    LDFK(0, 0); LDFK(1, 1); LDFK(2, 2);
    for (int kc = 0; kc < 48; kc++) {
        asm volatile("cp.async.wait_group 2;" ::: "memory");
        __syncthreads();
        if (kc + 3 < 48) LDFK((kc + 3) & 3, kc + 3);
        else asm volatile("cp.async.commit_group;" ::: "memory");
        const float* Aw = As[kc & 3];
        const float* Bw = Bs[kc & 3];
        #pragma unroll
        for (int s2 = 0; s2 < 2; s2++) {
            int kw = s2 * 8;
            uint32_t ah[2][4], al[2][4], bh[2][2], bl[2][2];
            #pragma unroll
            for (int mt = 0; mt < 2; mt++) {
                int m = wm * 32 + mt * 16 + g;
                tf32_split(__float_as_uint(Aw[m * 20 + kw + c]),        ah[mt][0], al[mt][0]);
                tf32_split(__float_as_uint(Aw[(m + 8) * 20 + kw + c]),  ah[mt][1], al[mt][1]);
                tf32_split(__float_as_uint(Aw[m * 20 + kw + c + 4]),    ah[mt][2], al[mt][2]);
                tf32_split(__float_as_uint(Aw[(m + 8) * 20 + kw + c+4]),ah[mt][3], al[mt][3]);
            }
            #pragma unroll
            for (int nt = 0; nt < 2; nt++) {
                int n = wn * 16 + nt * 8 + g;
                tf32_split(__float_as_uint(Bw[n * 20 + kw + c]),     bh[nt][0], bl[nt][0]);
                tf32_split(__float_as_uint(Bw[n * 20 + kw + c + 4]), bh[nt][1], bl[nt][1]);
            }
            #pragma unroll
            for (int mt = 0; mt < 2; mt++)
                #pragma unroll
                for (int nt = 0; nt < 2; nt++) {
                    mma_tf32_16x8x8(acc[mt][nt], ah[mt], bl[nt]);
                    mma_tf32_16x8x8(acc[mt][nt], al[mt], bh[nt]);
                    mma_tf32_16x8x8(acc[mt][nt], ah[mt], bh[nt]);
                }
        }
        __syncthreads();
    }
#undef LDFK
    #pragma unroll
    for (int mt = 0; mt < 2; mt++)
        #pragma unroll
        for (int nt = 0; nt < 2; nt++) {
            int r0 = i0 + wm * 32 + mt * 16 + g;
            int col = j0 + wn * 16 + nt * 8 + 2 * c;
            float b0 = g_u[4][col], b1 = g_u[4][col + 1];
            g_fk2h[(size_t)r0 * D + col]       = __float2half_rn(acc[mt][nt][0] + b0);
            g_fk2h[(size_t)r0 * D + col + 1]   = __float2half_rn(acc[mt][nt][1] + b1);
            g_fk2h[(size_t)(r0+8) * D + col]   = __float2half_rn(acc[mt][nt][2] + b0);
            g_fk2h[(size_t)(r0+8) * D + col+1] = __float2half_rn(acc[mt][nt][3] + b1);
        }
}

/* per (b,s): sbias' (+mask), and the three v projections  (warp per row) */
__global__ void k_colpack(const float* __restrict__ outp, const int* __restrict__ mask) {
    int row = blockIdx.x * 8 + (threadIdx.x >> 5);
    int lane = threadIdx.x & 31;
    const float* x = outp + (size_t)row * D;
    float p0 = 0, p1 = 0, p2 = 0, p3 = 0;
    for (int d = lane; d < D; d += 32) {
        float xv = x[d];
        p0 += xv * g_u[3][d]; p1 += xv * g_u[0][d];
        p2 += xv * g_u[1][d]; p3 += xv * g_u[2][d];
    }
    #pragma unroll
    for (int s = 16; s > 0; s >>= 1) {
        p0 += __shfl_xor_sync(0xFFFFFFFFu, p0, s);
        p1 += __shfl_xor_sync(0xFFFFFFFFu, p1, s);
        p2 += __shfl_xor_sync(0xFFFFFFFFu, p2, s);
        p3 += __shfl_xor_sync(0xFFFFFFFFu, p3, s);
    }
    if (lane == 0) {
        float sb = p0 + g_c[0] + (1.0f - (float)mask[row]) * (-10000.0f);
        g_colpack[row] = make_float4(sb, p1 + g_c[1], p2 + g_c[2], p3 + g_c[3]);
    }
}

/* ------------- big fused kernel: fp16 mma.sync GEMM + softmax epilogue ------ */
#define KT        32               /* halves per K chunk */
#define NKC       (D/KT)           /* 24 */
#define RSW       20               /* smem row stride in 32-bit words (80 B)   */
#define STG_B     30720
#define SMEM_BIG  139264

__global__ __launch_bounds__(512) void k_big_h(int dummy) {
    extern __shared__ float smf[];
    uint32_t sb = smem_u32(smf);
    const uint32_t* smw = (const uint32_t*)smf;
    int tid = threadIdx.x, lane = tid & 31, wid = tid >> 5;
    int wm = wid >> 2, wn = wid & 3;
    int g = lane >> 2, c = lane & 3;
    int b = blockIdx.y, m0 = blockIdx.x * 128;
    const __half* fk2b = g_fk2h + (size_t)b * SSEQ * D;

    float4* scp  = (float4*)(smf + 30720);
    float4* red4 = (float4*)(smf + 32768);

    { const float4* gcp = g_colpack + b * SSEQ;
      for (int i = tid; i < SSEQ; i += 512) scp[i] = gcp[i]; }

    float rs[2][2][4];
    #pragma unroll
    for (int mt = 0; mt < 2; mt++)
        #pragma unroll
        for (int h = 0; h < 2; h++)
            #pragma unroll
            for (int e = 0; e < 4; e++) rs[mt][h][e] = 0.f;

#define LOADH(st, kc, n0) do {                                                 \
        uint32_t Ab = sb + (st) * STG_B;                                       \
        uint32_t Bb = Ab + 10240;                                              \
        const __half* asrc = g_lawsh + (size_t)m0 * D + (kc) * KT;             \
        const __half* bsrc = fk2b + (size_t)(n0) * D + (kc) * KT;              \
        { int row = tid >> 2, seg = tid & 3;                                   \
          cpa16(Ab + row * 80 + seg * 16, asrc + (size_t)row * D + seg * 8); } \
        { int row = tid >> 2, seg = tid & 3;                                   \
          cpa16(Bb + row * 80 + seg * 16, bsrc + (size_t)row * D + seg * 8); } \
        { int i2 = tid + 512; int row = i2 >> 2, seg = i2 & 3;                 \
          cpa16(Bb + row * 80 + seg * 16, bsrc + (size_t)row * D + seg * 8); } \
        asm volatile("cp.async.commit_group;" ::: "memory");                   \
    } while (0)

    for (int chunk = 0; chunk < 2; chunk++) {
        int n0 = chunk * 256;
        float acc[2][8][4];
        #pragma unroll
        for (int mt = 0; mt < 2; mt++)
            #pragma unroll
            for (int nt = 0; nt < 8; nt++)
                #pragma unroll
                for (int e = 0; e < 4; e++) acc[mt][nt][e] = 0.f;

        LOADH(0, 0, n0); LOADH(1, 1, n0); LOADH(2, 2, n0);

        for (int kc = 0; kc < NKC; kc++) {
            asm volatile("cp.async.wait_group 2;" ::: "memory");
            __syncthreads();
            if (kc + 3 < NKC) LOADH((kc + 3) & 3, kc + 3, n0);
            else asm volatile("cp.async.commit_group;" ::: "memory");

            const uint32_t* Aw = smw + (kc & 3) * (STG_B / 4);
            const uint32_t* Bw = Aw + 2560;
            #pragma unroll
            for (int s2 = 0; s2 < 2; s2++) {
                int kw = s2 * 8;
                uint32_t af[2][4], bf[8][2];
                #pragma unroll
                for (int mt = 0; mt < 2; mt++) {
                    int m = wm * 32 + mt * 16 + g;
                    af[mt][0] = Aw[m * RSW + kw + c];
                    af[mt][1] = Aw[(m + 8) * RSW + kw + c];
                    af[mt][2] = Aw[m * RSW + kw + c + 4];
                    af[mt][3] = Aw[(m + 8) * RSW + kw + c + 4];
                }
                #pragma unroll
                for (int nt = 0; nt < 8; nt++) {
                    int n = wn * 64 + nt * 8 + g;
                    bf[nt][0] = Bw[n * RSW + kw + c];
                    bf[nt][1] = Bw[n * RSW + kw + c + 4];
                }
                #pragma unroll
                for (int mt = 0; mt < 2; mt++)
                    #pragma unroll
                    for (int nt = 0; nt < 8; nt++)
                        mma_f16_16x8x16(acc[mt][nt], af[mt], bf[nt]);
            }
        }

        #pragma unroll
        for (int mt = 0; mt < 2; mt++) {
            #pragma unroll
            for (int nt = 0; nt < 8; nt++) {
                int s = chunk * 256 + wn * 64 + nt * 8 + 2 * c;
                float4 cp0 = scp[s], cp1 = scp[s + 1];
                float e0 = __expf(acc[mt][nt][0] + cp0.x);
                rs[mt][0][0] += e0; rs[mt][0][1] += e0 * cp0.y;
                rs[mt][0][2] += e0 * cp0.z; rs[mt][0][3] += e0 * cp0.w;
                float e1 = __expf(acc[mt][nt][1] + cp1.x);
                rs[mt][0][0] += e1; rs[mt][0][1] += e1 * cp1.y;
                rs[mt][0][2] += e1 * cp1.z; rs[mt][0][3] += e1 * cp1.w;
                float e2 = __expf(acc[mt][nt][2] + cp0.x);
                rs[mt][1][0] += e2; rs[mt][1][1] += e2 * cp0.y;
                rs[mt][1][2] += e2 * cp0.z; rs[mt][1][3] += e2 * cp0.w;
                float e3 = __expf(acc[mt][nt][3] + cp1.x);
                rs[mt][1][0] += e3; rs[mt][1][1] += e3 * cp1.y;
                rs[mt][1][2] += e3 * cp1.z; rs[mt][1][3] += e3 * cp1.w;
            }
        }
    }
#undef LOADH

    #pragma unroll
    for (int mt = 0; mt < 2; mt++)
        #pragma unroll
        for (int h = 0; h < 2; h++)
            #pragma unroll
            for (int e = 0; e < 4; e++) {
                float v = rs[mt][h][e];
                v += __shfl_xor_sync(0xFFFFFFFFu, v, 1);
                v += __shfl_xor_sync(0xFFFFFFFFu, v, 2);
                rs[mt][h][e] = v;
            }
    __syncthreads();
    if (c == 0) {
        #pragma unroll
        for (int mt = 0; mt < 2; mt++)
            #pragma unroll
            for (int h = 0; h < 2; h++) {
                int row = wm * 32 + mt * 16 + h * 8 + g;
                red4[wn * 128 + row] = make_float4(rs[mt][h][0], rs[mt][h][1],
                                                   rs[mt][h][2], rs[mt][h][3]);
            }
    }
    __syncthreads();
    if (tid < 128) {
        float4 a0 = red4[tid], a1 = red4[128 + tid],
               a2 = red4[256 + tid], a3 = red4[384 + tid];
        float den = a0.x + a1.x + a2.x + a3.x;
        float inv = 1.0f / den;
        g_pre[(size_t)b * M_TOT + m0 + tid] =
            make_float4((a0.y + a1.y + a2.y + a3.y) * inv,
                        (a0.z + a1.z + a2.z + a3.z) * inv,
                        (a0.w + a1.w + a2.w + a3.w) * inv, 0.f);
    }
}

/* ------------- heads ------------------------------------------------------- */
__global__ void k_heads(const float* __restrict__ b_law_d, const float* __restrict__ w_law1,
                        const float* __restrict__ b_law1,
                        const float* __restrict__ b_accu_d, const float* __restrict__ w_accu1,
                        const float* __restrict__ b_accu1,
                        const float* __restrict__ b_term_d, const float* __restrict__ w_term1,
                        const float* __restrict__ b_term1,
                        float* __restrict__ out) {
    int l = blockIdx.x, b = blockIdx.y, tid = threadIdx.x;
    float bl = b_law_d[0], ba = b_accu_d[0], bt = b_term_d[0];
    float s0 = 0, s1 = 0, s2 = 0;
    for (int r = tid; r < RR; r += 256) {
        float4 p = g_pre[(size_t)b * M_TOT + l * RR + r];
        s0 += tanhf(p.x + bl) * w_law1[r];
        s1 += tanhf(p.y + ba) * w_accu1[r];
        s2 += tanhf(p.z + bt) * w_term1[r];
    }
    __shared__ float sm[3][256];
    sm[0][tid] = s0; sm[1][tid] = s1; sm[2][tid] = s2;
    __syncthreads();
    for (int s = 128; s > 0; s >>= 1) {
        if (tid < s) for (int c = 0; c < 3; c++) sm[c][tid] += sm[c][tid + s];
        __syncthreads();
    }
    if (tid == 0) {
        out[b * LL + l] = sm[0][0] + b_law1[0];
        g_hax[b * LL + l] = tanhf(sm[1][0] + b_accu1[0]);
        g_htx[b * LL + l] = tanhf(sm[2][0] + b_term1[0]);
    }
}

__global__ void k_final(const float* __restrict__ Wa2, const float* __restrict__ ba2,
                        const float* __restrict__ Wt2, const float* __restrict__ bt2,
                        float* __restrict__ out) {
    int b = blockIdx.x, tid = threadIdx.x;
    if (tid < 119) {
        float s = ba2[tid];
        for (int l = 0; l < LL; l++) s += Wa2[tid * LL + l] * g_hax[b * LL + l];
        out[BBATCH*LL + b * 119 + tid] = s;
    } else if (tid < 130) {
        int j = tid - 119;
        float s = bt2[j];
        for (int l = 0; l < LL; l++) s += Wt2[j * LL + l] * g_htx[b * LL + l];
        out[BBATCH*LL + BBATCH*119 + b * 11 + j] = s;
    }
}

/* ---------------- launch --------------------------------------------------- */
extern "C" void kernel_launch(void* const* d_in, const int* in_sizes, int n_in,
                              void* d_out, int out_size) {
    const float* outp   = (const float*)d_in[0];
    const int*   amask  = (const int*)  d_in[1];
    const float* laws   = (const float*)d_in[2];
    const float* Wq     = (const float*)d_in[3];
    const float* bq     = (const float*)d_in[4];
    const float* Wk     = (const float*)d_in[5];
    const float* bk     = (const float*)d_in[6];
    const float* Wv     = (const float*)d_in[7];
    const float* bv     = (const float*)d_in[8];
    const float* w_law_d  = (const float*)d_in[9];
    const float* b_law_d  = (const float*)d_in[10];
    const float* w_law1   = (const float*)d_in[11];
    const float* b_law1   = (const float*)d_in[12];
    const float* w_accu_d = (const float*)d_in[13];
    const float* b_accu_d = (const float*)d_in[14];
    const float* w_accu1  = (const float*)d_in[15];
    const float* b_accu1  = (const float*)d_in[16];
    const float* W_accu2  = (const float*)d_in[17];
    const float* b_accu2  = (const float*)d_in[18];
    const float* w_term_d = (const float*)d_in[19];
    const float* b_term_d = (const float*)d_in[20];
    const float* w_term1  = (const float*)d_in[21];
    const float* b_term1  = (const float*)d_in[22];
    const float* W_term2  = (const float*)d_in[23];
    const float* b_term2  = (const float*)d_in[24];
    float* out = (float*)d_out;

    cudaFuncSetAttribute(k_big_h, cudaFuncAttributeMaxDynamicSharedMemorySize, SMEM_BIG);

    /* fork: laws fp32->fp16 conversion runs concurrently on the per-thread
       stream (built-in handle, no stream creation), joined via events.
       Events are created fresh each call and intentionally not destroyed
       while the capture may still reference them. */
    cudaEvent_t evFork, evJoin;
    cudaEventCreateWithFlags(&evFork, cudaEventDisableTiming);
    cudaEventCreateWithFlags(&evJoin, cudaEventDisableTiming);

    cudaEventRecord(evFork, 0);
    cudaStreamWaitEvent(cudaStreamPerThread, evFork, 0);
    k_cvt<<<2048, 256, 0, cudaStreamPerThread>>>(laws);
    cudaEventRecord(evJoin, cudaStreamPerThread);

    k_vecs<<<480, 256>>>(Wv, Wk, Wq, w_law_d, w_accu_d, w_term_d, bq, bk);
    k_scal<<<1, 256>>>(bk, bq, bv, w_law_d, w_accu_d, w_term_d);
    k_wc_t<<<dim3(D/64, D/64), 256>>>(Wq, Wk);
    k_fk2_t<<<dim3(D/64, (BBATCH*SSEQ)/64), 256>>>(outp);
    k_colpack<<<BBATCH*SSEQ/8, 256>>>(outp, amask);

    cudaStreamWaitEvent(0, evJoin, 0);
    k_big_h<<<dim3(M_TOT/128, BBATCH), 512, SMEM_BIG>>>(0);
    k_heads<<<dim3(LL, BBATCH), 256>>>(b_law_d, w_law1, b_law1,
                                       b_accu_d, w_accu1, b_accu1,
                                       b_term_d, w_term1, b_term1, out);
    k_final<<<BBATCH, 130>>>(W_accu2, b_accu2, W_term2, b_term2, out);
}

// round 11
// speedup vs baseline: 7.3091x; 1.0368x over previous
#include <cuda_runtime.h>
#include <cuda_fp16.h>
#include <math.h>
#include <stdint.h>

#define D   768
#define LL  103
#define RR  512
#define BBATCH 2
#define SSEQ 512
#define M_TOT (LL*RR)              /* 52736 */
#define INV_SQRT_D 0.03608439182435161f

/* ---------------- static device scratch (no allocation allowed) ------------- */
__device__ __align__(128) float  g_Wct[D*D];               /* (Wq @ Wk^T)*inv = Wc^T    */
__device__ __align__(128) __half g_fk2h[BBATCH*SSEQ*D];    /* half(output @ Wc + bkq')  */
__device__ __align__(128) __half g_lawsh[M_TOT*D];         /* half(laws)                */
__device__ __align__(16)  float4 g_colpack[BBATCH*SSEQ];   /* {sbias', vlaw, vaccu, vterm} */
__device__ float  g_u[5][D];
__device__ float  g_c[4];
__device__ __align__(16) float4 g_pre[BBATCH*M_TOT];       /* {law,accu,term,0} pre-act */
__device__ float  g_hax[BBATCH*LL];
__device__ float  g_htx[BBATCH*LL];

/* ---------------- PTX helpers ---------------------------------------------- */
__device__ __forceinline__ uint32_t smem_u32(const void* p) {
    uint32_t a;
    asm("{ .reg .u64 t; cvta.to.shared.u64 t, %1; cvt.u32.u64 %0, t; }" : "=r"(a) : "l"(p));
    return a;
}
__device__ __forceinline__ void cpa16(uint32_t saddr, const void* g) {
    asm volatile("cp.async.cg.shared.global [%0], [%1], 16;" :: "r"(saddr), "l"(g) : "memory");
}
__device__ __forceinline__ void mma_f16_16x8x16(float* d, const uint32_t* a, const uint32_t* b) {
    asm volatile(
        "mma.sync.aligned.m16n8k16.row.col.f32.f16.f16.f32 "
        "{%0,%1,%2,%3}, {%4,%5,%6,%7}, {%8,%9}, {%0,%1,%2,%3};"
        : "+f"(d[0]), "+f"(d[1]), "+f"(d[2]), "+f"(d[3])
        : "r"(a[0]), "r"(a[1]), "r"(a[2]), "r"(a[3]), "r"(b[0]), "r"(b[1]));
}
__device__ __forceinline__ void mma_tf32_16x8x8(float* d, const uint32_t* a, const uint32_t* b) {
    asm volatile(
        "mma.sync.aligned.m16n8k8.row.col.f32.tf32.tf32.f32 "
        "{%0,%1,%2,%3}, {%4,%5,%6,%7}, {%8,%9}, {%0,%1,%2,%3};"
        : "+f"(d[0]), "+f"(d[1]), "+f"(d[2]), "+f"(d[3])
        : "r"(a[0]), "r"(a[1]), "r"(a[2]), "r"(a[3]), "r"(b[0]), "r"(b[1]));
}
__device__ __forceinline__ void ldsm_x4(uint32_t* r, uint32_t addr) {
    asm volatile("ldmatrix.sync.aligned.m8n8.x4.shared.b16 {%0,%1,%2,%3}, [%4];"
                 : "=r"(r[0]), "=r"(r[1]), "=r"(r[2]), "=r"(r[3]) : "r"(addr));
}
__device__ __forceinline__ void ldsm_x2(uint32_t* r, uint32_t addr) {
    asm volatile("ldmatrix.sync.aligned.m8n8.x2.shared.b16 {%0,%1}, [%2];"
                 : "=r"(r[0]), "=r"(r[1]) : "r"(addr));
}
/* split fp32 into tf32-exact hi + residual lo (3xTF32 compensation) */
__device__ __forceinline__ void tf32_split(uint32_t u, uint32_t& hi, uint32_t& lo) {
    hi = u & 0xFFFFE000u;
    lo = __float_as_uint(__uint_as_float(u) - __uint_as_float(hi));
}

/* ---------------- laws fp32 -> fp16 ---------------------------------------- */
__global__ void k_cvt(const float* __restrict__ laws) {
    const float4* src = (const float4*)laws;
    uint2* dst = (uint2*)g_lawsh;
    int n4 = M_TOT * D / 4;
    for (int i = blockIdx.x * blockDim.x + threadIdx.x; i < n4;
         i += gridDim.x * blockDim.x) {
        float4 v = src[i];
        __half2 h0 = __floats2half2_rn(v.x, v.y);
        __half2 h1 = __floats2half2_rn(v.z, v.w);
        dst[i] = make_uint2(*(uint32_t*)&h0, *(uint32_t*)&h1);
    }
}

/* ---------------- tiny precompute kernels (warp-per-dot) -------------------- */
__global__ void k_vecs(const float* __restrict__ Wv, const float* __restrict__ Wk,
                       const float* __restrict__ Wq,
                       const float* __restrict__ wl, const float* __restrict__ wa,
                       const float* __restrict__ wt,
                       const float* __restrict__ bq, const float* __restrict__ bk) {
    int gid = blockIdx.x * 8 + (threadIdx.x >> 5);
    int lane = threadIdx.x & 31;
    int w = gid / D, e = gid % D;
    const float *row, *vec; float scale = 1.0f;
    if      (w == 0) { row = Wv + e*D; vec = wl; }
    else if (w == 1) { row = Wv + e*D; vec = wa; }
    else if (w == 2) { row = Wv + e*D; vec = wt; }
    else if (w == 3) { row = Wk + e*D; vec = bq; scale = INV_SQRT_D; }
    else             { row = Wq + e*D; vec = bk; scale = INV_SQRT_D; }
    float p = 0.f;
    for (int d = lane; d < D; d += 32) p += row[d] * vec[d];
    #pragma unroll
    for (int s = 16; s > 0; s >>= 1) p += __shfl_xor_sync(0xFFFFFFFFu, p, s);
    if (lane == 0) g_u[w][e] = p * scale;
}

__global__ void k_scal(const float* __restrict__ bk, const float* __restrict__ bq,
                       const float* __restrict__ bv,
                       const float* __restrict__ wl, const float* __restrict__ wa,
                       const float* __restrict__ wt) {
    int tid = threadIdx.x;
    float p0 = 0, p1 = 0, p2 = 0, p3 = 0;
    for (int d = tid; d < D; d += 256) {
        float b = bv[d];
        p0 += bk[d] * bq[d]; p1 += b * wl[d]; p2 += b * wa[d]; p3 += b * wt[d];
    }
    __shared__ float sm[4][256];
    sm[0][tid] = p0; sm[1][tid] = p1; sm[2][tid] = p2; sm[3][tid] = p3;
    __syncthreads();
    for (int s = 128; s > 0; s >>= 1) {
        if (tid < s) for (int c = 0; c < 4; c++) sm[c][tid] += sm[c][tid + s];
        __syncthreads();
    }
    if (tid == 0) {
        g_c[0] = sm[0][0] * INV_SQRT_D;
        g_c[1] = sm[1][0]; g_c[2] = sm[2][0]; g_c[3] = sm[3][0];
    }
}

/* ---- 3xTF32 mma GEMM (NT), 4-stage: g_Wct = inv * Wq @ Wk^T  (768^3) ------- */
__global__ __launch_bounds__(256) void k_wc_t(const float* __restrict__ A,
                                              const float* __restrict__ B) {
    __shared__ float As[4][1280], Bs[4][1280];   /* 64 rows x 20 floats x 4 stages */
    int tid = threadIdx.x, lane = tid & 31, wid = tid >> 5;
    int wm = wid >> 2, wn = wid & 3, g = lane >> 2, c = lane & 3;
    int i0 = blockIdx.y * 64, j0 = blockIdx.x * 64;
    uint32_t sa = smem_u32(As), sbm = smem_u32(Bs);
    int row = tid >> 2, seg = tid & 3;
    float acc[2][2][4] = {};

#define LDWC(st, kc) do {                                                      \
        cpa16(sa  + (st)*5120 + row*80 + seg*16,                               \
              A + (size_t)(i0 + row)*D + (kc)*16 + seg*4);                     \
        cpa16(sbm + (st)*5120 + row*80 + seg*16,                               \
              B + (size_t)(j0 + row)*D + (kc)*16 + seg*4);                     \
        asm volatile("cp.async.commit_group;" ::: "memory");                   \
    } while (0)

    LDWC(0, 0); LDWC(1, 1); LDWC(2, 2);
    for (int kc = 0; kc < 48; kc++) {
        asm volatile("cp.async.wait_group 2;" ::: "memory");
        __syncthreads();
        if (kc + 3 < 48) LDWC((kc + 3) & 3, kc + 3);
        else asm volatile("cp.async.commit_group;" ::: "memory");
        const float* Aw = As[kc & 3];
        const float* Bw = Bs[kc & 3];
        #pragma unroll
        for (int s2 = 0; s2 < 2; s2++) {
            int kw = s2 * 8;
            uint32_t ah[2][4], al[2][4], bh[2][2], bl[2][2];
            #pragma unroll
            for (int mt = 0; mt < 2; mt++) {
                int m = wm * 32 + mt * 16 + g;
                tf32_split(__float_as_uint(Aw[m * 20 + kw + c]),        ah[mt][0], al[mt][0]);
                tf32_split(__float_as_uint(Aw[(m + 8) * 20 + kw + c]),  ah[mt][1], al[mt][1]);
                tf32_split(__float_as_uint(Aw[m * 20 + kw + c + 4]),    ah[mt][2], al[mt][2]);
                tf32_split(__float_as_uint(Aw[(m + 8) * 20 + kw + c+4]),ah[mt][3], al[mt][3]);
            }
            #pragma unroll
            for (int nt = 0; nt < 2; nt++) {
                int n = wn * 16 + nt * 8 + g;
                tf32_split(__float_as_uint(Bw[n * 20 + kw + c]),     bh[nt][0], bl[nt][0]);
                tf32_split(__float_as_uint(Bw[n * 20 + kw + c + 4]), bh[nt][1], bl[nt][1]);
            }
            #pragma unroll
            for (int mt = 0; mt < 2; mt++)
                #pragma unroll
                for (int nt = 0; nt < 2; nt++) {
                    mma_tf32_16x8x8(acc[mt][nt], ah[mt], bl[nt]);
                    mma_tf32_16x8x8(acc[mt][nt], al[mt], bh[nt]);
                    mma_tf32_16x8x8(acc[mt][nt], ah[mt], bh[nt]);
                }
        }
        __syncthreads();
    }
#undef LDWC
    #pragma unroll
    for (int mt = 0; mt < 2; mt++)
        #pragma unroll
        for (int nt = 0; nt < 2; nt++) {
            int r0 = i0 + wm * 32 + mt * 16 + g;
            int col = j0 + wn * 16 + nt * 8 + 2 * c;
            g_Wct[(size_t)r0 * D + col]       = acc[mt][nt][0] * INV_SQRT_D;
            g_Wct[(size_t)r0 * D + col + 1]   = acc[mt][nt][1] * INV_SQRT_D;
            g_Wct[(size_t)(r0+8) * D + col]   = acc[mt][nt][2] * INV_SQRT_D;
            g_Wct[(size_t)(r0+8) * D + col+1] = acc[mt][nt][3] * INV_SQRT_D;
        }
}

/* ---- 3xTF32 mma GEMM (NT), 4-stage: g_fk2h = half(output @ Wct^T + bkq') --- */
__global__ __launch_bounds__(256) void k_fk2_t(const float* __restrict__ A) {
    __shared__ float As[4][1280], Bs[4][1280];
    int tid = threadIdx.x, lane = tid & 31, wid = tid >> 5;
    int wm = wid >> 2, wn = wid & 3, g = lane >> 2, c = lane & 3;
    int i0 = blockIdx.y * 64, j0 = blockIdx.x * 64;
    uint32_t sa = smem_u32(As), sbm = smem_u32(Bs);
    int row = tid >> 2, seg = tid & 3;
    float acc[2][2][4] = {};

#define LDFK(st, kc) do {                                                      \
        cpa16(sa  + (st)*5120 + row*80 + seg*16,                               \
              A + (size_t)(i0 + row)*D + (kc)*16 + seg*4);                     \
        cpa16(sbm + (st)*5120 + row*80 + seg*16,                               \
              g_Wct + (size_t)(j0 + row)*D + (kc)*16 + seg*4);                 \
        asm volatile("cp.async.commit_group;" ::: "memory");                   \
    } while (0)

    LDFK(0, 0); LDFK(1, 1); LDFK(2, 2);
    for (int kc = 0; kc < 48; kc++) {
        asm volatile("cp.async.wait_group 2;" ::: "memory");
        __syncthreads();
        if (kc + 3 < 48) LDFK((kc + 3) & 3, kc + 3);
        else asm volatile("cp.async.commit_group;" ::: "memory");
        const float* Aw = As[kc & 3];
        const float* Bw = Bs[kc & 3];
        #pragma unroll
        for (int s2 = 0; s2 < 2; s2++) {
            int kw = s2 * 8;
            uint32_t ah[2][4], al[2][4], bh[2][2], bl[2][2];
            #pragma unroll
            for (int mt = 0; mt < 2; mt++) {
                int m = wm * 32 + mt * 16 + g;
                tf32_split(__float_as_uint(Aw[m * 20 + kw + c]),        ah[mt][0], al[mt][0]);
                tf32_split(__float_as_uint(Aw[(m + 8) * 20 + kw + c]),  ah[mt][1], al[mt][1]);
                tf32_split(__float_as_uint(Aw[m * 20 + kw + c + 4]),    ah[mt][2], al[mt][2]);
                tf32_split(__float_as_uint(Aw[(m + 8) * 20 + kw + c+4]),ah[mt][3], al[mt][3]);
            }
            #pragma unroll
            for (int nt = 0; nt < 2; nt++) {
                int n = wn * 16 + nt * 8 + g;
                tf32_split(__float_as_uint(Bw[n * 20 + kw + c]),     bh[nt][0], bl[nt][0]);
                tf32_split(__float_as_uint(Bw[n * 20 + kw + c + 4]), bh[nt][1], bl[nt][1]);
            }
            #pragma unroll
            for (int mt = 0; mt < 2; mt++)
                #pragma unroll
                for (int nt = 0; nt < 2; nt++) {
                    mma_tf32_16x8x8(acc[mt][nt], ah[mt], bl[nt]);
                    mma_tf32_16x8x8(acc[mt][nt], al[mt], bh[nt]);
                    mma_tf32_16x8x8(acc[mt][nt], ah[mt], bh[nt]);
                }
        }
        __syncthreads();
    }
#undef LDFK
    #pragma unroll
    for (int mt = 0; mt < 2; mt++)
        #pragma unroll
        for (int nt = 0; nt < 2; nt++) {
            int r0 = i0 + wm * 32 + mt * 16 + g;
            int col = j0 + wn * 16 + nt * 8 + 2 * c;
            float b0 = g_u[4][col], b1 = g_u[4][col + 1];
            g_fk2h[(size_t)r0 * D + col]       = __float2half_rn(acc[mt][nt][0] + b0);
            g_fk2h[(size_t)r0 * D + col + 1]   = __float2half_rn(acc[mt][nt][1] + b1);
            g_fk2h[(size_t)(r0+8) * D + col]   = __float2half_rn(acc[mt][nt][2] + b0);
            g_fk2h[(size_t)(r0+8) * D + col+1] = __float2half_rn(acc[mt][nt][3] + b1);
        }
}

/* per (b,s): sbias' (+mask), and the three v projections  (warp per row) */
__global__ void k_colpack(const float* __restrict__ outp, const int* __restrict__ mask) {
    int row = blockIdx.x * 8 + (threadIdx.x >> 5);
    int lane = threadIdx.x & 31;
    const float* x = outp + (size_t)row * D;
    float p0 = 0, p1 = 0, p2 = 0, p3 = 0;
    for (int d = lane; d < D; d += 32) {
        float xv = x[d];
        p0 += xv * g_u[3][d]; p1 += xv * g_u[0][d];
        p2 += xv * g_u[1][d]; p3 += xv * g_u[2][d];
    }
    #pragma unroll
    for (int s = 16; s > 0; s >>= 1) {
        p0 += __shfl_xor_sync(0xFFFFFFFFu, p0, s);
        p1 += __shfl_xor_sync(0xFFFFFFFFu, p1, s);
        p2 += __shfl_xor_sync(0xFFFFFFFFu, p2, s);
        p3 += __shfl_xor_sync(0xFFFFFFFFu, p3, s);
    }
    if (lane == 0) {
        float sb = p0 + g_c[0] + (1.0f - (float)mask[row]) * (-10000.0f);
        g_colpack[row] = make_float4(sb, p1 + g_c[1], p2 + g_c[2], p3 + g_c[3]);
    }
}

/* ------------- big fused kernel: fp16 mma.sync GEMM + softmax epilogue ------ */
/* fragment loads via ldmatrix (A: x4, B: x2) on conflict-free 80B-stride smem */
#define KT        32               /* halves per K chunk */
#define NKC       (D/KT)           /* 24 */
#define RSW       20               /* smem row stride in 32-bit words (80 B)   */
#define STG_B     30720
#define SMEM_BIG  139264

__global__ __launch_bounds__(512) void k_big_h(int dummy) {
    extern __shared__ float smf[];
    uint32_t sb = smem_u32(smf);
    int tid = threadIdx.x, lane = tid & 31, wid = tid >> 5;
    int wm = wid >> 2, wn = wid & 3;
    int g = lane >> 2, c = lane & 3;
    int b = blockIdx.y, m0 = blockIdx.x * 128;
    const __half* fk2b = g_fk2h + (size_t)b * SSEQ * D;

    float4* scp  = (float4*)(smf + 30720);
    float4* red4 = (float4*)(smf + 32768);

    { const float4* gcp = g_colpack + b * SSEQ;
      for (int i = tid; i < SSEQ; i += 512) scp[i] = gcp[i]; }

    /* ldmatrix per-lane address offsets (within a stage) */
    int quad = lane >> 3, l8 = lane & 7, lq = lane & 15;
    uint32_t aOff[2], bOff[8];
    #pragma unroll
    for (int mt = 0; mt < 2; mt++)
        aOff[mt] = (uint32_t)((wm * 32 + mt * 16 + ((quad & 1) << 3) + l8) * 80
                              + ((quad >> 1) << 4));
    #pragma unroll
    for (int nt = 0; nt < 8; nt++)
        bOff[nt] = (uint32_t)(10240 + (wn * 64 + nt * 8 + (lq & 7)) * 80
                              + ((lq >> 3) << 4));

    float rs[2][2][4];
    #pragma unroll
    for (int mt = 0; mt < 2; mt++)
        #pragma unroll
        for (int h = 0; h < 2; h++)
            #pragma unroll
            for (int e = 0; e < 4; e++) rs[mt][h][e] = 0.f;

#define LOADH(st, kc, n0) do {                                                 \
        uint32_t Ab = sb + (st) * STG_B;                                       \
        uint32_t Bb = Ab + 10240;                                              \
        const __half* asrc = g_lawsh + (size_t)m0 * D + (kc) * KT;             \
        const __half* bsrc = fk2b + (size_t)(n0) * D + (kc) * KT;              \
        { int row = tid >> 2, seg = tid & 3;                                   \
          cpa16(Ab + row * 80 + seg * 16, asrc + (size_t)row * D + seg * 8); } \
        { int row = tid >> 2, seg = tid & 3;                                   \
          cpa16(Bb + row * 80 + seg * 16, bsrc + (size_t)row * D + seg * 8); } \
        { int i2 = tid + 512; int row = i2 >> 2, seg = i2 & 3;                 \
          cpa16(Bb + row * 80 + seg * 16, bsrc + (size_t)row * D + seg * 8); } \
        asm volatile("cp.async.commit_group;" ::: "memory");                   \
    } while (0)

    for (int chunk = 0; chunk < 2; chunk++) {
        int n0 = chunk * 256;
        float acc[2][8][4];
        #pragma unroll
        for (int mt = 0; mt < 2; mt++)
            #pragma unroll
            for (int nt = 0; nt < 8; nt++)
                #pragma unroll
                for (int e = 0; e < 4; e++) acc[mt][nt][e] = 0.f;

        LOADH(0, 0, n0); LOADH(1, 1, n0); LOADH(2, 2, n0);

        for (int kc = 0; kc < NKC; kc++) {
            asm volatile("cp.async.wait_group 2;" ::: "memory");
            __syncthreads();
            if (kc + 3 < NKC) LOADH((kc + 3) & 3, kc + 3, n0);
            else asm volatile("cp.async.commit_group;" ::: "memory");

            uint32_t stBase = sb + (kc & 3) * STG_B;
            #pragma unroll
            for (int s2 = 0; s2 < 2; s2++) {
                uint32_t koff = s2 * 32;
                uint32_t af[2][4], bf[8][2];
                #pragma unroll
                for (int mt = 0; mt < 2; mt++)
                    ldsm_x4(af[mt], stBase + aOff[mt] + koff);
                #pragma unroll
                for (int nt = 0; nt < 8; nt++)
                    ldsm_x2(bf[nt], stBase + bOff[nt] + koff);
                #pragma unroll
                for (int mt = 0; mt < 2; mt++)
                    #pragma unroll
                    for (int nt = 0; nt < 8; nt++)
                        mma_f16_16x8x16(acc[mt][nt], af[mt], bf[nt]);
            }
            __syncthreads();
        }

        #pragma unroll
        for (int mt = 0; mt < 2; mt++) {
            #pragma unroll
            for (int nt = 0; nt < 8; nt++) {
                int s = chunk * 256 + wn * 64 + nt * 8 + 2 * c;
                float4 cp0 = scp[s], cp1 = scp[s + 1];
                float e0 = __expf(acc[mt][nt][0] + cp0.x);
                rs[mt][0][0] += e0; rs[mt][0][1] += e0 * cp0.y;
                rs[mt][0][2] += e0 * cp0.z; rs[mt][0][3] += e0 * cp0.w;
                float e1 = __expf(acc[mt][nt][1] + cp1.x);
                rs[mt][0][0] += e1; rs[mt][0][1] += e1 * cp1.y;
                rs[mt][0][2] += e1 * cp1.z; rs[mt][0][3] += e1 * cp1.w;
                float e2 = __expf(acc[mt][nt][2] + cp0.x);
                rs[mt][1][0] += e2; rs[mt][1][1] += e2 * cp0.y;
                rs[mt][1][2] += e2 * cp0.z; rs[mt][1][3] += e2 * cp0.w;
                float e3 = __expf(acc[mt][nt][3] + cp1.x);
                rs[mt][1][0] += e3; rs[mt][1][1] += e3 * cp1.y;
                rs[mt][1][2] += e3 * cp1.z; rs[mt][1][3] += e3 * cp1.w;
            }
        }
    }
#undef LOADH

    #pragma unroll
    for (int mt = 0; mt < 2; mt++)
        #pragma unroll
        for (int h = 0; h < 2; h++)
            #pragma unroll
            for (int e = 0; e < 4; e++) {
                float v = rs[mt][h][e];
                v += __shfl_xor_sync(0xFFFFFFFFu, v, 1);
                v += __shfl_xor_sync(0xFFFFFFFFu, v, 2);
                rs[mt][h][e] = v;
            }
    __syncthreads();
    if (c == 0) {
        #pragma unroll
        for (int mt = 0; mt < 2; mt++)
            #pragma unroll
            for (int h = 0; h < 2; h++) {
                int row = wm * 32 + mt * 16 + h * 8 + g;
                red4[wn * 128 + row] = make_float4(rs[mt][h][0], rs[mt][h][1],
                                                   rs[mt][h][2], rs[mt][h][3]);
            }
    }
    __syncthreads();
    if (tid < 128) {
        float4 a0 = red4[tid], a1 = red4[128 + tid],
               a2 = red4[256 + tid], a3 = red4[384 + tid];
        float den = a0.x + a1.x + a2.x + a3.x;
        float inv = 1.0f / den;
        g_pre[(size_t)b * M_TOT + m0 + tid] =
            make_float4((a0.y + a1.y + a2.y + a3.y) * inv,
                        (a0.z + a1.z + a2.z + a3.z) * inv,
                        (a0.w + a1.w + a2.w + a3.w) * inv, 0.f);
    }
}

/* ------------- heads ------------------------------------------------------- */
__global__ void k_heads(const float* __restrict__ b_law_d, const float* __restrict__ w_law1,
                        const float* __restrict__ b_law1,
                        const float* __restrict__ b_accu_d, const float* __restrict__ w_accu1,
                        const float* __restrict__ b_accu1,
                        const float* __restrict__ b_term_d, const float* __restrict__ w_term1,
                        const float* __restrict__ b_term1,
                        float* __restrict__ out) {
    int l = blockIdx.x, b = blockIdx.y, tid = threadIdx.x;
    float bl = b_law_d[0], ba = b_accu_d[0], bt = b_term_d[0];
    float s0 = 0, s1 = 0, s2 = 0;
    for (int r = tid; r < RR; r += 256) {
        float4 p = g_pre[(size_t)b * M_TOT + l * RR + r];
        s0 += tanhf(p.x + bl) * w_law1[r];
        s1 += tanhf(p.y + ba) * w_accu1[r];
        s2 += tanhf(p.z + bt) * w_term1[r];
    }
    __shared__ float sm[3][256];
    sm[0][tid] = s0; sm[1][tid] = s1; sm[2][tid] = s2;
    __syncthreads();
    for (int s = 128; s > 0; s >>= 1) {
        if (tid < s) for (int c = 0; c < 3; c++) sm[c][tid] += sm[c][tid + s];
        __syncthreads();
    }
    if (tid == 0) {
        out[b * LL + l] = sm[0][0] + b_law1[0];
        g_hax[b * LL + l] = tanhf(sm[1][0] + b_accu1[0]);
        g_htx[b * LL + l] = tanhf(sm[2][0] + b_term1[0]);
    }
}

__global__ void k_final(const float* __restrict__ Wa2, const float* __restrict__ ba2,
                        const float* __restrict__ Wt2, const float* __restrict__ bt2,
                        float* __restrict__ out) {
    int b = blockIdx.x, tid = threadIdx.x;
    if (tid < 119) {
        float s = ba2[tid];
        for (int l = 0; l < LL; l++) s += Wa2[tid * LL + l] * g_hax[b * LL + l];
        out[BBATCH*LL + b * 119 + tid] = s;
    } else if (tid < 130) {
        int j = tid - 119;
        float s = bt2[j];
        for (int l = 0; l < LL; l++) s += Wt2[j * LL + l] * g_htx[b * LL + l];
        out[BBATCH*LL + BBATCH*119 + b * 11 + j] = s;
    }
}

/* ---------------- launch --------------------------------------------------- */
extern "C" void kernel_launch(void* const* d_in, const int* in_sizes, int n_in,
                              void* d_out, int out_size) {
    const float* outp   = (const float*)d_in[0];
    const int*   amask  = (const int*)  d_in[1];
    const float* laws   = (const float*)d_in[2];
    const float* Wq     = (const float*)d_in[3];
    const float* bq     = (const float*)d_in[4];
    const float* Wk     = (const float*)d_in[5];
    const float* bk     = (const float*)d_in[6];
    const float* Wv     = (const float*)d_in[7];
    const float* bv     = (const float*)d_in[8];
    const float* w_law_d  = (const float*)d_in[9];
    const float* b_law_d  = (const float*)d_in[10];
    const float* w_law1   = (const float*)d_in[11];
    const float* b_law1   = (const float*)d_in[12];
    const float* w_accu_d = (const float*)d_in[13];
    const float* b_accu_d = (const float*)d_in[14];
    const float* w_accu1  = (const float*)d_in[15];
    const float* b_accu1  = (const float*)d_in[16];
    const float* W_accu2  = (const float*)d_in[17];
    const float* b_accu2  = (const float*)d_in[18];
    const float* w_term_d = (const float*)d_in[19];
    const float* b_term_d = (const float*)d_in[20];
    const float* w_term1  = (const float*)d_in[21];
    const float* b_term1  = (const float*)d_in[22];
    const float* W_term2  = (const float*)d_in[23];
    const float* b_term2  = (const float*)d_in[24];
    float* out = (float*)d_out;

    cudaFuncSetAttribute(k_big_h, cudaFuncAttributeMaxDynamicSharedMemorySize, SMEM_BIG);

    cudaEvent_t evFork, evJoin;
    cudaEventCreateWithFlags(&evFork, cudaEventDisableTiming);
    cudaEventCreateWithFlags(&evJoin, cudaEventDisableTiming);

    cudaEventRecord(evFork, 0);
    cudaStreamWaitEvent(cudaStreamPerThread, evFork, 0);
    k_cvt<<<2048, 256, 0, cudaStreamPerThread>>>(laws);
    cudaEventRecord(evJoin, cudaStreamPerThread);

    k_vecs<<<480, 256>>>(Wv, Wk, Wq, w_law_d, w_accu_d, w_term_d, bq, bk);
    k_scal<<<1, 256>>>(bk, bq, bv, w_law_d, w_accu_d, w_term_d);
    k_wc_t<<<dim3(D/64, D/64), 256>>>(Wq, Wk);
    k_fk2_t<<<dim3(D/64, (BBATCH*SSEQ)/64), 256>>>(outp);
    k_colpack<<<BBATCH*SSEQ/8, 256>>>(outp, amask);

    cudaStreamWaitEvent(0, evJoin, 0);
    k_big_h<<<dim3(M_TOT/128, BBATCH), 512, SMEM_BIG>>>(0);
    k_heads<<<dim3(LL, BBATCH), 256>>>(b_law_d, w_law1, b_law1,
                                       b_accu_d, w_accu1, b_accu1,
                                       b_term_d, w_term1, b_term1, out);
    k_final<<<BBATCH, 130>>>(W_accu2, b_accu2, W_term2, b_term2, out);
}

// round 13
// speedup vs baseline: 7.8432x; 1.0731x over previous
#include <cuda_runtime.h>
#include <cuda_fp16.h>
#include <math.h>
#include <stdint.h>

#define D   768
#define LL  103
#define RR  512
#define BBATCH 2
#define SSEQ 512
#define M_TOT (LL*RR)              /* 52736 */
#define INV_SQRT_D 0.03608439182435161f

/* ---------------- static device scratch (no allocation allowed) ------------- */
__device__ __align__(128) float  g_Wct[D*D];               /* (Wq @ Wk^T)*inv = Wc^T    */
__device__ __align__(128) __half g_fk2h[BBATCH*SSEQ*D];    /* half(output @ Wc + bkq')  */
__device__ __align__(128) __half g_lawsh[M_TOT*D];         /* half(laws)                */
__device__ __align__(16)  float4 g_colpack[BBATCH*SSEQ];   /* {sbias', vlaw, vaccu, vterm} */
__device__ float  g_u[5][D];
__device__ float  g_c[4];
__device__ __align__(16) float4 g_pre[BBATCH*M_TOT];       /* {law,accu,term,0} pre-act */
__device__ float  g_hax[BBATCH*LL];
__device__ float  g_htx[BBATCH*LL];

/* ---------------- PTX helpers ---------------------------------------------- */
__device__ __forceinline__ uint32_t smem_u32(const void* p) {
    uint32_t a;
    asm("{ .reg .u64 t; cvta.to.shared.u64 t, %1; cvt.u32.u64 %0, t; }" : "=r"(a) : "l"(p));
    return a;
}
__device__ __forceinline__ void cpa16(uint32_t saddr, const void* g) {
    asm volatile("cp.async.cg.shared.global [%0], [%1], 16;" :: "r"(saddr), "l"(g) : "memory");
}
__device__ __forceinline__ void mma_f16_16x8x16(float* d, const uint32_t* a, const uint32_t* b) {
    asm volatile(
        "mma.sync.aligned.m16n8k16.row.col.f32.f16.f16.f32 "
        "{%0,%1,%2,%3}, {%4,%5,%6,%7}, {%8,%9}, {%0,%1,%2,%3};"
        : "+f"(d[0]), "+f"(d[1]), "+f"(d[2]), "+f"(d[3])
        : "r"(a[0]), "r"(a[1]), "r"(a[2]), "r"(a[3]), "r"(b[0]), "r"(b[1]));
}
__device__ __forceinline__ void mma_tf32_16x8x8(float* d, const uint32_t* a, const uint32_t* b) {
    asm volatile(
        "mma.sync.aligned.m16n8k8.row.col.f32.tf32.tf32.f32 "
        "{%0,%1,%2,%3}, {%4,%5,%6,%7}, {%8,%9}, {%0,%1,%2,%3};"
        : "+f"(d[0]), "+f"(d[1]), "+f"(d[2]), "+f"(d[3])
        : "r"(a[0]), "r"(a[1]), "r"(a[2]), "r"(a[3]), "r"(b[0]), "r"(b[1]));
}
__device__ __forceinline__ void ldsm_x4(uint32_t* r, uint32_t addr) {
    asm volatile("ldmatrix.sync.aligned.m8n8.x4.shared.b16 {%0,%1,%2,%3}, [%4];"
                 : "=r"(r[0]), "=r"(r[1]), "=r"(r[2]), "=r"(r[3]) : "r"(addr));
}
/* split fp32 into tf32-exact hi + residual lo (3xTF32 compensation) */
__device__ __forceinline__ void tf32_split(uint32_t u, uint32_t& hi, uint32_t& lo) {
    hi = u & 0xFFFFE000u;
    lo = __float_as_uint(__uint_as_float(u) - __uint_as_float(hi));
}

/* ---------------- laws fp32 -> fp16 ---------------------------------------- */
__global__ void k_cvt(const float* __restrict__ laws) {
    const float4* src = (const float4*)laws;
    uint2* dst = (uint2*)g_lawsh;
    int n4 = M_TOT * D / 4;
    for (int i = blockIdx.x * blockDim.x + threadIdx.x; i < n4;
         i += gridDim.x * blockDim.x) {
        float4 v = src[i];
        __half2 h0 = __floats2half2_rn(v.x, v.y);
        __half2 h1 = __floats2half2_rn(v.z, v.w);
        dst[i] = make_uint2(*(uint32_t*)&h0, *(uint32_t*)&h1);
    }
}

/* ---------------- tiny precompute kernels (warp-per-dot) -------------------- */
__global__ void k_vecs(const float* __restrict__ Wv, const float* __restrict__ Wk,
                       const float* __restrict__ Wq,
                       const float* __restrict__ wl, const float* __restrict__ wa,
                       const float* __restrict__ wt,
                       const float* __restrict__ bq, const float* __restrict__ bk) {
    int gid = blockIdx.x * 8 + (threadIdx.x >> 5);
    int lane = threadIdx.x & 31;
    int w = gid / D, e = gid % D;
    const float *row, *vec; float scale = 1.0f;
    if      (w == 0) { row = Wv + e*D; vec = wl; }
    else if (w == 1) { row = Wv + e*D; vec = wa; }
    else if (w == 2) { row = Wv + e*D; vec = wt; }
    else if (w == 3) { row = Wk + e*D; vec = bq; scale = INV_SQRT_D; }
    else             { row = Wq + e*D; vec = bk; scale = INV_SQRT_D; }
    float p = 0.f;
    for (int d = lane; d < D; d += 32) p += row[d] * vec[d];
    #pragma unroll
    for (int s = 16; s > 0; s >>= 1) p += __shfl_xor_sync(0xFFFFFFFFu, p, s);
    if (lane == 0) g_u[w][e] = p * scale;
}

__global__ void k_scal(const float* __restrict__ bk, const float* __restrict__ bq,
                       const float* __restrict__ bv,
                       const float* __restrict__ wl, const float* __restrict__ wa,
                       const float* __restrict__ wt) {
    int tid = threadIdx.x;
    float p0 = 0, p1 = 0, p2 = 0, p3 = 0;
    for (int d = tid; d < D; d += 256) {
        float b = bv[d];
        p0 += bk[d] * bq[d]; p1 += b * wl[d]; p2 += b * wa[d]; p3 += b * wt[d];
    }
    __shared__ float sm[4][256];
    sm[0][tid] = p0; sm[1][tid] = p1; sm[2][tid] = p2; sm[3][tid] = p3;
    __syncthreads();
    for (int s = 128; s > 0; s >>= 1) {
        if (tid < s) for (int c = 0; c < 4; c++) sm[c][tid] += sm[c][tid + s];
        __syncthreads();
    }
    if (tid == 0) {
        g_c[0] = sm[0][0] * INV_SQRT_D;
        g_c[1] = sm[1][0]; g_c[2] = sm[2][0]; g_c[3] = sm[3][0];
    }
}

/* ---- 3xTF32 mma GEMM (NT), 4-stage, KT=32: g_Wct = inv * Wq @ Wk^T --------- */
/* stage per matrix = 64 rows x 36 floats (32 data + 4 pad) = 9216 B           */
#define PKC      24
#define PST      9216
#define PBOFF    36864
#define SMEM_PREP 73728

__global__ __launch_bounds__(256) void k_wc_t(const float* __restrict__ A,
                                              const float* __restrict__ B) {
    extern __shared__ float smf[];
    uint32_t sa = smem_u32(smf);
    int tid = threadIdx.x, lane = tid & 31, wid = tid >> 5;
    int wm = wid >> 2, wn = wid & 3, g = lane >> 2, c = lane & 3;
    int i0 = blockIdx.y * 64, j0 = blockIdx.x * 64;
    float acc[2][2][4] = {};

#define LDWC(st, kc) do {                                                       \
        { int i = tid;       int r = i >> 3, s = i & 7;                         \
          cpa16(sa + (st)*PST + r*144 + s*16, A + (size_t)(i0+r)*D + (kc)*32 + s*4); } \
        { int i = tid + 256; int r = i >> 3, s = i & 7;                         \
          cpa16(sa + (st)*PST + r*144 + s*16, A + (size_t)(i0+r)*D + (kc)*32 + s*4); } \
        { int i = tid;       int r = i >> 3, s = i & 7;                         \
          cpa16(sa + PBOFF + (st)*PST + r*144 + s*16, B + (size_t)(j0+r)*D + (kc)*32 + s*4); } \
        { int i = tid + 256; int r = i >> 3, s = i & 7;                         \
          cpa16(sa + PBOFF + (st)*PST + r*144 + s*16, B + (size_t)(j0+r)*D + (kc)*32 + s*4); } \
        asm volatile("cp.async.commit_group;" ::: "memory");                    \
    } while (0)

    LDWC(0, 0); LDWC(1, 1); LDWC(2, 2);
    for (int kc = 0; kc < PKC; kc++) {
        asm volatile("cp.async.wait_group 2;" ::: "memory");
        __syncthreads();
        if (kc + 3 < PKC) LDWC((kc + 3) & 3, kc + 3);
        else asm volatile("cp.async.commit_group;" ::: "memory");
        const float* Aw = smf + (kc & 3) * (PST/4);
        const float* Bw = smf + (PBOFF + (kc & 3) * PST) / 4;
        #pragma unroll
        for (int s2 = 0; s2 < 4; s2++) {
            int kw = s2 * 8;
            uint32_t ah[2][4], al[2][4], bh[2][2], bl[2][2];
            #pragma unroll
            for (int mt = 0; mt < 2; mt++) {
                int m = wm * 32 + mt * 16 + g;
                tf32_split(__float_as_uint(Aw[m * 36 + kw + c]),        ah[mt][0], al[mt][0]);
                tf32_split(__float_as_uint(Aw[(m + 8) * 36 + kw + c]),  ah[mt][1], al[mt][1]);
                tf32_split(__float_as_uint(Aw[m * 36 + kw + c + 4]),    ah[mt][2], al[mt][2]);
                tf32_split(__float_as_uint(Aw[(m + 8) * 36 + kw + c+4]),ah[mt][3], al[mt][3]);
            }
            #pragma unroll
            for (int nt = 0; nt < 2; nt++) {
                int n = wn * 16 + nt * 8 + g;
                tf32_split(__float_as_uint(Bw[n * 36 + kw + c]),     bh[nt][0], bl[nt][0]);
                tf32_split(__float_as_uint(Bw[n * 36 + kw + c + 4]), bh[nt][1], bl[nt][1]);
            }
            #pragma unroll
            for (int mt = 0; mt < 2; mt++)
                #pragma unroll
                for (int nt = 0; nt < 2; nt++) {
                    mma_tf32_16x8x8(acc[mt][nt], ah[mt], bl[nt]);
                    mma_tf32_16x8x8(acc[mt][nt], al[mt], bh[nt]);
                    mma_tf32_16x8x8(acc[mt][nt], ah[mt], bh[nt]);
                }
        }
        __syncthreads();
    }
#undef LDWC
    #pragma unroll
    for (int mt = 0; mt < 2; mt++)
        #pragma unroll
        for (int nt = 0; nt < 2; nt++) {
            int r0 = i0 + wm * 32 + mt * 16 + g;
            int col = j0 + wn * 16 + nt * 8 + 2 * c;
            g_Wct[(size_t)r0 * D + col]       = acc[mt][nt][0] * INV_SQRT_D;
            g_Wct[(size_t)r0 * D + col + 1]   = acc[mt][nt][1] * INV_SQRT_D;
            g_Wct[(size_t)(r0+8) * D + col]   = acc[mt][nt][2] * INV_SQRT_D;
            g_Wct[(size_t)(r0+8) * D + col+1] = acc[mt][nt][3] * INV_SQRT_D;
        }
}

/* ---- 3xTF32 mma GEMM (NT), 4-stage, KT=32: g_fk2h = half(out @ Wct^T + b) -- */
__global__ __launch_bounds__(256) void k_fk2_t(const float* __restrict__ A) {
    extern __shared__ float smf[];
    uint32_t sa = smem_u32(smf);
    int tid = threadIdx.x, lane = tid & 31, wid = tid >> 5;
    int wm = wid >> 2, wn = wid & 3, g = lane >> 2, c = lane & 3;
    int i0 = blockIdx.y * 64, j0 = blockIdx.x * 64;
    float acc[2][2][4] = {};

#define LDFK(st, kc) do {                                                       \
        { int i = tid;       int r = i >> 3, s = i & 7;                         \
          cpa16(sa + (st)*PST + r*144 + s*16, A + (size_t)(i0+r)*D + (kc)*32 + s*4); } \
        { int i = tid + 256; int r = i >> 3, s = i & 7;                         \
          cpa16(sa + (st)*PST + r*144 + s*16, A + (size_t)(i0+r)*D + (kc)*32 + s*4); } \
        { int i = tid;       int r = i >> 3, s = i & 7;                         \
          cpa16(sa + PBOFF + (st)*PST + r*144 + s*16, g_Wct + (size_t)(j0+r)*D + (kc)*32 + s*4); } \
        { int i = tid + 256; int r = i >> 3, s = i & 7;                         \
          cpa16(sa + PBOFF + (st)*PST + r*144 + s*16, g_Wct + (size_t)(j0+r)*D + (kc)*32 + s*4); } \
        asm volatile("cp.async.commit_group;" ::: "memory");                    \
    } while (0)

    LDFK(0, 0); LDFK(1, 1); LDFK(2, 2);
    for (int kc = 0; kc < PKC; kc++) {
        asm volatile("cp.async.wait_group 2;" ::: "memory");
        __syncthreads();
        if (kc + 3 < PKC) LDFK((kc + 3) & 3, kc + 3);
        else asm volatile("cp.async.commit_group;" ::: "memory");
        const float* Aw = smf + (kc & 3) * (PST/4);
        const float* Bw = smf + (PBOFF + (kc & 3) * PST) / 4;
        #pragma unroll
        for (int s2 = 0; s2 < 4; s2++) {
            int kw = s2 * 8;
            uint32_t ah[2][4], al[2][4], bh[2][2], bl[2][2];
            #pragma unroll
            for (int mt = 0; mt < 2; mt++) {
                int m = wm * 32 + mt * 16 + g;
                tf32_split(__float_as_uint(Aw[m * 36 + kw + c]),        ah[mt][0], al[mt][0]);
                tf32_split(__float_as_uint(Aw[(m + 8) * 36 + kw + c]),  ah[mt][1], al[mt][1]);
                tf32_split(__float_as_uint(Aw[m * 36 + kw + c + 4]),    ah[mt][2], al[mt][2]);
                tf32_split(__float_as_uint(Aw[(m + 8) * 36 + kw + c+4]),ah[mt][3], al[mt][3]);
            }
            #pragma unroll
            for (int nt = 0; nt < 2; nt++) {
                int n = wn * 16 + nt * 8 + g;
                tf32_split(__float_as_uint(Bw[n * 36 + kw + c]),     bh[nt][0], bl[nt][0]);
                tf32_split(__float_as_uint(Bw[n * 36 + kw + c + 4]), bh[nt][1], bl[nt][1]);
            }
            #pragma unroll
            for (int mt = 0; mt < 2; mt++)
                #pragma unroll
                for (int nt = 0; nt < 2; nt++) {
                    mma_tf32_16x8x8(acc[mt][nt], ah[mt], bl[nt]);
                    mma_tf32_16x8x8(acc[mt][nt], al[mt], bh[nt]);
                    mma_tf32_16x8x8(acc[mt][nt], ah[mt], bh[nt]);
                }
        }
        __syncthreads();
    }
#undef LDFK
    #pragma unroll
    for (int mt = 0; mt < 2; mt++)
        #pragma unroll
        for (int nt = 0; nt < 2; nt++) {
            int r0 = i0 + wm * 32 + mt * 16 + g;
            int col = j0 + wn * 16 + nt * 8 + 2 * c;
            float b0 = g_u[4][col], b1 = g_u[4][col + 1];
            g_fk2h[(size_t)r0 * D + col]       = __float2half_rn(acc[mt][nt][0] + b0);
            g_fk2h[(size_t)r0 * D + col + 1]   = __float2half_rn(acc[mt][nt][1] + b1);
            g_fk2h[(size_t)(r0+8) * D + col]   = __float2half_rn(acc[mt][nt][2] + b0);
            g_fk2h[(size_t)(r0+8) * D + col+1] = __float2half_rn(acc[mt][nt][3] + b1);
        }
}

/* per (b,s): sbias' (+mask), and the three v projections  (warp per row) */
__global__ void k_colpack(const float* __restrict__ outp, const int* __restrict__ mask) {
    int row = blockIdx.x * 8 + (threadIdx.x >> 5);
    int lane = threadIdx.x & 31;
    const float* x = outp + (size_t)row * D;
    float p0 = 0, p1 = 0, p2 = 0, p3 = 0;
    for (int d = lane; d < D; d += 32) {
        float xv = x[d];
        p0 += xv * g_u[3][d]; p1 += xv * g_u[0][d];
        p2 += xv * g_u[1][d]; p3 += xv * g_u[2][d];
    }
    #pragma unroll
    for (int s = 16; s > 0; s >>= 1) {
        p0 += __shfl_xor_sync(0xFFFFFFFFu, p0, s);
        p1 += __shfl_xor_sync(0xFFFFFFFFu, p1, s);
        p2 += __shfl_xor_sync(0xFFFFFFFFu, p2, s);
        p3 += __shfl_xor_sync(0xFFFFFFFFu, p3, s);
    }
    if (lane == 0) {
        float sb = p0 + g_c[0] + (1.0f - (float)mask[row]) * (-10000.0f);
        g_colpack[row] = make_float4(sb, p1 + g_c[1], p2 + g_c[2], p3 + g_c[3]);
    }
}

/* ------------- big fused kernel: fp16 mma.sync GEMM + softmax epilogue ------ */
/* fragment loads via ldmatrix x4 (A and B-pairs) on conflict-free 80B stride  */
#define KT        32               /* halves per K chunk */
#define NKC       (D/KT)           /* 24 */
#define STG_B     30720
#define SMEM_BIG  139264

__global__ __launch_bounds__(512) void k_big_h(int dummy) {
    extern __shared__ float smf[];
    uint32_t sb = smem_u32(smf);
    int tid = threadIdx.x, lane = tid & 31, wid = tid >> 5;
    int wm = wid >> 2, wn = wid & 3;
    int g = lane >> 2, c = lane & 3;
    int b = blockIdx.y, m0 = blockIdx.x * 128;
    const __half* fk2b = g_fk2h + (size_t)b * SSEQ * D;

    float4* scp  = (float4*)(smf + 30720);
    float4* red4 = (float4*)(smf + 32768);

    { const float4* gcp = g_colpack + b * SSEQ;
      for (int i = tid; i < SSEQ; i += 512) scp[i] = gcp[i]; }

    /* ldmatrix per-lane address offsets (within a stage) */
    int quad = lane >> 3, l8 = lane & 7;
    uint32_t aOff[2], bOff4[4];
    #pragma unroll
    for (int mt = 0; mt < 2; mt++)
        aOff[mt] = (uint32_t)((wm * 32 + mt * 16 + ((quad & 1) << 3) + l8) * 80
                              + ((quad >> 1) << 4));
    #pragma unroll
    for (int j = 0; j < 4; j++)
        bOff4[j] = (uint32_t)(10240 + (wn * 64 + j * 16 + ((lane >> 4) << 3) + l8) * 80
                              + (((lane >> 3) & 1) << 4));

    float rs[2][2][4];
    #pragma unroll
    for (int mt = 0; mt < 2; mt++)
        #pragma unroll
        for (int h = 0; h < 2; h++)
            #pragma unroll
            for (int e = 0; e < 4; e++) rs[mt][h][e] = 0.f;

#define LOADH(st, kc, n0) do {                                                 \
        uint32_t Ab = sb + (st) * STG_B;                                       \
        uint32_t Bb = Ab + 10240;                                              \
        const __half* asrc = g_lawsh + (size_t)m0 * D + (kc) * KT;             \
        const __half* bsrc = fk2b + (size_t)(n0) * D + (kc) * KT;              \
        { int row = tid >> 2, seg = tid & 3;                                   \
          cpa16(Ab + row * 80 + seg * 16, asrc + (size_t)row * D + seg * 8); } \
        { int row = tid >> 2, seg = tid & 3;                                   \
          cpa16(Bb + row * 80 + seg * 16, bsrc + (size_t)row * D + seg * 8); } \
        { int i2 = tid + 512; int row = i2 >> 2, seg = i2 & 3;                 \
          cpa16(Bb + row * 80 + seg * 16, bsrc + (size_t)row * D + seg * 8); } \
        asm volatile("cp.async.commit_group;" ::: "memory");                   \
    } while (0)

    for (int chunk = 0; chunk < 2; chunk++) {
        int n0 = chunk * 256;
        float acc[2][8][4];
        #pragma unroll
        for (int mt = 0; mt < 2; mt++)
            #pragma unroll
            for (int nt = 0; nt < 8; nt++)
                #pragma unroll
                for (int e = 0; e < 4; e++) acc[mt][nt][e] = 0.f;

        LOADH(0, 0, n0); LOADH(1, 1, n0); LOADH(2, 2, n0);

        for (int kc = 0; kc < NKC; kc++) {
            asm volatile("cp.async.wait_group 2;" ::: "memory");
            __syncthreads();
            if (kc + 3 < NKC) LOADH((kc + 3) & 3, kc + 3, n0);
            else asm volatile("cp.async.commit_group;" ::: "memory");

            uint32_t stBase = sb + (kc & 3) * STG_B;
            #pragma unroll
            for (int s2 = 0; s2 < 2; s2++) {
                uint32_t koff = s2 * 32;
                uint32_t af[2][4], bf[4][4];
                #pragma unroll
                for (int mt = 0; mt < 2; mt++)
                    ldsm_x4(af[mt], stBase + aOff[mt] + koff);
                #pragma unroll
                for (int j = 0; j < 4; j++)
                    ldsm_x4(bf[j], stBase + bOff4[j] + koff);
                #pragma unroll
                for (int mt = 0; mt < 2; mt++)
                    #pragma unroll
                    for (int j = 0; j < 4; j++) {
                        mma_f16_16x8x16(acc[mt][2*j],     af[mt], &bf[j][0]);
                        mma_f16_16x8x16(acc[mt][2*j + 1], af[mt], &bf[j][2]);
                    }
            }
        }

        #pragma unroll
        for (int mt = 0; mt < 2; mt++) {
            #pragma unroll
            for (int nt = 0; nt < 8; nt++) {
                int s = chunk * 256 + wn * 64 + nt * 8 + 2 * c;
                float4 cp0 = scp[s], cp1 = scp[s + 1];
                float e0 = __expf(acc[mt][nt][0] + cp0.x);
                rs[mt][0][0] += e0; rs[mt][0][1] += e0 * cp0.y;
                rs[mt][0][2] += e0 * cp0.z; rs[mt][0][3] += e0 * cp0.w;
                float e1 = __expf(acc[mt][nt][1] + cp1.x);
                rs[mt][0][0] += e1; rs[mt][0][1] += e1 * cp1.y;
                rs[mt][0][2] += e1 * cp1.z; rs[mt][0][3] += e1 * cp1.w;
                float e2 = __expf(acc[mt][nt][2] + cp0.x);
                rs[mt][1][0] += e2; rs[mt][1][1] += e2 * cp0.y;
                rs[mt][1][2] += e2 * cp0.z; rs[mt][1][3] += e2 * cp0.w;
                float e3 = __expf(acc[mt][nt][3] + cp1.x);
                rs[mt][1][0] += e3; rs[mt][1][1] += e3 * cp1.y;
                rs[mt][1][2] += e3 * cp1.z; rs[mt][1][3] += e3 * cp1.w;
            }
        }
    }
#undef LOADH

    #pragma unroll
    for (int mt = 0; mt < 2; mt++)
        #pragma unroll
        for (int h = 0; h < 2; h++)
            #pragma unroll
            for (int e = 0; e < 4; e++) {
                float v = rs[mt][h][e];
                v += __shfl_xor_sync(0xFFFFFFFFu, v, 1);
                v += __shfl_xor_sync(0xFFFFFFFFu, v, 2);
                rs[mt][h][e] = v;
            }
    __syncthreads();
    if (c == 0) {
        #pragma unroll
        for (int mt = 0; mt < 2; mt++)
            #pragma unroll
            for (int h = 0; h < 2; h++) {
                int row = wm * 32 + mt * 16 + h * 8 + g;
                red4[wn * 128 + row] = make_float4(rs[mt][h][0], rs[mt][h][1],
                                                   rs[mt][h][2], rs[mt][h][3]);
            }
    }
    __syncthreads();
    if (tid < 128) {
        float4 a0 = red4[tid], a1 = red4[128 + tid],
               a2 = red4[256 + tid], a3 = red4[384 + tid];
        float den = a0.x + a1.x + a2.x + a3.x;
        float inv = 1.0f / den;
        g_pre[(size_t)b * M_TOT + m0 + tid] =
            make_float4((a0.y + a1.y + a2.y + a3.y) * inv,
                        (a0.z + a1.z + a2.z + a3.z) * inv,
                        (a0.w + a1.w + a2.w + a3.w) * inv, 0.f);
    }
}

/* ------------- heads ------------------------------------------------------- */
__global__ void k_heads(const float* __restrict__ b_law_d, const float* __restrict__ w_law1,
                        const float* __restrict__ b_law1,
                        const float* __restrict__ b_accu_d, const float* __restrict__ w_accu1,
                        const float* __restrict__ b_accu1,
                        const float* __restrict__ b_term_d, const float* __restrict__ w_term1,
                        const float* __restrict__ b_term1,
                        float* __restrict__ out) {
    int l = blockIdx.x, b = blockIdx.y, tid = threadIdx.x;
    float bl = b_law_d[0], ba = b_accu_d[0], bt = b_term_d[0];
    float s0 = 0, s1 = 0, s2 = 0;
    for (int r = tid; r < RR; r += 256) {
        float4 p = g_pre[(size_t)b * M_TOT + l * RR + r];
        s0 += tanhf(p.x + bl) * w_law1[r];
        s1 += tanhf(p.y + ba) * w_accu1[r];
        s2 += tanhf(p.z + bt) * w_term1[r];
    }
    __shared__ float sm[3][256];
    sm[0][tid] = s0; sm[1][tid] = s1; sm[2][tid] = s2;
    __syncthreads();
    for (int s = 128; s > 0; s >>= 1) {
        if (tid < s) for (int c = 0; c < 3; c++) sm[c][tid] += sm[c][tid + s];
        __syncthreads();
    }
    if (tid == 0) {
        out[b * LL + l] = sm[0][0] + b_law1[0];
        g_hax[b * LL + l] = tanhf(sm[1][0] + b_accu1[0]);
        g_htx[b * LL + l] = tanhf(sm[2][0] + b_term1[0]);
    }
}

__global__ void k_final(const float* __restrict__ Wa2, const float* __restrict__ ba2,
                        const float* __restrict__ Wt2, const float* __restrict__ bt2,
                        float* __restrict__ out) {
    int b = blockIdx.x, tid = threadIdx.x;
    if (tid < 119) {
        float s = ba2[tid];
        for (int l = 0; l < LL; l++) s += Wa2[tid * LL + l] * g_hax[b * LL + l];
        out[BBATCH*LL + b * 119 + tid] = s;
    } else if (tid < 130) {
        int j = tid - 119;
        float s = bt2[j];
        for (int l = 0; l < LL; l++) s += Wt2[j * LL + l] * g_htx[b * LL + l];
        out[BBATCH*LL + BBATCH*119 + b * 11 + j] = s;
    }
}

/* ---------------- launch --------------------------------------------------- */
extern "C" void kernel_launch(void* const* d_in, const int* in_sizes, int n_in,
                              void* d_out, int out_size) {
    const float* outp   = (const float*)d_in[0];
    const int*   amask  = (const int*)  d_in[1];
    const float* laws   = (const float*)d_in[2];
    const float* Wq     = (const float*)d_in[3];
    const float* bq     = (const float*)d_in[4];
    const float* Wk     = (const float*)d_in[5];
    const float* bk     = (const float*)d_in[6];
    const float* Wv     = (const float*)d_in[7];
    const float* bv     = (const float*)d_in[8];
    const float* w_law_d  = (const float*)d_in[9];
    const float* b_law_d  = (const float*)d_in[10];
    const float* w_law1   = (const float*)d_in[11];
    const float* b_law1   = (const float*)d_in[12];
    const float* w_accu_d = (const float*)d_in[13];
    const float* b_accu_d = (const float*)d_in[14];
    const float* w_accu1  = (const float*)d_in[15];
    const float* b_accu1  = (const float*)d_in[16];
    const float* W_accu2  = (const float*)d_in[17];
    const float* b_accu2  = (const float*)d_in[18];
    const float* w_term_d = (const float*)d_in[19];
    const float* b_term_d = (const float*)d_in[20];
    const float* w_term1  = (const float*)d_in[21];
    const float* b_term1  = (const float*)d_in[22];
    const float* W_term2  = (const float*)d_in[23];
    const float* b_term2  = (const float*)d_in[24];
    float* out = (float*)d_out;

    cudaFuncSetAttribute(k_big_h, cudaFuncAttributeMaxDynamicSharedMemorySize, SMEM_BIG);
    cudaFuncSetAttribute(k_wc_t,  cudaFuncAttributeMaxDynamicSharedMemorySize, SMEM_PREP);
    cudaFuncSetAttribute(k_fk2_t, cudaFuncAttributeMaxDynamicSharedMemorySize, SMEM_PREP);

    cudaEvent_t evFork, evJoin;
    cudaEventCreateWithFlags(&evFork, cudaEventDisableTiming);
    cudaEventCreateWithFlags(&evJoin, cudaEventDisableTiming);

    cudaEventRecord(evFork, 0);
    cudaStreamWaitEvent(cudaStreamPerThread, evFork, 0);
    k_cvt<<<2048, 256, 0, cudaStreamPerThread>>>(laws);
    cudaEventRecord(evJoin, cudaStreamPerThread);

    k_vecs<<<480, 256>>>(Wv, Wk, Wq, w_law_d, w_accu_d, w_term_d, bq, bk);
    k_scal<<<1, 256>>>(bk, bq, bv, w_law_d, w_accu_d, w_term_d);
    k_wc_t<<<dim3(D/64, D/64), 256, SMEM_PREP>>>(Wq, Wk);
    k_fk2_t<<<dim3(D/64, (BBATCH*SSEQ)/64), 256, SMEM_PREP>>>(outp);
    k_colpack<<<BBATCH*SSEQ/8, 256>>>(outp, amask);

    cudaStreamWaitEvent(0, evJoin, 0);
    k_big_h<<<dim3(M_TOT/128, BBATCH), 512, SMEM_BIG>>>(0);
    k_heads<<<dim3(LL, BBATCH), 256>>>(b_law_d, w_law1, b_law1,
                                       b_accu_d, w_accu1, b_accu1,
                                       b_term_d, w_term1, b_term1, out);
    k_final<<<BBATCH, 130>>>(W_accu2, b_accu2, W_term2, b_term2, out);
}

// round 15
// speedup vs baseline: 7.8546x; 1.0015x over previous
#include <cuda_runtime.h>
#include <cuda_fp16.h>
#include <math.h>
#include <stdint.h>

#define D   768
#define LL  103
#define RR  512
#define BBATCH 2
#define SSEQ 512
#define M_TOT (LL*RR)              /* 52736 */
#define INV_SQRT_D 0.03608439182435161f

/* ---------------- static device scratch (no allocation allowed) ------------- */
__device__ __align__(128) float  g_Wct[D*D];               /* (Wq @ Wk^T)*inv = Wc^T    */
__device__ __align__(128) __half g_fk2h[BBATCH*SSEQ*D];    /* half(output @ Wc + bkq')  */
__device__ __align__(128) __half g_lawsh[M_TOT*D];         /* half(laws)                */
__device__ __align__(16)  float4 g_colpack[BBATCH*SSEQ];   /* {sbias', vlaw, vaccu, vterm} */
__device__ float  g_u[5][D];
__device__ float  g_c[4];
__device__ __align__(16) float4 g_pre[BBATCH*M_TOT];       /* {law,accu,term,0} pre-act */
__device__ float  g_hax[BBATCH*LL];
__device__ float  g_htx[BBATCH*LL];

/* ---------------- PTX helpers ---------------------------------------------- */
__device__ __forceinline__ uint32_t smem_u32(const void* p) {
    uint32_t a;
    asm("{ .reg .u64 t; cvta.to.shared.u64 t, %1; cvt.u32.u64 %0, t; }" : "=r"(a) : "l"(p));
    return a;
}
__device__ __forceinline__ void cpa16(uint32_t saddr, const void* g) {
    asm volatile("cp.async.cg.shared.global [%0], [%1], 16;" :: "r"(saddr), "l"(g) : "memory");
}
__device__ __forceinline__ void mma_f16_16x8x16(float* d, const uint32_t* a, const uint32_t* b) {
    asm volatile(
        "mma.sync.aligned.m16n8k16.row.col.f32.f16.f16.f32 "
        "{%0,%1,%2,%3}, {%4,%5,%6,%7}, {%8,%9}, {%0,%1,%2,%3};"
        : "+f"(d[0]), "+f"(d[1]), "+f"(d[2]), "+f"(d[3])
        : "r"(a[0]), "r"(a[1]), "r"(a[2]), "r"(a[3]), "r"(b[0]), "r"(b[1]));
}
__device__ __forceinline__ void mma_tf32_16x8x8(float* d, const uint32_t* a, const uint32_t* b) {
    asm volatile(
        "mma.sync.aligned.m16n8k8.row.col.f32.tf32.tf32.f32 "
        "{%0,%1,%2,%3}, {%4,%5,%6,%7}, {%8,%9}, {%0,%1,%2,%3};"
        : "+f"(d[0]), "+f"(d[1]), "+f"(d[2]), "+f"(d[3])
        : "r"(a[0]), "r"(a[1]), "r"(a[2]), "r"(a[3]), "r"(b[0]), "r"(b[1]));
}
__device__ __forceinline__ void ldsm_x4(uint32_t* r, uint32_t addr) {
    asm volatile("ldmatrix.sync.aligned.m8n8.x4.shared.b16 {%0,%1,%2,%3}, [%4];"
                 : "=r"(r[0]), "=r"(r[1]), "=r"(r[2]), "=r"(r[3]) : "r"(addr));
}
/* split fp32 into tf32-exact hi + residual lo (3xTF32 compensation) */
__device__ __forceinline__ void tf32_split(uint32_t u, uint32_t& hi, uint32_t& lo) {
    hi = u & 0xFFFFE000u;
    lo = __float_as_uint(__uint_as_float(u) - __uint_as_float(hi));
}

/* ---------------- laws fp32 -> fp16 ---------------------------------------- */
__global__ void k_cvt(const float* __restrict__ laws) {
    const float4* src = (const float4*)laws;
    uint2* dst = (uint2*)g_lawsh;
    int n4 = M_TOT * D / 4;
    for (int i = blockIdx.x * blockDim.x + threadIdx.x; i < n4;
         i += gridDim.x * blockDim.x) {
        float4 v = src[i];
        __half2 h0 = __floats2half2_rn(v.x, v.y);
        __half2 h1 = __floats2half2_rn(v.z, v.w);
        dst[i] = make_uint2(*(uint32_t*)&h0, *(uint32_t*)&h1);
    }
}

/* ---------------- tiny precompute kernels (warp-per-dot) -------------------- */
__global__ void k_vecs(const float* __restrict__ Wv, const float* __restrict__ Wk,
                       const float* __restrict__ Wq,
                       const float* __restrict__ wl, const float* __restrict__ wa,
                       const float* __restrict__ wt,
                       const float* __restrict__ bq, const float* __restrict__ bk) {
    int gid = blockIdx.x * 8 + (threadIdx.x >> 5);
    int lane = threadIdx.x & 31;
    int w = gid / D, e = gid % D;
    const float *row, *vec; float scale = 1.0f;
    if      (w == 0) { row = Wv + e*D; vec = wl; }
    else if (w == 1) { row = Wv + e*D; vec = wa; }
    else if (w == 2) { row = Wv + e*D; vec = wt; }
    else if (w == 3) { row = Wk + e*D; vec = bq; scale = INV_SQRT_D; }
    else             { row = Wq + e*D; vec = bk; scale = INV_SQRT_D; }
    float p = 0.f;
    for (int d = lane; d < D; d += 32) p += row[d] * vec[d];
    #pragma unroll
    for (int s = 16; s > 0; s >>= 1) p += __shfl_xor_sync(0xFFFFFFFFu, p, s);
    if (lane == 0) g_u[w][e] = p * scale;
}

__global__ void k_scal(const float* __restrict__ bk, const float* __restrict__ bq,
                       const float* __restrict__ bv,
                       const float* __restrict__ wl, const float* __restrict__ wa,
                       const float* __restrict__ wt) {
    int tid = threadIdx.x;
    float p0 = 0, p1 = 0, p2 = 0, p3 = 0;
    for (int d = tid; d < D; d += 256) {
        float b = bv[d];
        p0 += bk[d] * bq[d]; p1 += b * wl[d]; p2 += b * wa[d]; p3 += b * wt[d];
    }
    __shared__ float sm[4][256];
    sm[0][tid] = p0; sm[1][tid] = p1; sm[2][tid] = p2; sm[3][tid] = p3;
    __syncthreads();
    for (int s = 128; s > 0; s >>= 1) {
        if (tid < s) for (int c = 0; c < 4; c++) sm[c][tid] += sm[c][tid + s];
        __syncthreads();
    }
    if (tid == 0) {
        g_c[0] = sm[0][0] * INV_SQRT_D;
        g_c[1] = sm[1][0]; g_c[2] = sm[2][0]; g_c[3] = sm[3][0];
    }
}

/* ---- 3xTF32 mma GEMM (NT), 4-stage, KT=32, 512 thr (warp tile 16x16) ------- */
/* stage per matrix = 64 rows x 36 floats (32 data + 4 pad) = 9216 B           */
#define PKC      24
#define PST      9216
#define PBOFF    36864
#define SMEM_PREP 73728

__global__ __launch_bounds__(512) void k_wc_t(const float* __restrict__ A,
                                              const float* __restrict__ B) {
    extern __shared__ float smf[];
    uint32_t sa = smem_u32(smf);
    int tid = threadIdx.x, lane = tid & 31, wid = tid >> 5;
    int wm = wid >> 2, wn = wid & 3, g = lane >> 2, c = lane & 3;
    int i0 = blockIdx.y * 64, j0 = blockIdx.x * 64;
    float acc[2][4] = {};

#define LDWC(st, kc) do {                                                       \
        { int r = tid >> 3, s = tid & 7;                                        \
          cpa16(sa + (st)*PST + r*144 + s*16, A + (size_t)(i0+r)*D + (kc)*32 + s*4); } \
        { int r = tid >> 3, s = tid & 7;                                        \
          cpa16(sa + PBOFF + (st)*PST + r*144 + s*16, B + (size_t)(j0+r)*D + (kc)*32 + s*4); } \
        asm volatile("cp.async.commit_group;" ::: "memory");                    \
    } while (0)

    LDWC(0, 0); LDWC(1, 1); LDWC(2, 2);
    for (int kc = 0; kc < PKC; kc++) {
        asm volatile("cp.async.wait_group 2;" ::: "memory");
        __syncthreads();
        if (kc + 3 < PKC) LDWC((kc + 3) & 3, kc + 3);
        else asm volatile("cp.async.commit_group;" ::: "memory");
        const float* Aw = smf + (kc & 3) * (PST/4);
        const float* Bw = smf + (PBOFF + (kc & 3) * PST) / 4;
        #pragma unroll
        for (int s2 = 0; s2 < 4; s2++) {
            int kw = s2 * 8;
            uint32_t ah[4], al[4], bh[2][2], bl[2][2];
            {
                int m = wm * 16 + g;
                tf32_split(__float_as_uint(Aw[m * 36 + kw + c]),        ah[0], al[0]);
                tf32_split(__float_as_uint(Aw[(m + 8) * 36 + kw + c]),  ah[1], al[1]);
                tf32_split(__float_as_uint(Aw[m * 36 + kw + c + 4]),    ah[2], al[2]);
                tf32_split(__float_as_uint(Aw[(m + 8) * 36 + kw + c+4]),ah[3], al[3]);
            }
            #pragma unroll
            for (int nt = 0; nt < 2; nt++) {
                int n = wn * 16 + nt * 8 + g;
                tf32_split(__float_as_uint(Bw[n * 36 + kw + c]),     bh[nt][0], bl[nt][0]);
                tf32_split(__float_as_uint(Bw[n * 36 + kw + c + 4]), bh[nt][1], bl[nt][1]);
            }
            #pragma unroll
            for (int nt = 0; nt < 2; nt++) {
                mma_tf32_16x8x8(acc[nt], ah, bl[nt]);
                mma_tf32_16x8x8(acc[nt], al, bh[nt]);
                mma_tf32_16x8x8(acc[nt], ah, bh[nt]);
            }
        }
        __syncthreads();
    }
#undef LDWC
    #pragma unroll
    for (int nt = 0; nt < 2; nt++) {
        int r0 = i0 + wm * 16 + g;
        int col = j0 + wn * 16 + nt * 8 + 2 * c;
        g_Wct[(size_t)r0 * D + col]       = acc[nt][0] * INV_SQRT_D;
        g_Wct[(size_t)r0 * D + col + 1]   = acc[nt][1] * INV_SQRT_D;
        g_Wct[(size_t)(r0+8) * D + col]   = acc[nt][2] * INV_SQRT_D;
        g_Wct[(size_t)(r0+8) * D + col+1] = acc[nt][3] * INV_SQRT_D;
    }
}

/* ---- 3xTF32 mma GEMM (NT), 4-stage, KT=32, 512 thr: g_fk2h ----------------- */
__global__ __launch_bounds__(512) void k_fk2_t(const float* __restrict__ A) {
    extern __shared__ float smf[];
    uint32_t sa = smem_u32(smf);
    int tid = threadIdx.x, lane = tid & 31, wid = tid >> 5;
    int wm = wid >> 2, wn = wid & 3, g = lane >> 2, c = lane & 3;
    int i0 = blockIdx.y * 64, j0 = blockIdx.x * 64;
    float acc[2][4] = {};

#define LDFK(st, kc) do {                                                       \
        { int r = tid >> 3, s = tid & 7;                                        \
          cpa16(sa + (st)*PST + r*144 + s*16, A + (size_t)(i0+r)*D + (kc)*32 + s*4); } \
        { int r = tid >> 3, s = tid & 7;                                        \
          cpa16(sa + PBOFF + (st)*PST + r*144 + s*16, g_Wct + (size_t)(j0+r)*D + (kc)*32 + s*4); } \
        asm volatile("cp.async.commit_group;" ::: "memory");                    \
    } while (0)

    LDFK(0, 0); LDFK(1, 1); LDFK(2, 2);
    for (int kc = 0; kc < PKC; kc++) {
        asm volatile("cp.async.wait_group 2;" ::: "memory");
        __syncthreads();
        if (kc + 3 < PKC) LDFK((kc + 3) & 3, kc + 3);
        else asm volatile("cp.async.commit_group;" ::: "memory");
        const float* Aw = smf + (kc & 3) * (PST/4);
        const float* Bw = smf + (PBOFF + (kc & 3) * PST) / 4;
        #pragma unroll
        for (int s2 = 0; s2 < 4; s2++) {
            int kw = s2 * 8;
            uint32_t ah[4], al[4], bh[2][2], bl[2][2];
            {
                int m = wm * 16 + g;
                tf32_split(__float_as_uint(Aw[m * 36 + kw + c]),        ah[0], al[0]);
                tf32_split(__float_as_uint(Aw[(m + 8) * 36 + kw + c]),  ah[1], al[1]);
                tf32_split(__float_as_uint(Aw[m * 36 + kw + c + 4]),    ah[2], al[2]);
                tf32_split(__float_as_uint(Aw[(m + 8) * 36 + kw + c+4]),ah[3], al[3]);
            }
            #pragma unroll
            for (int nt = 0; nt < 2; nt++) {
                int n = wn * 16 + nt * 8 + g;
                tf32_split(__float_as_uint(Bw[n * 36 + kw + c]),     bh[nt][0], bl[nt][0]);
                tf32_split(__float_as_uint(Bw[n * 36 + kw + c + 4]), bh[nt][1], bl[nt][1]);
            }
            #pragma unroll
            for (int nt = 0; nt < 2; nt++) {
                mma_tf32_16x8x8(acc[nt], ah, bl[nt]);
                mma_tf32_16x8x8(acc[nt], al, bh[nt]);
                mma_tf32_16x8x8(acc[nt], ah, bh[nt]);
            }
        }
        __syncthreads();
    }
#undef LDFK
    #pragma unroll
    for (int nt = 0; nt < 2; nt++) {
        int r0 = i0 + wm * 16 + g;
        int col = j0 + wn * 16 + nt * 8 + 2 * c;
        float b0 = g_u[4][col], b1 = g_u[4][col + 1];
        g_fk2h[(size_t)r0 * D + col]       = __float2half_rn(acc[nt][0] + b0);
        g_fk2h[(size_t)r0 * D + col + 1]   = __float2half_rn(acc[nt][1] + b1);
        g_fk2h[(size_t)(r0+8) * D + col]   = __float2half_rn(acc[nt][2] + b0);
        g_fk2h[(size_t)(r0+8) * D + col+1] = __float2half_rn(acc[nt][3] + b1);
    }
}

/* per (b,s): sbias' (+mask), and the three v projections  (warp per row) */
__global__ void k_colpack(const float* __restrict__ outp, const int* __restrict__ mask) {
    int row = blockIdx.x * 8 + (threadIdx.x >> 5);
    int lane = threadIdx.x & 31;
    const float* x = outp + (size_t)row * D;
    float p0 = 0, p1 = 0, p2 = 0, p3 = 0;
    for (int d = lane; d < D; d += 32) {
        float xv = x[d];
        p0 += xv * g_u[3][d]; p1 += xv * g_u[0][d];
        p2 += xv * g_u[1][d]; p3 += xv * g_u[2][d];
    }
    #pragma unroll
    for (int s = 16; s > 0; s >>= 1) {
        p0 += __shfl_xor_sync(0xFFFFFFFFu, p0, s);
        p1 += __shfl_xor_sync(0xFFFFFFFFu, p1, s);
        p2 += __shfl_xor_sync(0xFFFFFFFFu, p2, s);
        p3 += __shfl_xor_sync(0xFFFFFFFFu, p3, s);
    }
    if (lane == 0) {
        float sb = p0 + g_c[0] + (1.0f - (float)mask[row]) * (-10000.0f);
        g_colpack[row] = make_float4(sb, p1 + g_c[1], p2 + g_c[2], p3 + g_c[3]);
    }
}

/* ------------- big fused kernel: fp16 mma.sync GEMM + softmax epilogue ------ */
/* fragment loads via ldmatrix x4 (A and B-pairs) on conflict-free 80B stride  */
#define KT        32               /* halves per K chunk */
#define NKC       (D/KT)           /* 24 */
#define STG_B     30720
#define SMEM_BIG  139264

__global__ __launch_bounds__(512) void k_big_h(int dummy) {
    extern __shared__ float smf[];
    uint32_t sb = smem_u32(smf);
    int tid = threadIdx.x, lane = tid & 31, wid = tid >> 5;
    int wm = wid >> 2, wn = wid & 3;
    int g = lane >> 2, c = lane & 3;
    int b = blockIdx.y, m0 = blockIdx.x * 128;
    const __half* fk2b = g_fk2h + (size_t)b * SSEQ * D;

    float4* scp  = (float4*)(smf + 30720);
    float4* red4 = (float4*)(smf + 32768);

    { const float4* gcp = g_colpack + b * SSEQ;
      for (int i = tid; i < SSEQ; i += 512) scp[i] = gcp[i]; }

    /* ldmatrix per-lane address offsets (within a stage) */
    int quad = lane >> 3, l8 = lane & 7;
    uint32_t aOff[2], bOff4[4];
    #pragma unroll
    for (int mt = 0; mt < 2; mt++)
        aOff[mt] = (uint32_t)((wm * 32 + mt * 16 + ((quad & 1) << 3) + l8) * 80
                              + ((quad >> 1) << 4));
    #pragma unroll
    for (int j = 0; j < 4; j++)
        bOff4[j] = (uint32_t)(10240 + (wn * 64 + j * 16 + ((lane >> 4) << 3) + l8) * 80
                              + (((lane >> 3) & 1) << 4));

    float rs[2][2][4];
    #pragma unroll
    for (int mt = 0; mt < 2; mt++)
        #pragma unroll
        for (int h = 0; h < 2; h++)
            #pragma unroll
            for (int e = 0; e < 4; e++) rs[mt][h][e] = 0.f;

#define LOADH(st, kc, n0) do {                                                 \
        uint32_t Ab = sb + (st) * STG_B;                                       \
        uint32_t Bb = Ab + 10240;                                              \
        const __half* asrc = g_lawsh + (size_t)m0 * D + (kc) * KT;             \
        const __half* bsrc = fk2b + (size_t)(n0) * D + (kc) * KT;              \
        { int row = tid >> 2, seg = tid & 3;                                   \
          cpa16(Ab + row * 80 + seg * 16, asrc + (size_t)row * D + seg * 8); } \
        { int row = tid >> 2, seg = tid & 3;                                   \
          cpa16(Bb + row * 80 + seg * 16, bsrc + (size_t)row * D + seg * 8); } \
        { int i2 = tid + 512; int row = i2 >> 2, seg = i2 & 3;                 \
          cpa16(Bb + row * 80 + seg * 16, bsrc + (size_t)row * D + seg * 8); } \
        asm volatile("cp.async.commit_group;" ::: "memory");                   \
    } while (0)

    for (int chunk = 0; chunk < 2; chunk++) {
        int n0 = chunk * 256;
        float acc[2][8][4];
        #pragma unroll
        for (int mt = 0; mt < 2; mt++)
            #pragma unroll
            for (int nt = 0; nt < 8; nt++)
                #pragma unroll
                for (int e = 0; e < 4; e++) acc[mt][nt][e] = 0.f;

        LOADH(0, 0, n0); LOADH(1, 1, n0); LOADH(2, 2, n0);

        for (int kc = 0; kc < NKC; kc++) {
            asm volatile("cp.async.wait_group 2;" ::: "memory");
            __syncthreads();
            if (kc + 3 < NKC) LOADH((kc + 3) & 3, kc + 3, n0);
            else asm volatile("cp.async.commit_group;" ::: "memory");

            uint32_t stBase = sb + (kc & 3) * STG_B;
            #pragma unroll
            for (int s2 = 0; s2 < 2; s2++) {
                uint32_t koff = s2 * 32;
                uint32_t af[2][4], bf[4][4];
                #pragma unroll
                for (int mt = 0; mt < 2; mt++)
                    ldsm_x4(af[mt], stBase + aOff[mt] + koff);
                #pragma unroll
                for (int j = 0; j < 4; j++)
                    ldsm_x4(bf[j], stBase + bOff4[j] + koff);
                #pragma unroll
                for (int mt = 0; mt < 2; mt++)
                    #pragma unroll
                    for (int j = 0; j < 4; j++) {
                        mma_f16_16x8x16(acc[mt][2*j],     af[mt], &bf[j][0]);
                        mma_f16_16x8x16(acc[mt][2*j + 1], af[mt], &bf[j][2]);
                    }
            }
        }

        #pragma unroll
        for (int mt = 0; mt < 2; mt++) {
            #pragma unroll
            for (int nt = 0; nt < 8; nt++) {
                int s = chunk * 256 + wn * 64 + nt * 8 + 2 * c;
                float4 cp0 = scp[s], cp1 = scp[s + 1];
                float e0 = __expf(acc[mt][nt][0] + cp0.x);
                rs[mt][0][0] += e0; rs[mt][0][1] += e0 * cp0.y;
                rs[mt][0][2] += e0 * cp0.z; rs[mt][0][3] += e0 * cp0.w;
                float e1 = __expf(acc[mt][nt][1] + cp1.x);
                rs[mt][0][0] += e1; rs[mt][0][1] += e1 * cp1.y;
                rs[mt][0][2] += e1 * cp1.z; rs[mt][0][3] += e1 * cp1.w;
                float e2 = __expf(acc[mt][nt][2] + cp0.x);
                rs[mt][1][0] += e2; rs[mt][1][1] += e2 * cp0.y;
                rs[mt][1][2] += e2 * cp0.z; rs[mt][1][3] += e2 * cp0.w;
                float e3 = __expf(acc[mt][nt][3] + cp1.x);
                rs[mt][1][0] += e3; rs[mt][1][1] += e3 * cp1.y;
                rs[mt][1][2] += e3 * cp1.z; rs[mt][1][3] += e3 * cp1.w;
            }
        }
    }
#undef LOADH

    #pragma unroll
    for (int mt = 0; mt < 2; mt++)
        #pragma unroll
        for (int h = 0; h < 2; h++)
            #pragma unroll
            for (int e = 0; e < 4; e++) {
                float v = rs[mt][h][e];
                v += __shfl_xor_sync(0xFFFFFFFFu, v, 1);
                v += __shfl_xor_sync(0xFFFFFFFFu, v, 2);
                rs[mt][h][e] = v;
            }
    __syncthreads();
    if (c == 0) {
        #pragma unroll
        for (int mt = 0; mt < 2; mt++)
            #pragma unroll
            for (int h = 0; h < 2; h++) {
                int row = wm * 32 + mt * 16 + h * 8 + g;
                red4[wn * 128 + row] = make_float4(rs[mt][h][0], rs[mt][h][1],
                                                   rs[mt][h][2], rs[mt][h][3]);
            }
    }
    __syncthreads();
    if (tid < 128) {
        float4 a0 = red4[tid], a1 = red4[128 + tid],
               a2 = red4[256 + tid], a3 = red4[384 + tid];
        float den = a0.x + a1.x + a2.x + a3.x;
        float inv = 1.0f / den;
        g_pre[(size_t)b * M_TOT + m0 + tid] =
            make_float4((a0.y + a1.y + a2.y + a3.y) * inv,
                        (a0.z + a1.z + a2.z + a3.z) * inv,
                        (a0.w + a1.w + a2.w + a3.w) * inv, 0.f);
    }
}

/* ------------- heads ------------------------------------------------------- */
__global__ void k_heads(const float* __restrict__ b_law_d, const float* __restrict__ w_law1,
                        const float* __restrict__ b_law1,
                        const float* __restrict__ b_accu_d, const float* __restrict__ w_accu1,
                        const float* __restrict__ b_accu1,
                        const float* __restrict__ b_term_d, const float* __restrict__ w_term1,
                        const float* __restrict__ b_term1,
                        float* __restrict__ out) {
    int l = blockIdx.x, b = blockIdx.y, tid = threadIdx.x;
    float bl = b_law_d[0], ba = b_accu_d[0], bt = b_term_d[0];
    float s0 = 0, s1 = 0, s2 = 0;
    for (int r = tid; r < RR; r += 256) {
        float4 p = g_pre[(size_t)b * M_TOT + l * RR + r];
        s0 += tanhf(p.x + bl) * w_law1[r];
        s1 += tanhf(p.y + ba) * w_accu1[r];
        s2 += tanhf(p.z + bt) * w_term1[r];
    }
    __shared__ float sm[3][256];
    sm[0][tid] = s0; sm[1][tid] = s1; sm[2][tid] = s2;
    __syncthreads();
    for (int s = 128; s > 0; s >>= 1) {
        if (tid < s) for (int c = 0; c < 3; c++) sm[c][tid] += sm[c][tid + s];
        __syncthreads();
    }
    if (tid == 0) {
        out[b * LL + l] = sm[0][0] + b_law1[0];
        g_hax[b * LL + l] = tanhf(sm[1][0] + b_accu1[0]);
        g_htx[b * LL + l] = tanhf(sm[2][0] + b_term1[0]);
    }
}

__global__ void k_final(const float* __restrict__ Wa2, const float* __restrict__ ba2,
                        const float* __restrict__ Wt2, const float* __restrict__ bt2,
                        float* __restrict__ out) {
    int b = blockIdx.x, tid = threadIdx.x;
    if (tid < 119) {
        float s = ba2[tid];
        for (int l = 0; l < LL; l++) s += Wa2[tid * LL + l] * g_hax[b * LL + l];
        out[BBATCH*LL + b * 119 + tid] = s;
    } else if (tid < 130) {
        int j = tid - 119;
        float s = bt2[j];
        for (int l = 0; l < LL; l++) s += Wt2[j * LL + l] * g_htx[b * LL + l];
        out[BBATCH*LL + BBATCH*119 + b * 11 + j] = s;
    }
}

/* ---------------- launch --------------------------------------------------- */
extern "C" void kernel_launch(void* const* d_in, const int* in_sizes, int n_in,
                              void* d_out, int out_size) {
    const float* outp   = (const float*)d_in[0];
    const int*   amask  = (const int*)  d_in[1];
    const float* laws   = (const float*)d_in[2];
    const float* Wq     = (const float*)d_in[3];
    const float* bq     = (const float*)d_in[4];
    const float* Wk     = (const float*)d_in[5];
    const float* bk     = (const float*)d_in[6];
    const float* Wv     = (const float*)d_in[7];
    const float* bv     = (const float*)d_in[8];
    const float* w_law_d  = (const float*)d_in[9];
    const float* b_law_d  = (const float*)d_in[10];
    const float* w_law1   = (const float*)d_in[11];
    const float* b_law1   = (const float*)d_in[12];
    const float* w_accu_d = (const float*)d_in[13];
    const float* b_accu_d = (const float*)d_in[14];
    const float* w_accu1  = (const float*)d_in[15];
    const float* b_accu1  = (const float*)d_in[16];
    const float* W_accu2  = (const float*)d_in[17];
    const float* b_accu2  = (const float*)d_in[18];
    const float* w_term_d = (const float*)d_in[19];
    const float* b_term_d = (const float*)d_in[20];
    const float* w_term1  = (const float*)d_in[21];
    const float* b_term1  = (const float*)d_in[22];
    const float* W_term2  = (const float*)d_in[23];
    const float* b_term2  = (const float*)d_in[24];
    float* out = (float*)d_out;

    cudaFuncSetAttribute(k_big_h, cudaFuncAttributeMaxDynamicSharedMemorySize, SMEM_BIG);
    cudaFuncSetAttribute(k_wc_t,  cudaFuncAttributeMaxDynamicSharedMemorySize, SMEM_PREP);
    cudaFuncSetAttribute(k_fk2_t, cudaFuncAttributeMaxDynamicSharedMemorySize, SMEM_PREP);

    cudaEvent_t evFork, evJoin;
    cudaEventCreateWithFlags(&evFork, cudaEventDisableTiming);
    cudaEventCreateWithFlags(&evJoin, cudaEventDisableTiming);

    cudaEventRecord(evFork, 0);
    cudaStreamWaitEvent(cudaStreamPerThread, evFork, 0);
    k_cvt<<<2048, 256, 0, cudaStreamPerThread>>>(laws);
    cudaEventRecord(evJoin, cudaStreamPerThread);

    k_vecs<<<480, 256>>>(Wv, Wk, Wq, w_law_d, w_accu_d, w_term_d, bq, bk);
    k_scal<<<1, 256>>>(bk, bq, bv, w_law_d, w_accu_d, w_term_d);
    k_wc_t<<<dim3(D/64, D/64), 512, SMEM_PREP>>>(Wq, Wk);
    k_fk2_t<<<dim3(D/64, (BBATCH*SSEQ)/64), 512, SMEM_PREP>>>(outp);
    k_colpack<<<BBATCH*SSEQ/8, 256>>>(outp, amask);

    cudaStreamWaitEvent(0, evJoin, 0);
    k_big_h<<<dim3(M_TOT/128, BBATCH), 512, SMEM_BIG>>>(0);
    k_heads<<<dim3(LL, BBATCH), 256>>>(b_law_d, w_law1, b_law1,
                                       b_accu_d, w_accu1, b_accu1,
                                       b_term_d, w_term1, b_term1, out);
    k_final<<<BBATCH, 130>>>(W_accu2, b_accu2, W_term2, b_term2, out);
}